// round 7
// baseline (speedup 1.0000x reference)
#include <cuda_runtime.h>
#include <cuda_bf16.h>
#include <math.h>
#include <stdint.h>

// ---------------------------------------------------------------------------
// Model_19104014532987: 2-layer transformer
// B=8 T=2048 DKQ=64 DV=64 EKQ=EV=128 H=4 dh=32 FF=512 OUT=32, R=16384
// All heavy math on mma.sync bf16 (HMMA), bf16x3 split precision.
// ---------------------------------------------------------------------------

#define R_TOTAL 16384
#define T_SEQ   2048
#define EMB     128
#define NHEAD   4
#define LOG2E   1.4426950408889634f

typedef __nv_bfloat16 bf16;

// Scratch pool: 56M floats (224 MB), static device allocation (allowed).
static __device__ __align__(256) float g_scratch[56ull * 1024 * 1024];

__device__ __forceinline__ float gelu_exact(float x) {
    return 0.5f * x * (1.0f + erff(x * 0.70710678118654752440f));
}
__device__ __forceinline__ float ex2(float x) {
    float y; asm("ex2.approx.ftz.f32 %0, %1;" : "=f"(y) : "f"(x)); return y;
}
__device__ __forceinline__ uint32_t smem_u32(const void* p) {
    uint32_t a;
    asm("{ .reg .u64 t; cvta.to.shared.u64 t, %1; cvt.u32.u64 %0, t; }" : "=r"(a) : "l"(p));
    return a;
}

#define LDMX4(r0, r1, r2, r3, addr) \
    asm volatile("ldmatrix.sync.aligned.m8n8.x4.shared.b16 {%0,%1,%2,%3}, [%4];" \
        : "=r"(r0), "=r"(r1), "=r"(r2), "=r"(r3) : "r"(addr))
#define LDMX4T(r0, r1, r2, r3, addr) \
    asm volatile("ldmatrix.sync.aligned.m8n8.x4.trans.shared.b16 {%0,%1,%2,%3}, [%4];" \
        : "=r"(r0), "=r"(r1), "=r"(r2), "=r"(r3) : "r"(addr))
#define MMA16816(d, a, b0, b1) \
    asm volatile("mma.sync.aligned.m16n8k16.row.col.f32.bf16.bf16.f32 " \
        "{%0,%1,%2,%3}, {%4,%5,%6,%7}, {%8,%9}, {%0,%1,%2,%3};" \
        : "+f"((d)[0]), "+f"((d)[1]), "+f"((d)[2]), "+f"((d)[3]) \
        : "r"((a)[0]), "r"((a)[1]), "r"((a)[2]), "r"((a)[3]), "r"(b0), "r"(b1))

__device__ __forceinline__ void packpair(uint32_t& ph, uint32_t& pl, float x, float y) {
    bf16 hx = __float2bfloat16(x), hy = __float2bfloat16(y);
    __nv_bfloat162 t; t.x = hx; t.y = hy;
    ph = *reinterpret_cast<uint32_t*>(&t);
    __nv_bfloat162 u;
    u.x = __float2bfloat16(x - __bfloat162float(hx));
    u.y = __float2bfloat16(y - __bfloat162float(hy));
    pl = *reinterpret_cast<uint32_t*>(&u);
}

// ---------------------------------------------------------------------------
// elementwise prep kernels
// ---------------------------------------------------------------------------
__global__ void split_k(const float* __restrict__ x, bf16* __restrict__ h,
                        bf16* __restrict__ l, int n4) {
    int i = blockIdx.x * 256 + threadIdx.x;
    if (i >= n4) return;
    float4 v = reinterpret_cast<const float4*>(x)[i];
    uint32_t h01, l01, h23, l23;
    packpair(h01, l01, v.x, v.y);
    packpair(h23, l23, v.z, v.w);
    reinterpret_cast<uint32_t*>(h)[i * 2]     = h01;
    reinterpret_cast<uint32_t*>(h)[i * 2 + 1] = h23;
    reinterpret_cast<uint32_t*>(l)[i * 2]     = l01;
    reinterpret_cast<uint32_t*>(l)[i * 2 + 1] = l23;
}

__global__ void splitcat_k(const float* __restrict__ kq, const float* __restrict__ v,
                           bf16* __restrict__ h, bf16* __restrict__ l) {
    int i = blockIdx.x * 256 + threadIdx.x;
    if (i >= R_TOTAL * 32) return;
    int e = i * 4;
    int r = e >> 7, d = e & 127;
    float4 val = (d < 64)
        ? *reinterpret_cast<const float4*>(&kq[(size_t)r * 64 + d])
        : *reinterpret_cast<const float4*>(&v[(size_t)r * 64 + (d - 64)]);
    uint32_t h01, l01, h23, l23;
    packpair(h01, l01, val.x, val.y);
    packpair(h23, l23, val.z, val.w);
    reinterpret_cast<uint32_t*>(h)[i * 2]     = h01;
    reinterpret_cast<uint32_t*>(h)[i * 2 + 1] = h23;
    reinterpret_cast<uint32_t*>(l)[i * 2]     = l01;
    reinterpret_cast<uint32_t*>(l)[i * 2 + 1] = l23;
}

// transpose+split with N padding and scale: W[K,N] -> Wt[Npad,K] bf16 hi/lo
__global__ void tsplit_k(const float* __restrict__ W, bf16* __restrict__ th,
                         bf16* __restrict__ tl, int Kd, int Nd, int Npad, float scale) {
    int idx = blockIdx.x * 256 + threadIdx.x;
    if (idx >= Npad * Kd) return;
    int n = idx / Kd, k = idx - n * Kd;
    float w = (n < Nd) ? W[(size_t)k * Nd + n] * scale : 0.f;
    bf16 h = __float2bfloat16(w);
    th[idx] = h;
    tl[idx] = __float2bfloat16(w - __bfloat162float(h));
}

__global__ void bcopy_k(const float* __restrict__ src, float* __restrict__ dst,
                        int n, float scale) {
    int i = blockIdx.x * 128 + threadIdx.x;
    if (i < n) dst[i] = src[i] * scale;
}

// Wc[k][n] = sum_j f2W[k][j] * outW[j][n]   (512 x 32, K=128)
__global__ void wcomb_k(const float* __restrict__ f2W, const float* __restrict__ outW,
                        float* __restrict__ Wc) {
    int idx = blockIdx.x * 256 + threadIdx.x;
    if (idx >= 512 * 32) return;
    int k = idx >> 5, n = idx & 31;
    float s = 0.f;
    for (int j = 0; j < 128; j++) s = fmaf(f2W[k * 128 + j], outW[j * 32 + n], s);
    Wc[idx] = s;
}
// bc[n] = out_b[n] + sum_j f2b[j] * outW[j][n]
__global__ void bcomb_k(const float* __restrict__ f2b, const float* __restrict__ outW,
                        const float* __restrict__ out_b, float* __restrict__ bc) {
    int n = threadIdx.x;
    if (n >= 32) return;
    float s = out_b[n];
    for (int j = 0; j < 128; j++) s = fmaf(f2b[j], outW[j * 32 + n], s);
    bc[n] = s;
}

// ---------------------------------------------------------------------------
// mma_gemm: C = A[M,K] @ Wt[N,K]^T + bias, bf16x3 split precision.
// 256 threads, CTA tile 128x128 (grid.x = N/128), warp tile 32x64.
// Outputs: optional fp32 Cf for cols in [f_lo, Nvalid) at stride fStride
// (col c stored at c-f_lo), optional bf16 hi/lo Ch/Cl at stride cStride.
// ---------------------------------------------------------------------------
__global__ __launch_bounds__(256) void mma_gemm(
    const bf16* __restrict__ Ah, const bf16* __restrict__ Al,
    const bf16* __restrict__ Bh, const bf16* __restrict__ Bl,
    const float* __restrict__ bias, int Nvalid,
    float* __restrict__ Cf, int f_lo, int fStride,
    bf16* __restrict__ Ch, bf16* __restrict__ Cl, int cStride,
    int K, int act)
{
    __shared__ __align__(16) bf16 smAh[128 * 40];
    __shared__ __align__(16) bf16 smAl[128 * 40];
    __shared__ __align__(16) bf16 smBh[128 * 40];
    __shared__ __align__(16) bf16 smBl[128 * 40];

    const int tid = threadIdx.x;
    const int l = tid & 31, w = tid >> 5;
    const int wm = w >> 1, wn = w & 1;
    const int bm = blockIdx.y * 128, bn = blockIdx.x * 128;

    float d[2][8][4];
#pragma unroll
    for (int mt = 0; mt < 2; mt++)
#pragma unroll
        for (int nt = 0; nt < 8; nt++)
#pragma unroll
            for (int q = 0; q < 4; q++) d[mt][nt][q] = 0.f;

    const uint32_t aAh = smem_u32(smAh), aAl = smem_u32(smAl);
    const uint32_t aBh = smem_u32(smBh), aBl = smem_u32(smBl);

    const int a_row = wm * 32 + (l & 7) + ((l >> 3) & 1) * 8;
    const int a_kof = (l >> 4) * 8;
    const int b_row = wn * 64 + (l >> 4) * 8 + (l & 7);
    const int b_kof = ((l >> 3) & 1) * 8;

    for (int kc = 0; kc < K; kc += 32) {
        if (kc) __syncthreads();
#pragma unroll
        for (int i = tid; i < 512; i += 256) {
            int row = i >> 2, ch = i & 3;
            size_t ga = (size_t)(bm + row) * K + kc + ch * 8;
            size_t gb = (size_t)(bn + row) * K + kc + ch * 8;
            int sa = row * 40 + ch * 8;
            *reinterpret_cast<uint4*>(smAh + sa) = *reinterpret_cast<const uint4*>(Ah + ga);
            *reinterpret_cast<uint4*>(smAl + sa) = *reinterpret_cast<const uint4*>(Al + ga);
            *reinterpret_cast<uint4*>(smBh + sa) = *reinterpret_cast<const uint4*>(Bh + gb);
            *reinterpret_cast<uint4*>(smBl + sa) = *reinterpret_cast<const uint4*>(Bl + gb);
        }
        __syncthreads();

#pragma unroll
        for (int ks = 0; ks < 32; ks += 16) {
            uint32_t ah[2][4], al2[2][4];
#pragma unroll
            for (int mt = 0; mt < 2; mt++) {
                uint32_t off = (uint32_t)(((a_row + mt * 16) * 40 + a_kof + ks) * 2);
                LDMX4(ah[mt][0], ah[mt][1], ah[mt][2], ah[mt][3], aAh + off);
                LDMX4(al2[mt][0], al2[mt][1], al2[mt][2], al2[mt][3], aAl + off);
            }
#pragma unroll
            for (int j = 0; j < 4; j++) {
                uint32_t boff = (uint32_t)(((b_row + j * 16) * 40 + b_kof + ks) * 2);
                uint32_t bh[4], bl2[4];
                LDMX4(bh[0], bh[1], bh[2], bh[3], aBh + boff);
                LDMX4(bl2[0], bl2[1], bl2[2], bl2[3], aBl + boff);
#pragma unroll
                for (int mt = 0; mt < 2; mt++) {
                    MMA16816(d[mt][2 * j],     ah[mt],  bh[0],  bh[1]);
                    MMA16816(d[mt][2 * j],     al2[mt], bh[0],  bh[1]);
                    MMA16816(d[mt][2 * j],     ah[mt],  bl2[0], bl2[1]);
                    MMA16816(d[mt][2 * j + 1], ah[mt],  bh[2],  bh[3]);
                    MMA16816(d[mt][2 * j + 1], al2[mt], bh[2],  bh[3]);
                    MMA16816(d[mt][2 * j + 1], ah[mt],  bl2[2], bl2[3]);
                }
            }
        }
    }

#pragma unroll
    for (int mt = 0; mt < 2; mt++) {
        int r0 = bm + wm * 32 + mt * 16 + (l >> 2);
#pragma unroll
        for (int nt = 0; nt < 8; nt++) {
            int c = bn + wn * 64 + nt * 8 + (l & 3) * 2;
            if (c >= Nvalid) continue;
            float b0 = bias[c], b1 = bias[c + 1];
            float2 v0, v1;
            v0.x = d[mt][nt][0] + b0; v0.y = d[mt][nt][1] + b1;
            v1.x = d[mt][nt][2] + b0; v1.y = d[mt][nt][3] + b1;
            if (act) {
                v0.x = gelu_exact(v0.x); v0.y = gelu_exact(v0.y);
                v1.x = gelu_exact(v1.x); v1.y = gelu_exact(v1.y);
            }
            if (Cf && c >= f_lo) {
                *reinterpret_cast<float2*>(&Cf[(size_t)r0 * fStride + (c - f_lo)]) = v0;
                *reinterpret_cast<float2*>(&Cf[(size_t)(r0 + 8) * fStride + (c - f_lo)]) = v1;
            }
            if (Ch) {
                uint32_t h0, l0p, h1v, l1p;
                packpair(h0, l0p, v0.x, v0.y);
                packpair(h1v, l1p, v1.x, v1.y);
                *reinterpret_cast<uint32_t*>(&Ch[(size_t)r0 * cStride + c]) = h0;
                *reinterpret_cast<uint32_t*>(&Cl[(size_t)r0 * cStride + c]) = l0p;
                *reinterpret_cast<uint32_t*>(&Ch[(size_t)(r0 + 8) * cStride + c]) = h1v;
                *reinterpret_cast<uint32_t*>(&Cl[(size_t)(r0 + 8) * cStride + c]) = l1p;
            }
        }
    }
}

// ---------------------------------------------------------------------------
// attn_tc: tensor-core flash attention, 128q x 64k tiles, dh=32.
// 256 threads = 8 warps x 16 q rows. Q pre-scaled by log2(e) (in weights).
// Per-tensor strides; head col offset (bh&3)*32 applied internally.
// mode 0: j <= i.  mode 1: j < i OR (i==0 && j==0).
// ---------------------------------------------------------------------------
__global__ __launch_bounds__(256) void attn_tc(
    const bf16* __restrict__ Qh, const bf16* __restrict__ Ql, int qStride,
    const bf16* __restrict__ Kh, const bf16* __restrict__ Kl, int kStride,
    const bf16* __restrict__ Vh, const bf16* __restrict__ Vl, int vStride,
    float* __restrict__ Of, bf16* __restrict__ Oh, bf16* __restrict__ Ol, int oStride,
    int mode)
{
    __shared__ __align__(16) bf16 sQh[128 * 40], sQl[128 * 40];
    __shared__ __align__(16) bf16 sKh[64 * 40], sKl[64 * 40];
    __shared__ __align__(16) bf16 sVh[64 * 40], sVl[64 * 40];

    const int tid = threadIdx.x, l = tid & 31, w = tid >> 5;
    const int bh = blockIdx.y;
    const int hc = (bh & 3) * 32;
    const int bb = bh >> 2;
    const size_t baseQ = (size_t)bb * T_SEQ * qStride + hc;
    const size_t baseK = (size_t)bb * T_SEQ * kStride + hc;
    const size_t baseV = (size_t)bb * T_SEQ * vStride + hc;
    const size_t baseO = (size_t)bb * T_SEQ * oStride + hc;
    const int qbase = (gridDim.x - 1 - blockIdx.x) * 128;

    // Q tile (128 rows) -> smem
    for (int i = tid; i < 512; i += 256) {
        int row = i >> 2, ch = i & 3;
        size_t g = baseQ + (size_t)(qbase + row) * qStride + ch * 8;
        *reinterpret_cast<uint4*>(&sQh[row * 40 + ch * 8]) = *reinterpret_cast<const uint4*>(&Qh[g]);
        *reinterpret_cast<uint4*>(&sQl[row * 40 + ch * 8]) = *reinterpret_cast<const uint4*>(&Ql[g]);
    }
    __syncthreads();

    const uint32_t aQh = smem_u32(sQh), aQl = smem_u32(sQl);
    const uint32_t aKh = smem_u32(sKh), aKl = smem_u32(sKl);
    const uint32_t aVh = smem_u32(sVh), aVl = smem_u32(sVl);

    uint32_t qh[2][4], ql[2][4];
    const int a_row = w * 16 + (l & 7) + ((l >> 3) & 1) * 8;
    const int a_col = (l >> 4) * 8;
#pragma unroll
    for (int ks = 0; ks < 2; ks++) {
        uint32_t off = (uint32_t)((a_row * 40 + a_col + ks * 16) * 2);
        LDMX4(qh[ks][0], qh[ks][1], qh[ks][2], qh[ks][3], aQh + off);
        LDMX4(ql[ks][0], ql[ks][1], ql[ks][2], ql[ks][3], aQl + off);
    }

    const float NEG = -1e30f;
    const int r0 = qbase + w * 16 + (l >> 2);
    const int r1 = r0 + 8;
    float m0 = NEG, m1 = NEG, lac0 = 0.f, lac1 = 0.f;
    float o[4][4];
#pragma unroll
    for (int n = 0; n < 4; n++)
#pragma unroll
        for (int q = 0; q < 4; q++) o[n][q] = 0.f;

    const int b_row_base = (l >> 4) * 8 + (l & 7);
    const int b_kof = ((l >> 3) & 1) * 8;
    const int jmax = qbase + 64;

    for (int j0 = 0; j0 <= jmax; j0 += 64) {
        __syncthreads();
        for (int i = tid; i < 256; i += 256) {}  // no-op keep structure
        for (int i = tid; i < 256; i += 256) {}
        for (int i = tid; i < 256; i += 256) {}
        for (int i = tid; i < 256; i += 256) {
            // unreachable filler removed below
        }
        for (int i = tid; i < 256; i += 256) {}
        // K/V tile loads: 64 rows x 4 chunks = 256 tasks over 256 threads
        {
            int row = tid >> 2, ch = tid & 3;
            size_t gk = baseK + (size_t)(j0 + row) * kStride + ch * 8;
            size_t gv = baseV + (size_t)(j0 + row) * vStride + ch * 8;
            *reinterpret_cast<uint4*>(&sKh[row * 40 + ch * 8]) = *reinterpret_cast<const uint4*>(&Kh[gk]);
            *reinterpret_cast<uint4*>(&sKl[row * 40 + ch * 8]) = *reinterpret_cast<const uint4*>(&Kl[gk]);
            *reinterpret_cast<uint4*>(&sVh[row * 40 + ch * 8]) = *reinterpret_cast<const uint4*>(&Vh[gv]);
            *reinterpret_cast<uint4*>(&sVl[row * 40 + ch * 8]) = *reinterpret_cast<const uint4*>(&Vl[gv]);
        }
        __syncthreads();

        // ---- S = Q K^T (bf16x3) ----
        float s[8][4];
#pragma unroll
        for (int nt = 0; nt < 8; nt++)
#pragma unroll
            for (int q = 0; q < 4; q++) s[nt][q] = 0.f;

#pragma unroll
        for (int ks = 0; ks < 2; ks++) {
#pragma unroll
            for (int jp = 0; jp < 4; jp++) {
                uint32_t off = (uint32_t)(((jp * 16 + b_row_base) * 40 + b_kof + ks * 16) * 2);
                uint32_t kb[4], kbl[4];
                LDMX4(kb[0], kb[1], kb[2], kb[3], aKh + off);
                LDMX4(kbl[0], kbl[1], kbl[2], kbl[3], aKl + off);
                MMA16816(s[2 * jp],     qh[ks], kb[0],  kb[1]);
                MMA16816(s[2 * jp],     ql[ks], kb[0],  kb[1]);
                MMA16816(s[2 * jp],     qh[ks], kbl[0], kbl[1]);
                MMA16816(s[2 * jp + 1], qh[ks], kb[2],  kb[3]);
                MMA16816(s[2 * jp + 1], ql[ks], kb[2],  kb[3]);
                MMA16816(s[2 * jp + 1], qh[ks], kbl[2], kbl[3]);
            }
        }

        // ---- mask (diagonal region) ----
        if (j0 >= qbase) {
#pragma unroll
            for (int nt = 0; nt < 8; nt++) {
                int cb = j0 + nt * 8 + (l & 3) * 2;
                if (mode == 0) {
                    if (cb     > r0) s[nt][0] = NEG;
                    if (cb + 1 > r0) s[nt][1] = NEG;
                    if (cb     > r1) s[nt][2] = NEG;
                    if (cb + 1 > r1) s[nt][3] = NEG;
                } else {
                    if (!(cb     < r0 || (r0 == 0 && cb == 0))) s[nt][0] = NEG;
                    if (!(cb + 1 < r0))                          s[nt][1] = NEG;
                    if (!(cb     < r1)) s[nt][2] = NEG;
                    if (!(cb + 1 < r1)) s[nt][3] = NEG;
                }
            }
        }

        // ---- online softmax ----
        float ml0 = NEG, ml1 = NEG;
#pragma unroll
        for (int nt = 0; nt < 8; nt++) {
            ml0 = fmaxf(ml0, fmaxf(s[nt][0], s[nt][1]));
            ml1 = fmaxf(ml1, fmaxf(s[nt][2], s[nt][3]));
        }
        ml0 = fmaxf(ml0, __shfl_xor_sync(0xffffffffu, ml0, 1));
        ml0 = fmaxf(ml0, __shfl_xor_sync(0xffffffffu, ml0, 2));
        ml1 = fmaxf(ml1, __shfl_xor_sync(0xffffffffu, ml1, 1));
        ml1 = fmaxf(ml1, __shfl_xor_sync(0xffffffffu, ml1, 2));
        float mn0 = fmaxf(m0, ml0), mn1 = fmaxf(m1, ml1);
        float sc0 = ex2(m0 - mn0), sc1 = ex2(m1 - mn1);

        uint32_t pah[4][4], pal[4][4];
        float ps0 = 0.f, ps1 = 0.f;
#pragma unroll
        for (int t = 0; t < 4; t++) {
#pragma unroll
            for (int half = 0; half < 2; half++) {
                int nt = 2 * t + half;
                float p0 = ex2(s[nt][0] - mn0), p1 = ex2(s[nt][1] - mn0);
                float p2 = ex2(s[nt][2] - mn1), p3 = ex2(s[nt][3] - mn1);
                ps0 += p0 + p1; ps1 += p2 + p3;
                packpair(pah[t][2 * half],     pal[t][2 * half],     p0, p1);
                packpair(pah[t][2 * half + 1], pal[t][2 * half + 1], p2, p3);
            }
        }
        lac0 = lac0 * sc0 + ps0;
        lac1 = lac1 * sc1 + ps1;
#pragma unroll
        for (int n = 0; n < 4; n++) {
            o[n][0] *= sc0; o[n][1] *= sc0; o[n][2] *= sc1; o[n][3] *= sc1;
        }

        // ---- O += P V (bf16x3), V via trans ldmatrix ----
#pragma unroll
        for (int t = 0; t < 4; t++) {
#pragma unroll
            for (int np = 0; np < 2; np++) {
                uint32_t off = (uint32_t)(((t * 16 + (l & 15)) * 40 + np * 16 + (l >> 4) * 8) * 2);
                uint32_t vb[4], vbl[4];
                LDMX4T(vb[0], vb[1], vb[2], vb[3], aVh + off);
                LDMX4T(vbl[0], vbl[1], vbl[2], vbl[3], aVl + off);
                MMA16816(o[2 * np],     pah[t], vb[0],  vb[1]);
                MMA16816(o[2 * np],     pal[t], vb[0],  vb[1]);
                MMA16816(o[2 * np],     pah[t], vbl[0], vbl[1]);
                MMA16816(o[2 * np + 1], pah[t], vb[2],  vb[3]);
                MMA16816(o[2 * np + 1], pal[t], vb[2],  vb[3]);
                MMA16816(o[2 * np + 1], pah[t], vbl[2], vbl[3]);
            }
        }
        m0 = mn0; m1 = mn1;
    }

    lac0 += __shfl_xor_sync(0xffffffffu, lac0, 1);
    lac0 += __shfl_xor_sync(0xffffffffu, lac0, 2);
    lac1 += __shfl_xor_sync(0xffffffffu, lac1, 1);
    lac1 += __shfl_xor_sync(0xffffffffu, lac1, 2);
    float inv0 = 1.f / lac0, inv1 = 1.f / lac1;

#pragma unroll
    for (int nt = 0; nt < 4; nt++) {
        int col = nt * 8 + (l & 3) * 2;
        float v00 = o[nt][0] * inv0, v01 = o[nt][1] * inv0;
        float v10 = o[nt][2] * inv1, v11 = o[nt][3] * inv1;
        if (Of) {
            float2 a; a.x = v00; a.y = v01;
            float2 b; b.x = v10; b.y = v11;
            *reinterpret_cast<float2*>(&Of[baseO + (size_t)r0 * oStride + col]) = a;
            *reinterpret_cast<float2*>(&Of[baseO + (size_t)r1 * oStride + col]) = b;
        }
        if (Oh) {
            uint32_t h0, l0p, h1v, l1p;
            packpair(h0, l0p, v00, v01);
            packpair(h1v, l1p, v10, v11);
            *reinterpret_cast<uint32_t*>(&Oh[baseO + (size_t)r0 * oStride + col]) = h0;
            *reinterpret_cast<uint32_t*>(&Ol[baseO + (size_t)r0 * oStride + col]) = l0p;
            *reinterpret_cast<uint32_t*>(&Oh[baseO + (size_t)r1 * oStride + col]) = h1v;
            *reinterpret_cast<uint32_t*>(&Ol[baseO + (size_t)r1 * oStride + col]) = l1p;
        }
    }
}

// ---------------------------------------------------------------------------
// out = LayerNorm(A + B) * gamma + beta; fp32 out optional, bf16 hi/lo optional
// ---------------------------------------------------------------------------
__global__ void add_ln_k(const float* __restrict__ A, const float* __restrict__ Bv,
                         const float* __restrict__ gam, const float* __restrict__ bet,
                         float* __restrict__ outf, bf16* __restrict__ outh,
                         bf16* __restrict__ outl)
{
    int row = blockIdx.x;
    int d = threadIdx.x;  // 128
    float x = A[(size_t)row * 128 + d] + Bv[(size_t)row * 128 + d];

    __shared__ float ws[4], ws2[4];
    float v = x;
#pragma unroll
    for (int off = 16; off; off >>= 1) v += __shfl_xor_sync(0xffffffffu, v, off);
    if ((d & 31) == 0) ws[d >> 5] = v;
    __syncthreads();
    float mean = (ws[0] + ws[1] + ws[2] + ws[3]) * (1.f / 128.f);
    float dif = x - mean;
    float v2 = dif * dif;
#pragma unroll
    for (int off = 16; off; off >>= 1) v2 += __shfl_xor_sync(0xffffffffu, v2, off);
    if ((d & 31) == 0) ws2[d >> 5] = v2;
    __syncthreads();
    float var = (ws2[0] + ws2[1] + ws2[2] + ws2[3]) * (1.f / 128.f);
    float y = dif * rsqrtf(var + 1e-5f) * gam[d] + bet[d];
    if (outf) outf[(size_t)row * 128 + d] = y;
    if (outh) {
        bf16 h = __float2bfloat16(y);
        outh[(size_t)row * 128 + d] = h;
        outl[(size_t)row * 128 + d] = __float2bfloat16(y - __bfloat162float(h));
    }
}

// ---------------------------------------------------------------------------
extern "C" void kernel_launch(void* const* d_in, const int* in_sizes, int n_in,
                              void* d_out, int out_size)
{
    const float* kq    = (const float*)d_in[0];
    const float* v_in  = (const float*)d_in[1];
    const float* A_Wk  = (const float*)d_in[2];
    const float* A_bk  = (const float*)d_in[3];
    const float* A_Wq  = (const float*)d_in[4];
    const float* A_bq  = (const float*)d_in[5];
    const float* A_Wv  = (const float*)d_in[6];
    const float* A_bv  = (const float*)d_in[7];
    const float* A_f1W = (const float*)d_in[8];
    const float* A_f1b = (const float*)d_in[9];
    const float* A_f2W = (const float*)d_in[10];
    const float* A_f2b = (const float*)d_in[11];
    const float* A_n1g = (const float*)d_in[12];
    const float* A_n1b = (const float*)d_in[13];
    const float* A_n2g = (const float*)d_in[14];
    const float* A_n2b = (const float*)d_in[15];
    const float* B_Wk  = (const float*)d_in[16];
    const float* B_bk  = (const float*)d_in[17];
    const float* B_Wq  = (const float*)d_in[18];
    const float* B_bq  = (const float*)d_in[19];
    const float* B_Wv  = (const float*)d_in[20];
    const float* B_bv  = (const float*)d_in[21];
    const float* B_f1W = (const float*)d_in[22];
    const float* B_f1b = (const float*)d_in[23];
    const float* B_f2W = (const float*)d_in[24];
    const float* B_f2b = (const float*)d_in[25];
    const float* out_W = (const float*)d_in[26];
    const float* out_b = (const float*)d_in[27];
    float* out = (float*)d_out;

    float* pool = nullptr;
    cudaGetSymbolAddress((void**)&pool, g_scratch);

    const size_t S = (size_t)R_TOTAL * 128;  // 2M floats per slot
    float* attnA = pool + 0 * S;
    float* h1    = pool + 1 * S;
    float* t1    = pool + 2 * S;
    float* Va    = pool + 3 * S;
    bf16* qkvA_h = (bf16*)(pool + 4 * S);    // R x 384 (slots 4-5)
    bf16* qkvA_l = (bf16*)(pool + 6 * S);    // slots 6-7
    bf16* sXh    = (bf16*)(pool + 8 * S);
    bf16* sXl    = (bf16*)(pool + 9 * S);
    bf16* ffh    = (bf16*)(pool + 10 * S);   // R x 512 (slots 10-11)
    bf16* ffl    = (bf16*)(pool + 12 * S);   // slots 12-13
    bf16* kqh    = (bf16*)(pool + 14 * S);
    bf16* kql    = (bf16*)(pool + 15 * S);
    bf16* kq2h   = (bf16*)(pool + 16 * S);   // R x 256
    bf16* kq2l   = (bf16*)(pool + 17 * S);
    bf16* v2h    = (bf16*)(pool + 18 * S);
    bf16* v2l    = (bf16*)(pool + 19 * S);
    bf16* at2h   = (bf16*)(pool + 20 * S);
    bf16* at2l   = (bf16*)(pool + 21 * S);
    bf16* vAh    = (bf16*)(pool + 22 * S);
    bf16* vAl    = (bf16*)(pool + 23 * S);
    float* Wc    = pool + 24 * S;            // 512x32 fp32
    float* bc    = Wc + 512 * 32;
    float* qkvbA = bc + 64;                  // 384
    float* kqb2  = qkvbA + 384;              // 256
    bf16* wbuf   = (bf16*)(pool + 25 * S);
    bf16* qkvW_h = wbuf;                       bf16* qkvW_l = qkvW_h + 384 * 128;
    bf16* kqW_h  = qkvW_l + 384 * 128;         bf16* kqW_l  = kqW_h + 256 * 64;
    bf16* bWv_h  = kqW_l + 256 * 64;           bf16* bWv_l  = bWv_h + 128 * 128;
    bf16* af1_h  = bWv_l + 128 * 128;          bf16* af1_l  = af1_h + 512 * 128;
    bf16* af2_h  = af1_l + 512 * 128;          bf16* af2_l  = af2_h + 128 * 512;
    bf16* bf1_h  = af2_l + 128 * 512;          bf16* bf1_l  = bf1_h + 512 * 128;
    bf16* wc_h   = bf1_l + 512 * 128;          bf16* wc_l   = wc_h + 128 * 512;

    // ---- weight prep ----
    // QKV-A packed Wt[384,128]: [K | Q(*log2e) | V]
    tsplit_k<<<(128*128+255)/256, 256>>>(A_Wk, qkvW_h,             qkvW_l,             128, 128, 128, 1.f);
    tsplit_k<<<(128*128+255)/256, 256>>>(A_Wq, qkvW_h + 128*128,   qkvW_l + 128*128,   128, 128, 128, LOG2E);
    tsplit_k<<<(128*128+255)/256, 256>>>(A_Wv, qkvW_h + 2*128*128, qkvW_l + 2*128*128, 128, 128, 128, 1.f);
    bcopy_k<<<1, 128>>>(A_bk, qkvbA,       128, 1.f);
    bcopy_k<<<1, 128>>>(A_bq, qkvbA + 128, 128, LOG2E);
    bcopy_k<<<1, 128>>>(A_bv, qkvbA + 256, 128, 1.f);
    // KQ-B packed Wt[256,64]: [K | Q(*log2e)]
    tsplit_k<<<(128*64+255)/256, 256>>>(B_Wk, kqW_h,          kqW_l,          64, 128, 128, 1.f);
    tsplit_k<<<(128*64+255)/256, 256>>>(B_Wq, kqW_h + 128*64, kqW_l + 128*64, 64, 128, 128, LOG2E);
    bcopy_k<<<1, 128>>>(B_bk, kqb2,       128, 1.f);
    bcopy_k<<<1, 128>>>(B_bq, kqb2 + 128, 128, LOG2E);
    // rest
    tsplit_k<<<(128*128+255)/256, 256>>>(B_Wv, bWv_h, bWv_l, 128, 128, 128, 1.f);
    tsplit_k<<<(512*128+255)/256, 256>>>(A_f1W, af1_h, af1_l, 128, 512, 512, 1.f);
    tsplit_k<<<(512*128+255)/256, 256>>>(A_f2W, af2_h, af2_l, 512, 128, 128, 1.f);
    tsplit_k<<<(512*128+255)/256, 256>>>(B_f1W, bf1_h, bf1_l, 128, 512, 512, 1.f);
    // folded FF2B @ OUT head
    wcomb_k<<<(512*32+255)/256, 256>>>(B_f2W, out_W, Wc);
    bcomb_k<<<1, 32>>>(B_f2b, out_W, out_b, bc);
    tsplit_k<<<(128*512+255)/256, 256>>>(Wc, wc_h, wc_l, 512, 32, 128, 1.f);

    dim3 blk256(256);
    dim3 attnGrid(T_SEQ / 128, 8 * NHEAD);  // (16, 32)

    // ---- Layer A ----
    splitcat_k<<<(R_TOTAL*32+255)/256, 256>>>(kq, v_in, sXh, sXl);
    mma_gemm<<<dim3(3, 128), blk256>>>(sXh, sXl, qkvW_h, qkvW_l, qkvbA, 384,
                                       Va, 256, 128, qkvA_h, qkvA_l, 384, 128, 0);
    attn_tc<<<attnGrid, blk256>>>(qkvA_h + 128, qkvA_l + 128, 384,
                                  qkvA_h, qkvA_l, 384,
                                  qkvA_h + 256, qkvA_l + 256, 384,
                                  attnA, nullptr, nullptr, 128, 0);
    add_ln_k<<<R_TOTAL, 128>>>(Va, attnA, A_n1g, A_n1b, h1, sXh, sXl);
    mma_gemm<<<dim3(4, 128), blk256>>>(sXh, sXl, af1_h, af1_l, A_f1b, 512,
                                       nullptr, 0, 0, ffh, ffl, 512, 128, 1);
    mma_gemm<<<dim3(1, 128), blk256>>>(ffh, ffl, af2_h, af2_l, A_f2b, 128,
                                       t1, 0, 128, nullptr, nullptr, 0, 512, 0);
    add_ln_k<<<R_TOTAL, 128>>>(h1, t1, A_n2g, A_n2b, nullptr, vAh, vAl);

    // ---- Layer B ----
    split_k<<<(R_TOTAL*16+255)/256, 256>>>(kq, kqh, kql, R_TOTAL*16);
    mma_gemm<<<dim3(2, 128), blk256>>>(kqh, kql, kqW_h, kqW_l, kqb2, 256,
                                       nullptr, 0, 0, kq2h, kq2l, 256, 64, 0);
    mma_gemm<<<dim3(1, 128), blk256>>>(vAh, vAl, bWv_h, bWv_l, B_bv, 128,
                                       nullptr, 0, 0, v2h, v2l, 128, 128, 0);
    attn_tc<<<attnGrid, blk256>>>(kq2h + 128, kq2l + 128, 256,
                                  kq2h, kq2l, 256,
                                  v2h, v2l, 128,
                                  nullptr, at2h, at2l, 128, 1);
    mma_gemm<<<dim3(4, 128), blk256>>>(at2h, at2l, bf1_h, bf1_l, B_f1b, 512,
                                       nullptr, 0, 0, ffh, ffl, 512, 128, 1);
    // folded FF2B+head: N=32 valid, padded Wt[128,512]
    mma_gemm<<<dim3(1, 128), blk256>>>(ffh, ffl, wc_h, wc_l, bc, 32,
                                       out, 0, 32, nullptr, nullptr, 0, 512, 0);
}

// round 8
// speedup vs baseline: 1.0983x; 1.0983x over previous
#include <cuda_runtime.h>
#include <cuda_bf16.h>
#include <math.h>
#include <stdint.h>

// ---------------------------------------------------------------------------
// Model_19104014532987: 2-layer transformer
// B=8 T=2048 DKQ=64 DV=64 EKQ=EV=128 H=4 dh=32 FF=512 OUT=32, R=16384
// All heavy math on mma.sync bf16 (HMMA), bf16x3 split precision.
// ---------------------------------------------------------------------------

#define R_TOTAL 16384
#define T_SEQ   2048
#define EMB     128
#define NHEAD   4
#define LOG2E   1.4426950408889634f

typedef __nv_bfloat16 bf16;

// Scratch pool: 56M floats (224 MB), static device allocation (allowed).
static __device__ __align__(256) float g_scratch[56ull * 1024 * 1024];

__device__ __forceinline__ float gelu_exact(float x) {
    return 0.5f * x * (1.0f + erff(x * 0.70710678118654752440f));
}
__device__ __forceinline__ float ex2(float x) {
    float y; asm("ex2.approx.ftz.f32 %0, %1;" : "=f"(y) : "f"(x)); return y;
}
__device__ __forceinline__ uint32_t smem_u32(const void* p) {
    uint32_t a;
    asm("{ .reg .u64 t; cvta.to.shared.u64 t, %1; cvt.u32.u64 %0, t; }" : "=r"(a) : "l"(p));
    return a;
}

#define LDMX4(r0, r1, r2, r3, addr) \
    asm volatile("ldmatrix.sync.aligned.m8n8.x4.shared.b16 {%0,%1,%2,%3}, [%4];" \
        : "=r"(r0), "=r"(r1), "=r"(r2), "=r"(r3) : "r"(addr))
#define LDMX4T(r0, r1, r2, r3, addr) \
    asm volatile("ldmatrix.sync.aligned.m8n8.x4.trans.shared.b16 {%0,%1,%2,%3}, [%4];" \
        : "=r"(r0), "=r"(r1), "=r"(r2), "=r"(r3) : "r"(addr))
#define MMA16816(d, a, b0, b1) \
    asm volatile("mma.sync.aligned.m16n8k16.row.col.f32.bf16.bf16.f32 " \
        "{%0,%1,%2,%3}, {%4,%5,%6,%7}, {%8,%9}, {%0,%1,%2,%3};" \
        : "+f"((d)[0]), "+f"((d)[1]), "+f"((d)[2]), "+f"((d)[3]) \
        : "r"((a)[0]), "r"((a)[1]), "r"((a)[2]), "r"((a)[3]), "r"(b0), "r"(b1))

__device__ __forceinline__ void packpair(uint32_t& ph, uint32_t& pl, float x, float y) {
    bf16 hx = __float2bfloat16(x), hy = __float2bfloat16(y);
    __nv_bfloat162 t; t.x = hx; t.y = hy;
    ph = *reinterpret_cast<uint32_t*>(&t);
    __nv_bfloat162 u;
    u.x = __float2bfloat16(x - __bfloat162float(hx));
    u.y = __float2bfloat16(y - __bfloat162float(hy));
    pl = *reinterpret_cast<uint32_t*>(&u);
}

// ---------------------------------------------------------------------------
// activation split kernels
// ---------------------------------------------------------------------------
__global__ void split_k(const float* __restrict__ x, bf16* __restrict__ h,
                        bf16* __restrict__ l, int n4) {
    int i = blockIdx.x * 256 + threadIdx.x;
    if (i >= n4) return;
    float4 v = reinterpret_cast<const float4*>(x)[i];
    uint32_t h01, l01, h23, l23;
    packpair(h01, l01, v.x, v.y);
    packpair(h23, l23, v.z, v.w);
    reinterpret_cast<uint32_t*>(h)[i * 2]     = h01;
    reinterpret_cast<uint32_t*>(h)[i * 2 + 1] = h23;
    reinterpret_cast<uint32_t*>(l)[i * 2]     = l01;
    reinterpret_cast<uint32_t*>(l)[i * 2 + 1] = l23;
}

__global__ void splitcat_k(const float* __restrict__ kq, const float* __restrict__ v,
                           bf16* __restrict__ h, bf16* __restrict__ l) {
    int i = blockIdx.x * 256 + threadIdx.x;
    if (i >= R_TOTAL * 32) return;
    int e = i * 4;
    int r = e >> 7, d = e & 127;
    float4 val = (d < 64)
        ? *reinterpret_cast<const float4*>(&kq[(size_t)r * 64 + d])
        : *reinterpret_cast<const float4*>(&v[(size_t)r * 64 + (d - 64)]);
    uint32_t h01, l01, h23, l23;
    packpair(h01, l01, val.x, val.y);
    packpair(h23, l23, val.z, val.w);
    reinterpret_cast<uint32_t*>(h)[i * 2]     = h01;
    reinterpret_cast<uint32_t*>(h)[i * 2 + 1] = h23;
    reinterpret_cast<uint32_t*>(l)[i * 2]     = l01;
    reinterpret_cast<uint32_t*>(l)[i * 2 + 1] = l23;
}

// ---------------------------------------------------------------------------
// fused weight prep
// ---------------------------------------------------------------------------
// small prep: Wc = B_f2W @ out_W (512x32), bc = out_b + B_f2b @ out_W,
// plus 5 scaled bias copies. One launch.
__global__ void smallprep_k(const float* __restrict__ f2W, const float* __restrict__ outW,
                            const float* __restrict__ f2b, const float* __restrict__ out_b,
                            const float* __restrict__ A_bk, const float* __restrict__ A_bq,
                            const float* __restrict__ A_bv, const float* __restrict__ B_bk,
                            const float* __restrict__ B_bq,
                            float* __restrict__ Wc, float* __restrict__ bc,
                            float* __restrict__ qkvbA, float* __restrict__ kqb2)
{
    int gid = blockIdx.x * 256 + threadIdx.x;
    if (gid < 512 * 32) {
        int k = gid >> 5, n = gid & 31;
        float s = 0.f;
        for (int j = 0; j < 128; j++) s = fmaf(f2W[k * 128 + j], outW[j * 32 + n], s);
        Wc[gid] = s;
        return;
    }
    int r = gid - 512 * 32;
    if (r < 32) {
        float s = out_b[r];
        for (int j = 0; j < 128; j++) s = fmaf(f2b[j], outW[j * 32 + r], s);
        bc[r] = s;
        return;
    }
    r -= 32;
    if (r < 384) {
        float v = (r < 128) ? A_bk[r] : (r < 256) ? A_bq[r - 128] * LOG2E : A_bv[r - 256];
        qkvbA[r] = v;
        return;
    }
    r -= 384;
    if (r < 256) {
        kqb2[r] = (r < 128) ? B_bk[r] : B_bq[r - 128] * LOG2E;
    }
}

// big prep: all 10 transpose+split+scale weight transforms, one launch.
// Segment s: W[Kd,Nd] -> Wt[Npad,Kd] bf16 hi/lo at arena offset segstart[s].
// dst index == global index (arena layout matches segment order).
struct Prep10 { const float* s[10]; };
__device__ __constant__ const int  PS_START[10] = {0,16384,32768,49152,57344,65536,81920,147456,212992,278528};
#define PW_TOTAL 344064
__device__ __constant__ const int  PS_KD[10]    = {128,128,128, 64, 64,128,128,512,128,512};
__device__ __constant__ const int  PS_ND[10]    = {128,128,128,128,128,128,512,128,512, 32};
__device__ __constant__ const float PS_SC[10]   = {1.f,LOG2E,1.f,1.f,LOG2E,1.f,1.f,1.f,1.f,1.f};

__global__ void prepw_k(Prep10 srcs, bf16* __restrict__ th, bf16* __restrict__ tl) {
    int gid = blockIdx.x * 256 + threadIdx.x;
    if (gid >= PW_TOTAL) return;
    int s = 0;
#pragma unroll
    for (int i = 1; i < 10; i++) if (gid >= PS_START[i]) s = i;
    int idx = gid - PS_START[s];
    int Kd = PS_KD[s], Nd = PS_ND[s];
    int n = idx / Kd, k = idx - n * Kd;
    float w = (n < Nd) ? srcs.s[s][(size_t)k * Nd + n] * PS_SC[s] : 0.f;
    bf16 h = __float2bfloat16(w);
    th[gid] = h;
    tl[gid] = __float2bfloat16(w - __bfloat162float(h));
}

// ---------------------------------------------------------------------------
// mma_gemm: C = A[M,K] @ Wt[N,K]^T + bias, bf16x3 split precision.
// 256 threads, CTA tile 128x128 (grid.x = N/128), warp tile 32x64.
// ---------------------------------------------------------------------------
__global__ __launch_bounds__(256) void mma_gemm(
    const bf16* __restrict__ Ah, const bf16* __restrict__ Al,
    const bf16* __restrict__ Bh, const bf16* __restrict__ Bl,
    const float* __restrict__ bias, int Nvalid,
    float* __restrict__ Cf, int f_lo, int fStride,
    bf16* __restrict__ Ch, bf16* __restrict__ Cl, int cStride,
    int K, int act)
{
    __shared__ __align__(16) bf16 smAh[128 * 40];
    __shared__ __align__(16) bf16 smAl[128 * 40];
    __shared__ __align__(16) bf16 smBh[128 * 40];
    __shared__ __align__(16) bf16 smBl[128 * 40];

    const int tid = threadIdx.x;
    const int l = tid & 31, w = tid >> 5;
    const int wm = w >> 1, wn = w & 1;
    const int bm = blockIdx.y * 128, bn = blockIdx.x * 128;

    float d[2][8][4];
#pragma unroll
    for (int mt = 0; mt < 2; mt++)
#pragma unroll
        for (int nt = 0; nt < 8; nt++)
#pragma unroll
            for (int q = 0; q < 4; q++) d[mt][nt][q] = 0.f;

    const uint32_t aAh = smem_u32(smAh), aAl = smem_u32(smAl);
    const uint32_t aBh = smem_u32(smBh), aBl = smem_u32(smBl);

    const int a_row = wm * 32 + (l & 7) + ((l >> 3) & 1) * 8;
    const int a_kof = (l >> 4) * 8;
    const int b_row = wn * 64 + (l >> 4) * 8 + (l & 7);
    const int b_kof = ((l >> 3) & 1) * 8;

    for (int kc = 0; kc < K; kc += 32) {
        if (kc) __syncthreads();
#pragma unroll
        for (int i = tid; i < 512; i += 256) {
            int row = i >> 2, ch = i & 3;
            size_t ga = (size_t)(bm + row) * K + kc + ch * 8;
            size_t gb = (size_t)(bn + row) * K + kc + ch * 8;
            int sa = row * 40 + ch * 8;
            *reinterpret_cast<uint4*>(smAh + sa) = *reinterpret_cast<const uint4*>(Ah + ga);
            *reinterpret_cast<uint4*>(smAl + sa) = *reinterpret_cast<const uint4*>(Al + ga);
            *reinterpret_cast<uint4*>(smBh + sa) = *reinterpret_cast<const uint4*>(Bh + gb);
            *reinterpret_cast<uint4*>(smBl + sa) = *reinterpret_cast<const uint4*>(Bl + gb);
        }
        __syncthreads();

#pragma unroll
        for (int ks = 0; ks < 32; ks += 16) {
            uint32_t ah[2][4], al2[2][4];
#pragma unroll
            for (int mt = 0; mt < 2; mt++) {
                uint32_t off = (uint32_t)(((a_row + mt * 16) * 40 + a_kof + ks) * 2);
                LDMX4(ah[mt][0], ah[mt][1], ah[mt][2], ah[mt][3], aAh + off);
                LDMX4(al2[mt][0], al2[mt][1], al2[mt][2], al2[mt][3], aAl + off);
            }
#pragma unroll
            for (int j = 0; j < 4; j++) {
                uint32_t boff = (uint32_t)(((b_row + j * 16) * 40 + b_kof + ks) * 2);
                uint32_t bh[4], bl2[4];
                LDMX4(bh[0], bh[1], bh[2], bh[3], aBh + boff);
                LDMX4(bl2[0], bl2[1], bl2[2], bl2[3], aBl + boff);
#pragma unroll
                for (int mt = 0; mt < 2; mt++) {
                    MMA16816(d[mt][2 * j],     ah[mt],  bh[0],  bh[1]);
                    MMA16816(d[mt][2 * j],     al2[mt], bh[0],  bh[1]);
                    MMA16816(d[mt][2 * j],     ah[mt],  bl2[0], bl2[1]);
                    MMA16816(d[mt][2 * j + 1], ah[mt],  bh[2],  bh[3]);
                    MMA16816(d[mt][2 * j + 1], al2[mt], bh[2],  bh[3]);
                    MMA16816(d[mt][2 * j + 1], ah[mt],  bl2[2], bl2[3]);
                }
            }
        }
    }

#pragma unroll
    for (int mt = 0; mt < 2; mt++) {
        int r0 = bm + wm * 32 + mt * 16 + (l >> 2);
#pragma unroll
        for (int nt = 0; nt < 8; nt++) {
            int c = bn + wn * 64 + nt * 8 + (l & 3) * 2;
            if (c >= Nvalid) continue;
            float b0 = bias[c], b1 = bias[c + 1];
            float2 v0, v1;
            v0.x = d[mt][nt][0] + b0; v0.y = d[mt][nt][1] + b1;
            v1.x = d[mt][nt][2] + b0; v1.y = d[mt][nt][3] + b1;
            if (act) {
                v0.x = gelu_exact(v0.x); v0.y = gelu_exact(v0.y);
                v1.x = gelu_exact(v1.x); v1.y = gelu_exact(v1.y);
            }
            if (Cf && c >= f_lo) {
                *reinterpret_cast<float2*>(&Cf[(size_t)r0 * fStride + (c - f_lo)]) = v0;
                *reinterpret_cast<float2*>(&Cf[(size_t)(r0 + 8) * fStride + (c - f_lo)]) = v1;
            }
            if (Ch) {
                uint32_t h0, l0p, h1v, l1p;
                packpair(h0, l0p, v0.x, v0.y);
                packpair(h1v, l1p, v1.x, v1.y);
                *reinterpret_cast<uint32_t*>(&Ch[(size_t)r0 * cStride + c]) = h0;
                *reinterpret_cast<uint32_t*>(&Cl[(size_t)r0 * cStride + c]) = l0p;
                *reinterpret_cast<uint32_t*>(&Ch[(size_t)(r0 + 8) * cStride + c]) = h1v;
                *reinterpret_cast<uint32_t*>(&Cl[(size_t)(r0 + 8) * cStride + c]) = l1p;
            }
        }
    }
}

// ---------------------------------------------------------------------------
// attn_tc: tensor-core flash attention, 64q x 64k tiles, dh=32 (R6-proven).
// 128 threads = 4 warps x 16 q rows. Q pre-scaled by log2(e) (in weights).
// mode 0: j <= i.  mode 1: j < i OR (i==0 && j==0).
// ---------------------------------------------------------------------------
__global__ __launch_bounds__(128) void attn_tc(
    const bf16* __restrict__ Qh, const bf16* __restrict__ Ql, int qStride,
    const bf16* __restrict__ Kh, const bf16* __restrict__ Kl, int kStride,
    const bf16* __restrict__ Vh, const bf16* __restrict__ Vl, int vStride,
    float* __restrict__ Of, bf16* __restrict__ Oh, bf16* __restrict__ Ol, int oStride,
    int mode)
{
    __shared__ __align__(16) bf16 sQh[64 * 40], sQl[64 * 40];
    __shared__ __align__(16) bf16 sKh[64 * 40], sKl[64 * 40];
    __shared__ __align__(16) bf16 sVh[64 * 40], sVl[64 * 40];

    const int tid = threadIdx.x, l = tid & 31, w = tid >> 5;
    const int bh = blockIdx.y;
    const int hc = (bh & 3) * 32;
    const int bb = bh >> 2;
    const size_t baseQ = (size_t)bb * T_SEQ * qStride + hc;
    const size_t baseK = (size_t)bb * T_SEQ * kStride + hc;
    const size_t baseV = (size_t)bb * T_SEQ * vStride + hc;
    const size_t baseO = (size_t)bb * T_SEQ * oStride + hc;
    const int q0 = (gridDim.x - 1 - blockIdx.x) * 64;

    for (int i = tid; i < 256; i += 128) {
        int row = i >> 2, ch = i & 3;
        size_t g = baseQ + (size_t)(q0 + row) * qStride + ch * 8;
        *reinterpret_cast<uint4*>(&sQh[row * 40 + ch * 8]) = *reinterpret_cast<const uint4*>(&Qh[g]);
        *reinterpret_cast<uint4*>(&sQl[row * 40 + ch * 8]) = *reinterpret_cast<const uint4*>(&Ql[g]);
    }
    __syncthreads();

    const uint32_t aQh = smem_u32(sQh), aQl = smem_u32(sQl);
    const uint32_t aKh = smem_u32(sKh), aKl = smem_u32(sKl);
    const uint32_t aVh = smem_u32(sVh), aVl = smem_u32(sVl);

    uint32_t qh[2][4], ql[2][4];
    const int a_row = w * 16 + (l & 7) + ((l >> 3) & 1) * 8;
    const int a_col = (l >> 4) * 8;
#pragma unroll
    for (int ks = 0; ks < 2; ks++) {
        uint32_t off = (uint32_t)((a_row * 40 + a_col + ks * 16) * 2);
        LDMX4(qh[ks][0], qh[ks][1], qh[ks][2], qh[ks][3], aQh + off);
        LDMX4(ql[ks][0], ql[ks][1], ql[ks][2], ql[ks][3], aQl + off);
    }

    const float NEG = -1e30f;
    const int r0 = q0 + w * 16 + (l >> 2);
    const int r1 = r0 + 8;
    float m0 = NEG, m1 = NEG, lac0 = 0.f, lac1 = 0.f;
    float o[4][4];
#pragma unroll
    for (int n = 0; n < 4; n++)
#pragma unroll
        for (int q = 0; q < 4; q++) o[n][q] = 0.f;

    const int b_row_base = (l >> 4) * 8 + (l & 7);
    const int b_kof = ((l >> 3) & 1) * 8;

    for (int j0 = 0; j0 <= q0; j0 += 64) {
        __syncthreads();
        for (int i = tid; i < 256; i += 128) {
            int row = i >> 2, ch = i & 3;
            size_t gk = baseK + (size_t)(j0 + row) * kStride + ch * 8;
            size_t gv = baseV + (size_t)(j0 + row) * vStride + ch * 8;
            *reinterpret_cast<uint4*>(&sKh[row * 40 + ch * 8]) = *reinterpret_cast<const uint4*>(&Kh[gk]);
            *reinterpret_cast<uint4*>(&sKl[row * 40 + ch * 8]) = *reinterpret_cast<const uint4*>(&Kl[gk]);
            *reinterpret_cast<uint4*>(&sVh[row * 40 + ch * 8]) = *reinterpret_cast<const uint4*>(&Vh[gv]);
            *reinterpret_cast<uint4*>(&sVl[row * 40 + ch * 8]) = *reinterpret_cast<const uint4*>(&Vl[gv]);
        }
        __syncthreads();

        // ---- S = Q K^T (bf16x3) ----
        float s[8][4];
#pragma unroll
        for (int nt = 0; nt < 8; nt++)
#pragma unroll
            for (int q = 0; q < 4; q++) s[nt][q] = 0.f;

#pragma unroll
        for (int ks = 0; ks < 2; ks++) {
#pragma unroll
            for (int jp = 0; jp < 4; jp++) {
                uint32_t off = (uint32_t)(((jp * 16 + b_row_base) * 40 + b_kof + ks * 16) * 2);
                uint32_t kb[4], kbl[4];
                LDMX4(kb[0], kb[1], kb[2], kb[3], aKh + off);
                LDMX4(kbl[0], kbl[1], kbl[2], kbl[3], aKl + off);
                MMA16816(s[2 * jp],     qh[ks], kb[0],  kb[1]);
                MMA16816(s[2 * jp],     ql[ks], kb[0],  kb[1]);
                MMA16816(s[2 * jp],     qh[ks], kbl[0], kbl[1]);
                MMA16816(s[2 * jp + 1], qh[ks], kb[2],  kb[3]);
                MMA16816(s[2 * jp + 1], ql[ks], kb[2],  kb[3]);
                MMA16816(s[2 * jp + 1], qh[ks], kbl[2], kbl[3]);
            }
        }

        // ---- mask (diagonal tile only) ----
        if (j0 >= q0) {
#pragma unroll
            for (int nt = 0; nt < 8; nt++) {
                int cb = j0 + nt * 8 + (l & 3) * 2;
                if (mode == 0) {
                    if (cb     > r0) s[nt][0] = NEG;
                    if (cb + 1 > r0) s[nt][1] = NEG;
                    if (cb     > r1) s[nt][2] = NEG;
                    if (cb + 1 > r1) s[nt][3] = NEG;
                } else {
                    if (!(cb     < r0 || (r0 == 0 && cb == 0))) s[nt][0] = NEG;
                    if (!(cb + 1 < r0))                          s[nt][1] = NEG;
                    if (!(cb     < r1)) s[nt][2] = NEG;
                    if (!(cb + 1 < r1)) s[nt][3] = NEG;
                }
            }
        }

        // ---- online softmax ----
        float ml0 = NEG, ml1 = NEG;
#pragma unroll
        for (int nt = 0; nt < 8; nt++) {
            ml0 = fmaxf(ml0, fmaxf(s[nt][0], s[nt][1]));
            ml1 = fmaxf(ml1, fmaxf(s[nt][2], s[nt][3]));
        }
        ml0 = fmaxf(ml0, __shfl_xor_sync(0xffffffffu, ml0, 1));
        ml0 = fmaxf(ml0, __shfl_xor_sync(0xffffffffu, ml0, 2));
        ml1 = fmaxf(ml1, __shfl_xor_sync(0xffffffffu, ml1, 1));
        ml1 = fmaxf(ml1, __shfl_xor_sync(0xffffffffu, ml1, 2));
        float mn0 = fmaxf(m0, ml0), mn1 = fmaxf(m1, ml1);
        float sc0 = ex2(m0 - mn0), sc1 = ex2(m1 - mn1);

        uint32_t pah[4][4], pal[4][4];
        float ps0 = 0.f, ps1 = 0.f;
#pragma unroll
        for (int t = 0; t < 4; t++) {
#pragma unroll
            for (int half = 0; half < 2; half++) {
                int nt = 2 * t + half;
                float p0 = ex2(s[nt][0] - mn0), p1 = ex2(s[nt][1] - mn0);
                float p2 = ex2(s[nt][2] - mn1), p3 = ex2(s[nt][3] - mn1);
                ps0 += p0 + p1; ps1 += p2 + p3;
                packpair(pah[t][2 * half],     pal[t][2 * half],     p0, p1);
                packpair(pah[t][2 * half + 1], pal[t][2 * half + 1], p2, p3);
            }
        }
        lac0 = lac0 * sc0 + ps0;
        lac1 = lac1 * sc1 + ps1;
#pragma unroll
        for (int n = 0; n < 4; n++) {
            o[n][0] *= sc0; o[n][1] *= sc0; o[n][2] *= sc1; o[n][3] *= sc1;
        }

        // ---- O += P V (bf16x3), V via trans ldmatrix ----
#pragma unroll
        for (int t = 0; t < 4; t++) {
#pragma unroll
            for (int np = 0; np < 2; np++) {
                uint32_t off = (uint32_t)(((t * 16 + (l & 15)) * 40 + np * 16 + (l >> 4) * 8) * 2);
                uint32_t vb[4], vbl[4];
                LDMX4T(vb[0], vb[1], vb[2], vb[3], aVh + off);
                LDMX4T(vbl[0], vbl[1], vbl[2], vbl[3], aVl + off);
                MMA16816(o[2 * np],     pah[t], vb[0],  vb[1]);
                MMA16816(o[2 * np],     pal[t], vb[0],  vb[1]);
                MMA16816(o[2 * np],     pah[t], vbl[0], vbl[1]);
                MMA16816(o[2 * np + 1], pah[t], vb[2],  vb[3]);
                MMA16816(o[2 * np + 1], pal[t], vb[2],  vb[3]);
                MMA16816(o[2 * np + 1], pah[t], vbl[2], vbl[3]);
            }
        }
        m0 = mn0; m1 = mn1;
    }

    lac0 += __shfl_xor_sync(0xffffffffu, lac0, 1);
    lac0 += __shfl_xor_sync(0xffffffffu, lac0, 2);
    lac1 += __shfl_xor_sync(0xffffffffu, lac1, 1);
    lac1 += __shfl_xor_sync(0xffffffffu, lac1, 2);
    float inv0 = 1.f / lac0, inv1 = 1.f / lac1;

#pragma unroll
    for (int nt = 0; nt < 4; nt++) {
        int col = nt * 8 + (l & 3) * 2;
        float v00 = o[nt][0] * inv0, v01 = o[nt][1] * inv0;
        float v10 = o[nt][2] * inv1, v11 = o[nt][3] * inv1;
        if (Of) {
            float2 a; a.x = v00; a.y = v01;
            float2 b; b.x = v10; b.y = v11;
            *reinterpret_cast<float2*>(&Of[baseO + (size_t)r0 * oStride + col]) = a;
            *reinterpret_cast<float2*>(&Of[baseO + (size_t)r1 * oStride + col]) = b;
        }
        if (Oh) {
            uint32_t h0, l0p, h1v, l1p;
            packpair(h0, l0p, v00, v01);
            packpair(h1v, l1p, v10, v11);
            *reinterpret_cast<uint32_t*>(&Oh[baseO + (size_t)r0 * oStride + col]) = h0;
            *reinterpret_cast<uint32_t*>(&Ol[baseO + (size_t)r0 * oStride + col]) = l0p;
            *reinterpret_cast<uint32_t*>(&Oh[baseO + (size_t)r1 * oStride + col]) = h1v;
            *reinterpret_cast<uint32_t*>(&Ol[baseO + (size_t)r1 * oStride + col]) = l1p;
        }
    }
}

// ---------------------------------------------------------------------------
// out = LayerNorm(A + B) * gamma + beta; fp32 out optional, bf16 hi/lo optional
// ---------------------------------------------------------------------------
__global__ void add_ln_k(const float* __restrict__ A, const float* __restrict__ Bv,
                         const float* __restrict__ gam, const float* __restrict__ bet,
                         float* __restrict__ outf, bf16* __restrict__ outh,
                         bf16* __restrict__ outl)
{
    int row = blockIdx.x;
    int d = threadIdx.x;  // 128
    float x = A[(size_t)row * 128 + d] + Bv[(size_t)row * 128 + d];

    __shared__ float ws[4], ws2[4];
    float v = x;
#pragma unroll
    for (int off = 16; off; off >>= 1) v += __shfl_xor_sync(0xffffffffu, v, off);
    if ((d & 31) == 0) ws[d >> 5] = v;
    __syncthreads();
    float mean = (ws[0] + ws[1] + ws[2] + ws[3]) * (1.f / 128.f);
    float dif = x - mean;
    float v2 = dif * dif;
#pragma unroll
    for (int off = 16; off; off >>= 1) v2 += __shfl_xor_sync(0xffffffffu, v2, off);
    if ((d & 31) == 0) ws2[d >> 5] = v2;
    __syncthreads();
    float var = (ws2[0] + ws2[1] + ws2[2] + ws2[3]) * (1.f / 128.f);
    float y = dif * rsqrtf(var + 1e-5f) * gam[d] + bet[d];
    if (outf) outf[(size_t)row * 128 + d] = y;
    if (outh) {
        bf16 h = __float2bfloat16(y);
        outh[(size_t)row * 128 + d] = h;
        outl[(size_t)row * 128 + d] = __float2bfloat16(y - __bfloat162float(h));
    }
}

// ---------------------------------------------------------------------------
extern "C" void kernel_launch(void* const* d_in, const int* in_sizes, int n_in,
                              void* d_out, int out_size)
{
    const float* kq    = (const float*)d_in[0];
    const float* v_in  = (const float*)d_in[1];
    const float* A_Wk  = (const float*)d_in[2];
    const float* A_bk  = (const float*)d_in[3];
    const float* A_Wq  = (const float*)d_in[4];
    const float* A_bq  = (const float*)d_in[5];
    const float* A_Wv  = (const float*)d_in[6];
    const float* A_bv  = (const float*)d_in[7];
    const float* A_f1W = (const float*)d_in[8];
    const float* A_f1b = (const float*)d_in[9];
    const float* A_f2W = (const float*)d_in[10];
    const float* A_f2b = (const float*)d_in[11];
    const float* A_n1g = (const float*)d_in[12];
    const float* A_n1b = (const float*)d_in[13];
    const float* A_n2g = (const float*)d_in[14];
    const float* A_n2b = (const float*)d_in[15];
    const float* B_Wk  = (const float*)d_in[16];
    const float* B_bk  = (const float*)d_in[17];
    const float* B_Wq  = (const float*)d_in[18];
    const float* B_bq  = (const float*)d_in[19];
    const float* B_Wv  = (const float*)d_in[20];
    const float* B_bv  = (const float*)d_in[21];
    const float* B_f1W = (const float*)d_in[22];
    const float* B_f1b = (const float*)d_in[23];
    const float* B_f2W = (const float*)d_in[24];
    const float* B_f2b = (const float*)d_in[25];
    const float* out_W = (const float*)d_in[26];
    const float* out_b = (const float*)d_in[27];
    float* out = (float*)d_out;

    float* pool = nullptr;
    cudaGetSymbolAddress((void**)&pool, g_scratch);

    const size_t S = (size_t)R_TOTAL * 128;  // 2M floats per slot
    float* attnA = pool + 0 * S;
    float* h1    = pool + 1 * S;
    float* t1    = pool + 2 * S;
    float* Va    = pool + 3 * S;
    bf16* qkvA_h = (bf16*)(pool + 4 * S);    // R x 384 (slots 4-5)
    bf16* qkvA_l = (bf16*)(pool + 6 * S);    // slots 6-7
    bf16* sXh    = (bf16*)(pool + 8 * S);
    bf16* sXl    = (bf16*)(pool + 9 * S);
    bf16* ffh    = (bf16*)(pool + 10 * S);   // R x 512 (slots 10-11)
    bf16* ffl    = (bf16*)(pool + 12 * S);   // slots 12-13
    bf16* kqh    = (bf16*)(pool + 14 * S);
    bf16* kql    = (bf16*)(pool + 15 * S);
    bf16* kq2h   = (bf16*)(pool + 16 * S);   // R x 256
    bf16* kq2l   = (bf16*)(pool + 17 * S);
    bf16* v2h    = (bf16*)(pool + 18 * S);
    bf16* v2l    = (bf16*)(pool + 19 * S);
    bf16* at2h   = (bf16*)(pool + 20 * S);
    bf16* at2l   = (bf16*)(pool + 21 * S);
    bf16* vAh    = (bf16*)(pool + 22 * S);
    bf16* vAl    = (bf16*)(pool + 23 * S);
    float* Wc    = pool + 24 * S;            // 512x32 fp32
    float* bc    = Wc + 512 * 32;
    float* qkvbA = bc + 64;                  // 384
    float* kqb2  = qkvbA + 384;              // 256
    // weight arena: hi at wArena, lo at wArena + PW_TOTAL (segment layout per PS_START)
    bf16* wArena = (bf16*)(pool + 25 * S);
    bf16* wH = wArena;
    bf16* wL = wArena + PW_TOTAL;
    bf16* qkvW_h = wH + 0;       bf16* qkvW_l = wL + 0;        // segs 0-2 (384x128)
    bf16* kqW_h  = wH + 49152;   bf16* kqW_l  = wL + 49152;    // segs 3-4 (256x64)
    bf16* bWv_h  = wH + 65536;   bf16* bWv_l  = wL + 65536;    // seg 5 (128x128)
    bf16* af1_h  = wH + 81920;   bf16* af1_l  = wL + 81920;    // seg 6 (512x128)
    bf16* af2_h  = wH + 147456;  bf16* af2_l  = wL + 147456;   // seg 7 (128x512)
    bf16* bf1_h  = wH + 212992;  bf16* bf1_l  = wL + 212992;   // seg 8 (512x128)
    bf16* wc_h   = wH + 278528;  bf16* wc_l   = wL + 278528;   // seg 9 (128x512)

    // ---- weight prep: 2 launches ----
    smallprep_k<<<(512*32 + 32 + 640 + 255) / 256, 256>>>(
        B_f2W, out_W, B_f2b, out_b, A_bk, A_bq, A_bv, B_bk, B_bq,
        Wc, bc, qkvbA, kqb2);
    Prep10 p10;
    p10.s[0] = A_Wk; p10.s[1] = A_Wq; p10.s[2] = A_Wv;
    p10.s[3] = B_Wk; p10.s[4] = B_Wq; p10.s[5] = B_Wv;
    p10.s[6] = A_f1W; p10.s[7] = A_f2W; p10.s[8] = B_f1W; p10.s[9] = Wc;
    prepw_k<<<(PW_TOTAL + 255) / 256, 256>>>(p10, wH, wL);

    dim3 blk256(256);
    dim3 attnGrid(T_SEQ / 64, 8 * NHEAD);  // (32, 32)

    // ---- Layer A ----
    splitcat_k<<<(R_TOTAL*32+255)/256, 256>>>(kq, v_in, sXh, sXl);
    mma_gemm<<<dim3(3, 128), blk256>>>(sXh, sXl, qkvW_h, qkvW_l, qkvbA, 384,
                                       Va, 256, 128, qkvA_h, qkvA_l, 384, 128, 0);
    attn_tc<<<attnGrid, 128>>>(qkvA_h + 128, qkvA_l + 128, 384,
                               qkvA_h, qkvA_l, 384,
                               qkvA_h + 256, qkvA_l + 256, 384,
                               attnA, nullptr, nullptr, 128, 0);
    add_ln_k<<<R_TOTAL, 128>>>(Va, attnA, A_n1g, A_n1b, h1, sXh, sXl);
    mma_gemm<<<dim3(4, 128), blk256>>>(sXh, sXl, af1_h, af1_l, A_f1b, 512,
                                       nullptr, 0, 0, ffh, ffl, 512, 128, 1);
    mma_gemm<<<dim3(1, 128), blk256>>>(ffh, ffl, af2_h, af2_l, A_f2b, 128,
                                       t1, 0, 128, nullptr, nullptr, 0, 512, 0);
    add_ln_k<<<R_TOTAL, 128>>>(h1, t1, A_n2g, A_n2b, nullptr, vAh, vAl);

    // ---- Layer B ----
    split_k<<<(R_TOTAL*16+255)/256, 256>>>(kq, kqh, kql, R_TOTAL*16);
    mma_gemm<<<dim3(2, 128), blk256>>>(kqh, kql, kqW_h, kqW_l, kqb2, 256,
                                       nullptr, 0, 0, kq2h, kq2l, 256, 64, 0);
    mma_gemm<<<dim3(1, 128), blk256>>>(vAh, vAl, bWv_h, bWv_l, B_bv, 128,
                                       nullptr, 0, 0, v2h, v2l, 128, 128, 0);
    attn_tc<<<attnGrid, 128>>>(kq2h + 128, kq2l + 128, 256,
                               kq2h, kq2l, 256,
                               v2h, v2l, 128,
                               nullptr, at2h, at2l, 128, 1);
    mma_gemm<<<dim3(4, 128), blk256>>>(at2h, at2l, bf1_h, bf1_l, B_f1b, 512,
                                       nullptr, 0, 0, ffh, ffl, 512, 128, 1);
    // folded FF2B+head: N=32 valid, padded Wt[128,512]
    mma_gemm<<<dim3(1, 128), blk256>>>(ffh, ffl, wc_h, wc_l, bc, 32,
                                       out, 0, 32, nullptr, nullptr, 0, 512, 0);
}

// round 9
// speedup vs baseline: 1.1034x; 1.0047x over previous
#include <cuda_runtime.h>
#include <cuda_bf16.h>
#include <math.h>
#include <stdint.h>

// ---------------------------------------------------------------------------
// Model_19104014532987: 2-layer transformer
// B=8 T=2048 DKQ=64 DV=64 EKQ=EV=128 H=4 dh=32 FF=512 OUT=32, R=16384
// All heavy math on mma.sync bf16 (HMMA), bf16x3 split precision.
// cp.async double-buffered pipelines in GEMM and attention.
// ---------------------------------------------------------------------------

#define R_TOTAL 16384
#define T_SEQ   2048
#define EMB     128
#define NHEAD   4
#define LOG2E   1.4426950408889634f

typedef __nv_bfloat16 bf16;

// Scratch pool: 56M floats (224 MB), static device allocation (allowed).
static __device__ __align__(256) float g_scratch[56ull * 1024 * 1024];

__device__ __forceinline__ float gelu_exact(float x) {
    return 0.5f * x * (1.0f + erff(x * 0.70710678118654752440f));
}
__device__ __forceinline__ float ex2(float x) {
    float y; asm("ex2.approx.ftz.f32 %0, %1;" : "=f"(y) : "f"(x)); return y;
}
__device__ __forceinline__ uint32_t smem_u32(const void* p) {
    uint32_t a;
    asm("{ .reg .u64 t; cvta.to.shared.u64 t, %1; cvt.u32.u64 %0, t; }" : "=r"(a) : "l"(p));
    return a;
}

#define LDMX4(r0, r1, r2, r3, addr) \
    asm volatile("ldmatrix.sync.aligned.m8n8.x4.shared.b16 {%0,%1,%2,%3}, [%4];" \
        : "=r"(r0), "=r"(r1), "=r"(r2), "=r"(r3) : "r"(addr))
#define LDMX4T(r0, r1, r2, r3, addr) \
    asm volatile("ldmatrix.sync.aligned.m8n8.x4.trans.shared.b16 {%0,%1,%2,%3}, [%4];" \
        : "=r"(r0), "=r"(r1), "=r"(r2), "=r"(r3) : "r"(addr))
#define MMA16816(d, a, b0, b1) \
    asm volatile("mma.sync.aligned.m16n8k16.row.col.f32.bf16.bf16.f32 " \
        "{%0,%1,%2,%3}, {%4,%5,%6,%7}, {%8,%9}, {%0,%1,%2,%3};" \
        : "+f"((d)[0]), "+f"((d)[1]), "+f"((d)[2]), "+f"((d)[3]) \
        : "r"((a)[0]), "r"((a)[1]), "r"((a)[2]), "r"((a)[3]), "r"(b0), "r"(b1))

#define CP_ASYNC16(saddr, gptr) \
    asm volatile("cp.async.cg.shared.global [%0], [%1], 16;" :: "r"(saddr), "l"(gptr))
#define CP_COMMIT() asm volatile("cp.async.commit_group;" ::: "memory")
#define CP_WAIT1()  asm volatile("cp.async.wait_group 1;" ::: "memory")
#define CP_WAIT0()  asm volatile("cp.async.wait_group 0;" ::: "memory")

__device__ __forceinline__ void packpair(uint32_t& ph, uint32_t& pl, float x, float y) {
    bf16 hx = __float2bfloat16(x), hy = __float2bfloat16(y);
    __nv_bfloat162 t; t.x = hx; t.y = hy;
    ph = *reinterpret_cast<uint32_t*>(&t);
    __nv_bfloat162 u;
    u.x = __float2bfloat16(x - __bfloat162float(hx));
    u.y = __float2bfloat16(y - __bfloat162float(hy));
    pl = *reinterpret_cast<uint32_t*>(&u);
}

// ---------------------------------------------------------------------------
// activation split kernels
// ---------------------------------------------------------------------------
__global__ void split_k(const float* __restrict__ x, bf16* __restrict__ h,
                        bf16* __restrict__ l, int n4) {
    int i = blockIdx.x * 256 + threadIdx.x;
    if (i >= n4) return;
    float4 v = reinterpret_cast<const float4*>(x)[i];
    uint32_t h01, l01, h23, l23;
    packpair(h01, l01, v.x, v.y);
    packpair(h23, l23, v.z, v.w);
    reinterpret_cast<uint32_t*>(h)[i * 2]     = h01;
    reinterpret_cast<uint32_t*>(h)[i * 2 + 1] = h23;
    reinterpret_cast<uint32_t*>(l)[i * 2]     = l01;
    reinterpret_cast<uint32_t*>(l)[i * 2 + 1] = l23;
}

__global__ void splitcat_k(const float* __restrict__ kq, const float* __restrict__ v,
                           bf16* __restrict__ h, bf16* __restrict__ l) {
    int i = blockIdx.x * 256 + threadIdx.x;
    if (i >= R_TOTAL * 32) return;
    int e = i * 4;
    int r = e >> 7, d = e & 127;
    float4 val = (d < 64)
        ? *reinterpret_cast<const float4*>(&kq[(size_t)r * 64 + d])
        : *reinterpret_cast<const float4*>(&v[(size_t)r * 64 + (d - 64)]);
    uint32_t h01, l01, h23, l23;
    packpair(h01, l01, val.x, val.y);
    packpair(h23, l23, val.z, val.w);
    reinterpret_cast<uint32_t*>(h)[i * 2]     = h01;
    reinterpret_cast<uint32_t*>(h)[i * 2 + 1] = h23;
    reinterpret_cast<uint32_t*>(l)[i * 2]     = l01;
    reinterpret_cast<uint32_t*>(l)[i * 2 + 1] = l23;
}

// ---------------------------------------------------------------------------
// fused weight prep
// ---------------------------------------------------------------------------
__global__ void smallprep_k(const float* __restrict__ f2W, const float* __restrict__ outW,
                            const float* __restrict__ f2b, const float* __restrict__ out_b,
                            const float* __restrict__ A_bk, const float* __restrict__ A_bq,
                            const float* __restrict__ A_bv, const float* __restrict__ B_bk,
                            const float* __restrict__ B_bq,
                            float* __restrict__ Wc, float* __restrict__ bc,
                            float* __restrict__ qkvbA, float* __restrict__ kqb2)
{
    int gid = blockIdx.x * 256 + threadIdx.x;
    if (gid < 512 * 32) {
        int k = gid >> 5, n = gid & 31;
        float s = 0.f;
        for (int j = 0; j < 128; j++) s = fmaf(f2W[k * 128 + j], outW[j * 32 + n], s);
        Wc[gid] = s;
        return;
    }
    int r = gid - 512 * 32;
    if (r < 32) {
        float s = out_b[r];
        for (int j = 0; j < 128; j++) s = fmaf(f2b[j], outW[j * 32 + r], s);
        bc[r] = s;
        return;
    }
    r -= 32;
    if (r < 384) {
        float v = (r < 128) ? A_bk[r] : (r < 256) ? A_bq[r - 128] * LOG2E : A_bv[r - 256];
        qkvbA[r] = v;
        return;
    }
    r -= 384;
    if (r < 256) {
        kqb2[r] = (r < 128) ? B_bk[r] : B_bq[r - 128] * LOG2E;
    }
}

struct Prep10 { const float* s[10]; };
__device__ __constant__ const int  PS_START[10] = {0,16384,32768,49152,57344,65536,81920,147456,212992,278528};
#define PW_TOTAL 344064
__device__ __constant__ const int  PS_KD[10]    = {128,128,128, 64, 64,128,128,512,128,512};
__device__ __constant__ const int  PS_ND[10]    = {128,128,128,128,128,128,512,128,512, 32};
__device__ __constant__ const float PS_SC[10]   = {1.f,LOG2E,1.f,1.f,LOG2E,1.f,1.f,1.f,1.f,1.f};

__global__ void prepw_k(Prep10 srcs, bf16* __restrict__ th, bf16* __restrict__ tl) {
    int gid = blockIdx.x * 256 + threadIdx.x;
    if (gid >= PW_TOTAL) return;
    int s = 0;
#pragma unroll
    for (int i = 1; i < 10; i++) if (gid >= PS_START[i]) s = i;
    int idx = gid - PS_START[s];
    int Kd = PS_KD[s], Nd = PS_ND[s];
    int n = idx / Kd, k = idx - n * Kd;
    float w = (n < Nd) ? srcs.s[s][(size_t)k * Nd + n] * PS_SC[s] : 0.f;
    bf16 h = __float2bfloat16(w);
    th[gid] = h;
    tl[gid] = __float2bfloat16(w - __bfloat162float(h));
}

// ---------------------------------------------------------------------------
// mma_gemm: C = A[M,K] @ Wt[N,K]^T + bias, bf16x3 split, cp.async pipelined.
// 256 threads, CTA tile 128x128, warp tile 32x64. Dynamic smem 80KB (2 bufs).
// ---------------------------------------------------------------------------
#define GEMM_SMEM 81920
__global__ __launch_bounds__(256) void mma_gemm(
    const bf16* __restrict__ Ah, const bf16* __restrict__ Al,
    const bf16* __restrict__ Bh, const bf16* __restrict__ Bl,
    const float* __restrict__ bias, int Nvalid,
    float* __restrict__ Cf, int f_lo, int fStride,
    bf16* __restrict__ Ch, bf16* __restrict__ Cl, int cStride,
    int K, int act)
{
    extern __shared__ __align__(16) char dsm[];
    bf16* smA_h = (bf16*)dsm;            // [2][5120]
    bf16* smA_l = smA_h + 10240;
    bf16* smB_h = smA_l + 10240;
    bf16* smB_l = smB_h + 10240;

    const int tid = threadIdx.x;
    const int l = tid & 31, w = tid >> 5;
    const int wm = w >> 1, wn = w & 1;
    const int bm = blockIdx.y * 128, bn = blockIdx.x * 128;

    float d[2][8][4];
#pragma unroll
    for (int mt = 0; mt < 2; mt++)
#pragma unroll
        for (int nt = 0; nt < 8; nt++)
#pragma unroll
            for (int q = 0; q < 4; q++) d[mt][nt][q] = 0.f;

    const uint32_t aAh = smem_u32(smA_h), aAl = smem_u32(smA_l);
    const uint32_t aBh = smem_u32(smB_h), aBl = smem_u32(smB_l);

    const int a_row = wm * 32 + (l & 7) + ((l >> 3) & 1) * 8;
    const int a_kof = (l >> 4) * 8;
    const int b_row = wn * 64 + (l >> 4) * 8 + (l & 7);
    const int b_kof = ((l >> 3) & 1) * 8;

    auto issue_chunk = [&](int kcElem, int buf) {
#pragma unroll
        for (int i = tid; i < 512; i += 256) {
            int row = i >> 2, ch = i & 3;
            size_t ga = (size_t)(bm + row) * K + kcElem + ch * 8;
            size_t gb = (size_t)(bn + row) * K + kcElem + ch * 8;
            int sa = buf * 5120 + row * 40 + ch * 8;
            CP_ASYNC16(smem_u32(smA_h + sa), Ah + ga);
            CP_ASYNC16(smem_u32(smA_l + sa), Al + ga);
            CP_ASYNC16(smem_u32(smB_h + sa), Bh + gb);
            CP_ASYNC16(smem_u32(smB_l + sa), Bl + gb);
        }
    };

    const int nch = K >> 5;
    issue_chunk(0, 0);
    CP_COMMIT();

    for (int kc = 0; kc < nch; kc++) {
        const int buf = kc & 1;
        if (kc + 1 < nch) { issue_chunk((kc + 1) << 5, buf ^ 1); CP_COMMIT(); CP_WAIT1(); }
        else              { CP_WAIT0(); }
        __syncthreads();

        const uint32_t bufB = (uint32_t)buf * 10240;
#pragma unroll
        for (int ks = 0; ks < 32; ks += 16) {
            uint32_t ah[2][4], al2[2][4];
#pragma unroll
            for (int mt = 0; mt < 2; mt++) {
                uint32_t off = bufB + (uint32_t)(((a_row + mt * 16) * 40 + a_kof + ks) * 2);
                LDMX4(ah[mt][0], ah[mt][1], ah[mt][2], ah[mt][3], aAh + off);
                LDMX4(al2[mt][0], al2[mt][1], al2[mt][2], al2[mt][3], aAl + off);
            }
#pragma unroll
            for (int j = 0; j < 4; j++) {
                uint32_t boff = bufB + (uint32_t)(((b_row + j * 16) * 40 + b_kof + ks) * 2);
                uint32_t bh[4], bl2[4];
                LDMX4(bh[0], bh[1], bh[2], bh[3], aBh + boff);
                LDMX4(bl2[0], bl2[1], bl2[2], bl2[3], aBl + boff);
#pragma unroll
                for (int mt = 0; mt < 2; mt++) {
                    MMA16816(d[mt][2 * j],     ah[mt],  bh[0],  bh[1]);
                    MMA16816(d[mt][2 * j],     al2[mt], bh[0],  bh[1]);
                    MMA16816(d[mt][2 * j],     ah[mt],  bl2[0], bl2[1]);
                    MMA16816(d[mt][2 * j + 1], ah[mt],  bh[2],  bh[3]);
                    MMA16816(d[mt][2 * j + 1], al2[mt], bh[2],  bh[3]);
                    MMA16816(d[mt][2 * j + 1], ah[mt],  bl2[2], bl2[3]);
                }
            }
        }
        __syncthreads();
    }

#pragma unroll
    for (int mt = 0; mt < 2; mt++) {
        int r0 = bm + wm * 32 + mt * 16 + (l >> 2);
#pragma unroll
        for (int nt = 0; nt < 8; nt++) {
            int c = bn + wn * 64 + nt * 8 + (l & 3) * 2;
            if (c >= Nvalid) continue;
            float b0 = bias[c], b1 = bias[c + 1];
            float2 v0, v1;
            v0.x = d[mt][nt][0] + b0; v0.y = d[mt][nt][1] + b1;
            v1.x = d[mt][nt][2] + b0; v1.y = d[mt][nt][3] + b1;
            if (act) {
                v0.x = gelu_exact(v0.x); v0.y = gelu_exact(v0.y);
                v1.x = gelu_exact(v1.x); v1.y = gelu_exact(v1.y);
            }
            if (Cf && c >= f_lo) {
                *reinterpret_cast<float2*>(&Cf[(size_t)r0 * fStride + (c - f_lo)]) = v0;
                *reinterpret_cast<float2*>(&Cf[(size_t)(r0 + 8) * fStride + (c - f_lo)]) = v1;
            }
            if (Ch) {
                uint32_t h0, l0p, h1v, l1p;
                packpair(h0, l0p, v0.x, v0.y);
                packpair(h1v, l1p, v1.x, v1.y);
                *reinterpret_cast<uint32_t*>(&Ch[(size_t)r0 * cStride + c]) = h0;
                *reinterpret_cast<uint32_t*>(&Cl[(size_t)r0 * cStride + c]) = l0p;
                *reinterpret_cast<uint32_t*>(&Ch[(size_t)(r0 + 8) * cStride + c]) = h1v;
                *reinterpret_cast<uint32_t*>(&Cl[(size_t)(r0 + 8) * cStride + c]) = l1p;
            }
        }
    }
}

// ---------------------------------------------------------------------------
// attn_tc: tensor-core flash attention, 64q x 64k tiles, dh=32,
// cp.async double-buffered K/V. 128 threads = 4 warps x 16 q rows.
// Q pre-scaled by log2(e). mode 0: j <= i. mode 1: j < i OR (i==0 && j==0).
// ---------------------------------------------------------------------------
#define ATTN_SMEM 51200
__global__ __launch_bounds__(128) void attn_tc(
    const bf16* __restrict__ Qh, const bf16* __restrict__ Ql, int qStride,
    const bf16* __restrict__ Kh, const bf16* __restrict__ Kl, int kStride,
    const bf16* __restrict__ Vh, const bf16* __restrict__ Vl, int vStride,
    float* __restrict__ Of, bf16* __restrict__ Oh, bf16* __restrict__ Ol, int oStride,
    int mode)
{
    extern __shared__ __align__(16) char dsm[];
    bf16* sQh = (bf16*)dsm;        // 2560
    bf16* sQl = sQh + 2560;
    bf16* sKh = sQl + 2560;        // [2][2560]
    bf16* sKl = sKh + 5120;
    bf16* sVh = sKl + 5120;
    bf16* sVl = sVh + 5120;

    const int tid = threadIdx.x, l = tid & 31, w = tid >> 5;
    const int bh = blockIdx.y;
    const int hc = (bh & 3) * 32;
    const int bb = bh >> 2;
    const size_t baseQ = (size_t)bb * T_SEQ * qStride + hc;
    const size_t baseK = (size_t)bb * T_SEQ * kStride + hc;
    const size_t baseV = (size_t)bb * T_SEQ * vStride + hc;
    const size_t baseO = (size_t)bb * T_SEQ * oStride + hc;
    const int q0 = (gridDim.x - 1 - blockIdx.x) * 64;

    auto issue_kv = [&](int j0, int buf) {
#pragma unroll
        for (int i = tid; i < 256; i += 128) {
            int row = i >> 2, ch = i & 3;
            size_t gk = baseK + (size_t)(j0 + row) * kStride + ch * 8;
            size_t gv = baseV + (size_t)(j0 + row) * vStride + ch * 8;
            int sa = buf * 2560 + row * 40 + ch * 8;
            CP_ASYNC16(smem_u32(sKh + sa), Kh + gk);
            CP_ASYNC16(smem_u32(sKl + sa), Kl + gk);
            CP_ASYNC16(smem_u32(sVh + sa), Vh + gv);
            CP_ASYNC16(smem_u32(sVl + sa), Vl + gv);
        }
    };

    issue_kv(0, 0);
    CP_COMMIT();

    // Q tile -> smem (regular loads), then fragments
    for (int i = tid; i < 256; i += 128) {
        int row = i >> 2, ch = i & 3;
        size_t g = baseQ + (size_t)(q0 + row) * qStride + ch * 8;
        *reinterpret_cast<uint4*>(&sQh[row * 40 + ch * 8]) = *reinterpret_cast<const uint4*>(&Qh[g]);
        *reinterpret_cast<uint4*>(&sQl[row * 40 + ch * 8]) = *reinterpret_cast<const uint4*>(&Ql[g]);
    }
    __syncthreads();

    const uint32_t aQh = smem_u32(sQh), aQl = smem_u32(sQl);
    const uint32_t aKh = smem_u32(sKh), aKl = smem_u32(sKl);
    const uint32_t aVh = smem_u32(sVh), aVl = smem_u32(sVl);

    uint32_t qh[2][4], ql[2][4];
    const int a_row = w * 16 + (l & 7) + ((l >> 3) & 1) * 8;
    const int a_col = (l >> 4) * 8;
#pragma unroll
    for (int ks = 0; ks < 2; ks++) {
        uint32_t off = (uint32_t)((a_row * 40 + a_col + ks * 16) * 2);
        LDMX4(qh[ks][0], qh[ks][1], qh[ks][2], qh[ks][3], aQh + off);
        LDMX4(ql[ks][0], ql[ks][1], ql[ks][2], ql[ks][3], aQl + off);
    }

    const float NEG = -1e30f;
    const int r0 = q0 + w * 16 + (l >> 2);
    const int r1 = r0 + 8;
    float m0 = NEG, m1 = NEG, lac0 = 0.f, lac1 = 0.f;
    float o[4][4];
#pragma unroll
    for (int n = 0; n < 4; n++)
#pragma unroll
        for (int q = 0; q < 4; q++) o[n][q] = 0.f;

    const int b_row_base = (l >> 4) * 8 + (l & 7);
    const int b_kof = ((l >> 3) & 1) * 8;
    const int ntiles = (q0 >> 6) + 1;

    for (int jt = 0; jt < ntiles; jt++) {
        const int j0 = jt * 64;
        const int buf = jt & 1;
        if (jt + 1 < ntiles) { issue_kv(j0 + 64, buf ^ 1); CP_COMMIT(); CP_WAIT1(); }
        else                 { CP_WAIT0(); }
        __syncthreads();
        const uint32_t bufB = (uint32_t)buf * 5120;

        // ---- S = Q K^T (bf16x3) ----
        float s[8][4];
#pragma unroll
        for (int nt = 0; nt < 8; nt++)
#pragma unroll
            for (int q = 0; q < 4; q++) s[nt][q] = 0.f;

#pragma unroll
        for (int ks = 0; ks < 2; ks++) {
#pragma unroll
            for (int jp = 0; jp < 4; jp++) {
                uint32_t off = bufB + (uint32_t)(((jp * 16 + b_row_base) * 40 + b_kof + ks * 16) * 2);
                uint32_t kb[4], kbl[4];
                LDMX4(kb[0], kb[1], kb[2], kb[3], aKh + off);
                LDMX4(kbl[0], kbl[1], kbl[2], kbl[3], aKl + off);
                MMA16816(s[2 * jp],     qh[ks], kb[0],  kb[1]);
                MMA16816(s[2 * jp],     ql[ks], kb[0],  kb[1]);
                MMA16816(s[2 * jp],     qh[ks], kbl[0], kbl[1]);
                MMA16816(s[2 * jp + 1], qh[ks], kb[2],  kb[3]);
                MMA16816(s[2 * jp + 1], ql[ks], kb[2],  kb[3]);
                MMA16816(s[2 * jp + 1], qh[ks], kbl[2], kbl[3]);
            }
        }

        // ---- mask (diagonal tile only) ----
        if (j0 >= q0) {
#pragma unroll
            for (int nt = 0; nt < 8; nt++) {
                int cb = j0 + nt * 8 + (l & 3) * 2;
                if (mode == 0) {
                    if (cb     > r0) s[nt][0] = NEG;
                    if (cb + 1 > r0) s[nt][1] = NEG;
                    if (cb     > r1) s[nt][2] = NEG;
                    if (cb + 1 > r1) s[nt][3] = NEG;
                } else {
                    if (!(cb     < r0 || (r0 == 0 && cb == 0))) s[nt][0] = NEG;
                    if (!(cb + 1 < r0))                          s[nt][1] = NEG;
                    if (!(cb     < r1)) s[nt][2] = NEG;
                    if (!(cb + 1 < r1)) s[nt][3] = NEG;
                }
            }
        }

        // ---- online softmax ----
        float ml0 = NEG, ml1 = NEG;
#pragma unroll
        for (int nt = 0; nt < 8; nt++) {
            ml0 = fmaxf(ml0, fmaxf(s[nt][0], s[nt][1]));
            ml1 = fmaxf(ml1, fmaxf(s[nt][2], s[nt][3]));
        }
        ml0 = fmaxf(ml0, __shfl_xor_sync(0xffffffffu, ml0, 1));
        ml0 = fmaxf(ml0, __shfl_xor_sync(0xffffffffu, ml0, 2));
        ml1 = fmaxf(ml1, __shfl_xor_sync(0xffffffffu, ml1, 1));
        ml1 = fmaxf(ml1, __shfl_xor_sync(0xffffffffu, ml1, 2));
        float mn0 = fmaxf(m0, ml0), mn1 = fmaxf(m1, ml1);
        float sc0 = ex2(m0 - mn0), sc1 = ex2(m1 - mn1);

        uint32_t pah[4][4], pal[4][4];
        float ps0 = 0.f, ps1 = 0.f;
#pragma unroll
        for (int pt = 0; pt < 4; pt++) {
#pragma unroll
            for (int half = 0; half < 2; half++) {
                int nt = 2 * pt + half;
                float p0 = ex2(s[nt][0] - mn0), p1 = ex2(s[nt][1] - mn0);
                float p2 = ex2(s[nt][2] - mn1), p3 = ex2(s[nt][3] - mn1);
                ps0 += p0 + p1; ps1 += p2 + p3;
                packpair(pah[pt][2 * half],     pal[pt][2 * half],     p0, p1);
                packpair(pah[pt][2 * half + 1], pal[pt][2 * half + 1], p2, p3);
            }
        }
        lac0 = lac0 * sc0 + ps0;
        lac1 = lac1 * sc1 + ps1;
#pragma unroll
        for (int n = 0; n < 4; n++) {
            o[n][0] *= sc0; o[n][1] *= sc0; o[n][2] *= sc1; o[n][3] *= sc1;
        }

        // ---- O += P V (bf16x3), V via trans ldmatrix ----
#pragma unroll
        for (int pt = 0; pt < 4; pt++) {
#pragma unroll
            for (int np = 0; np < 2; np++) {
                uint32_t off = bufB + (uint32_t)(((pt * 16 + (l & 15)) * 40 + np * 16 + (l >> 4) * 8) * 2);
                uint32_t vb[4], vbl[4];
                LDMX4T(vb[0], vb[1], vb[2], vb[3], aVh + off);
                LDMX4T(vbl[0], vbl[1], vbl[2], vbl[3], aVl + off);
                MMA16816(o[2 * np],     pah[pt], vb[0],  vb[1]);
                MMA16816(o[2 * np],     pal[pt], vb[0],  vb[1]);
                MMA16816(o[2 * np],     pah[pt], vbl[0], vbl[1]);
                MMA16816(o[2 * np + 1], pah[pt], vb[2],  vb[3]);
                MMA16816(o[2 * np + 1], pal[pt], vb[2],  vb[3]);
                MMA16816(o[2 * np + 1], pah[pt], vbl[2], vbl[3]);
            }
        }
        m0 = mn0; m1 = mn1;
        __syncthreads();
    }

    lac0 += __shfl_xor_sync(0xffffffffu, lac0, 1);
    lac0 += __shfl_xor_sync(0xffffffffu, lac0, 2);
    lac1 += __shfl_xor_sync(0xffffffffu, lac1, 1);
    lac1 += __shfl_xor_sync(0xffffffffu, lac1, 2);
    float inv0 = 1.f / lac0, inv1 = 1.f / lac1;

#pragma unroll
    for (int nt = 0; nt < 4; nt++) {
        int col = nt * 8 + (l & 3) * 2;
        float v00 = o[nt][0] * inv0, v01 = o[nt][1] * inv0;
        float v10 = o[nt][2] * inv1, v11 = o[nt][3] * inv1;
        if (Of) {
            float2 a; a.x = v00; a.y = v01;
            float2 b; b.x = v10; b.y = v11;
            *reinterpret_cast<float2*>(&Of[baseO + (size_t)r0 * oStride + col]) = a;
            *reinterpret_cast<float2*>(&Of[baseO + (size_t)r1 * oStride + col]) = b;
        }
        if (Oh) {
            uint32_t h0, l0p, h1v, l1p;
            packpair(h0, l0p, v00, v01);
            packpair(h1v, l1p, v10, v11);
            *reinterpret_cast<uint32_t*>(&Oh[baseO + (size_t)r0 * oStride + col]) = h0;
            *reinterpret_cast<uint32_t*>(&Ol[baseO + (size_t)r0 * oStride + col]) = l0p;
            *reinterpret_cast<uint32_t*>(&Oh[baseO + (size_t)r1 * oStride + col]) = h1v;
            *reinterpret_cast<uint32_t*>(&Ol[baseO + (size_t)r1 * oStride + col]) = l1p;
        }
    }
}

// ---------------------------------------------------------------------------
// out = LayerNorm(A + B) * gamma + beta; fp32 out optional, bf16 hi/lo optional
// ---------------------------------------------------------------------------
__global__ void add_ln_k(const float* __restrict__ A, const float* __restrict__ Bv,
                         const float* __restrict__ gam, const float* __restrict__ bet,
                         float* __restrict__ outf, bf16* __restrict__ outh,
                         bf16* __restrict__ outl)
{
    int row = blockIdx.x;
    int d = threadIdx.x;  // 128
    float x = A[(size_t)row * 128 + d] + Bv[(size_t)row * 128 + d];

    __shared__ float ws[4], ws2[4];
    float v = x;
#pragma unroll
    for (int off = 16; off; off >>= 1) v += __shfl_xor_sync(0xffffffffu, v, off);
    if ((d & 31) == 0) ws[d >> 5] = v;
    __syncthreads();
    float mean = (ws[0] + ws[1] + ws[2] + ws[3]) * (1.f / 128.f);
    float dif = x - mean;
    float v2 = dif * dif;
#pragma unroll
    for (int off = 16; off; off >>= 1) v2 += __shfl_xor_sync(0xffffffffu, v2, off);
    if ((d & 31) == 0) ws2[d >> 5] = v2;
    __syncthreads();
    float var = (ws2[0] + ws2[1] + ws2[2] + ws2[3]) * (1.f / 128.f);
    float y = dif * rsqrtf(var + 1e-5f) * gam[d] + bet[d];
    if (outf) outf[(size_t)row * 128 + d] = y;
    if (outh) {
        bf16 h = __float2bfloat16(y);
        outh[(size_t)row * 128 + d] = h;
        outl[(size_t)row * 128 + d] = __float2bfloat16(y - __bfloat162float(h));
    }
}

// ---------------------------------------------------------------------------
extern "C" void kernel_launch(void* const* d_in, const int* in_sizes, int n_in,
                              void* d_out, int out_size)
{
    const float* kq    = (const float*)d_in[0];
    const float* v_in  = (const float*)d_in[1];
    const float* A_Wk  = (const float*)d_in[2];
    const float* A_bk  = (const float*)d_in[3];
    const float* A_Wq  = (const float*)d_in[4];
    const float* A_bq  = (const float*)d_in[5];
    const float* A_Wv  = (const float*)d_in[6];
    const float* A_bv  = (const float*)d_in[7];
    const float* A_f1W = (const float*)d_in[8];
    const float* A_f1b = (const float*)d_in[9];
    const float* A_f2W = (const float*)d_in[10];
    const float* A_f2b = (const float*)d_in[11];
    const float* A_n1g = (const float*)d_in[12];
    const float* A_n1b = (const float*)d_in[13];
    const float* A_n2g = (const float*)d_in[14];
    const float* A_n2b = (const float*)d_in[15];
    const float* B_Wk  = (const float*)d_in[16];
    const float* B_bk  = (const float*)d_in[17];
    const float* B_Wq  = (const float*)d_in[18];
    const float* B_bq  = (const float*)d_in[19];
    const float* B_Wv  = (const float*)d_in[20];
    const float* B_bv  = (const float*)d_in[21];
    const float* B_f1W = (const float*)d_in[22];
    const float* B_f1b = (const float*)d_in[23];
    const float* B_f2W = (const float*)d_in[24];
    const float* B_f2b = (const float*)d_in[25];
    const float* out_W = (const float*)d_in[26];
    const float* out_b = (const float*)d_in[27];
    float* out = (float*)d_out;

    float* pool = nullptr;
    cudaGetSymbolAddress((void**)&pool, g_scratch);

    static bool attr_done = false;
    if (!attr_done) {
        cudaFuncSetAttribute(mma_gemm, cudaFuncAttributeMaxDynamicSharedMemorySize, GEMM_SMEM);
        cudaFuncSetAttribute(attn_tc, cudaFuncAttributeMaxDynamicSharedMemorySize, ATTN_SMEM);
        attr_done = true;
    }

    const size_t S = (size_t)R_TOTAL * 128;  // 2M floats per slot
    float* attnA = pool + 0 * S;
    float* h1    = pool + 1 * S;
    float* t1    = pool + 2 * S;
    float* Va    = pool + 3 * S;
    bf16* qkvA_h = (bf16*)(pool + 4 * S);    // R x 384 (slots 4-5)
    bf16* qkvA_l = (bf16*)(pool + 6 * S);    // slots 6-7
    bf16* sXh    = (bf16*)(pool + 8 * S);
    bf16* sXl    = (bf16*)(pool + 9 * S);
    bf16* ffh    = (bf16*)(pool + 10 * S);   // R x 512 (slots 10-11)
    bf16* ffl    = (bf16*)(pool + 12 * S);   // slots 12-13
    bf16* kqh    = (bf16*)(pool + 14 * S);
    bf16* kql    = (bf16*)(pool + 15 * S);
    bf16* kq2h   = (bf16*)(pool + 16 * S);   // R x 256
    bf16* kq2l   = (bf16*)(pool + 17 * S);
    bf16* v2h    = (bf16*)(pool + 18 * S);
    bf16* v2l    = (bf16*)(pool + 19 * S);
    bf16* at2h   = (bf16*)(pool + 20 * S);
    bf16* at2l   = (bf16*)(pool + 21 * S);
    bf16* vAh    = (bf16*)(pool + 22 * S);
    bf16* vAl    = (bf16*)(pool + 23 * S);
    float* Wc    = pool + 24 * S;            // 512x32 fp32
    float* bc    = Wc + 512 * 32;
    float* qkvbA = bc + 64;                  // 384
    float* kqb2  = qkvbA + 384;              // 256
    bf16* wArena = (bf16*)(pool + 25 * S);
    bf16* wH = wArena;
    bf16* wL = wArena + PW_TOTAL;
    bf16* qkvW_h = wH + 0;       bf16* qkvW_l = wL + 0;
    bf16* kqW_h  = wH + 49152;   bf16* kqW_l  = wL + 49152;
    bf16* bWv_h  = wH + 65536;   bf16* bWv_l  = wL + 65536;
    bf16* af1_h  = wH + 81920;   bf16* af1_l  = wL + 81920;
    bf16* af2_h  = wH + 147456;  bf16* af2_l  = wL + 147456;
    bf16* bf1_h  = wH + 212992;  bf16* bf1_l  = wL + 212992;
    bf16* wc_h   = wH + 278528;  bf16* wc_l   = wL + 278528;

    // ---- weight prep: 2 launches ----
    smallprep_k<<<(512*32 + 32 + 640 + 255) / 256, 256>>>(
        B_f2W, out_W, B_f2b, out_b, A_bk, A_bq, A_bv, B_bk, B_bq,
        Wc, bc, qkvbA, kqb2);
    Prep10 p10;
    p10.s[0] = A_Wk; p10.s[1] = A_Wq; p10.s[2] = A_Wv;
    p10.s[3] = B_Wk; p10.s[4] = B_Wq; p10.s[5] = B_Wv;
    p10.s[6] = A_f1W; p10.s[7] = A_f2W; p10.s[8] = B_f1W; p10.s[9] = Wc;
    prepw_k<<<(PW_TOTAL + 255) / 256, 256>>>(p10, wH, wL);

    dim3 blk256(256);
    dim3 attnGrid(T_SEQ / 64, 8 * NHEAD);  // (32, 32)

    // ---- Layer A ----
    splitcat_k<<<(R_TOTAL*32+255)/256, 256>>>(kq, v_in, sXh, sXl);
    mma_gemm<<<dim3(3, 128), blk256, GEMM_SMEM>>>(sXh, sXl, qkvW_h, qkvW_l, qkvbA, 384,
                                       Va, 256, 128, qkvA_h, qkvA_l, 384, 128, 0);
    attn_tc<<<attnGrid, 128, ATTN_SMEM>>>(qkvA_h + 128, qkvA_l + 128, 384,
                               qkvA_h, qkvA_l, 384,
                               qkvA_h + 256, qkvA_l + 256, 384,
                               attnA, nullptr, nullptr, 128, 0);
    add_ln_k<<<R_TOTAL, 128>>>(Va, attnA, A_n1g, A_n1b, h1, sXh, sXl);
    mma_gemm<<<dim3(4, 128), blk256, GEMM_SMEM>>>(sXh, sXl, af1_h, af1_l, A_f1b, 512,
                                       nullptr, 0, 0, ffh, ffl, 512, 128, 1);
    mma_gemm<<<dim3(1, 128), blk256, GEMM_SMEM>>>(ffh, ffl, af2_h, af2_l, A_f2b, 128,
                                       t1, 0, 128, nullptr, nullptr, 0, 512, 0);
    add_ln_k<<<R_TOTAL, 128>>>(h1, t1, A_n2g, A_n2b, nullptr, vAh, vAl);

    // ---- Layer B ----
    split_k<<<(R_TOTAL*16+255)/256, 256>>>(kq, kqh, kql, R_TOTAL*16);
    mma_gemm<<<dim3(2, 128), blk256, GEMM_SMEM>>>(kqh, kql, kqW_h, kqW_l, kqb2, 256,
                                       nullptr, 0, 0, kq2h, kq2l, 256, 64, 0);
    mma_gemm<<<dim3(1, 128), blk256, GEMM_SMEM>>>(vAh, vAl, bWv_h, bWv_l, B_bv, 128,
                                       nullptr, 0, 0, v2h, v2l, 128, 128, 0);
    attn_tc<<<attnGrid, 128, ATTN_SMEM>>>(kq2h + 128, kq2l + 128, 256,
                               kq2h, kq2l, 256,
                               v2h, v2l, 128,
                               nullptr, at2h, at2l, 128, 1);
    mma_gemm<<<dim3(4, 128), blk256, GEMM_SMEM>>>(at2h, at2l, bf1_h, bf1_l, B_f1b, 512,
                                       nullptr, 0, 0, ffh, ffl, 512, 128, 1);
    mma_gemm<<<dim3(1, 128), blk256, GEMM_SMEM>>>(ffh, ffl, wc_h, wc_l, bc, 32,
                                       out, 0, 32, nullptr, nullptr, 0, 512, 0);
}

// round 10
// speedup vs baseline: 1.1176x; 1.0128x over previous
#include <cuda_runtime.h>
#include <cuda_bf16.h>
#include <math.h>
#include <stdint.h>

// ---------------------------------------------------------------------------
// Model_19104014532987: 2-layer transformer
// B=8 T=2048 DKQ=64 DV=64 EKQ=EV=128 H=4 dh=32 FF=512 OUT=32, R=16384
// All heavy math on mma.sync bf16 (HMMA), bf16x3 split precision.
// cp.async double-buffered pipelines; GEMM forced to 2 CTAs/SM;
// attention Q-staging aliased into KV buf1 (40KB smem -> 5 CTAs/SM).
// ---------------------------------------------------------------------------

#define R_TOTAL 16384
#define T_SEQ   2048
#define EMB     128
#define NHEAD   4
#define LOG2E   1.4426950408889634f

typedef __nv_bfloat16 bf16;

// Scratch pool: 56M floats (224 MB), static device allocation (allowed).
static __device__ __align__(256) float g_scratch[56ull * 1024 * 1024];

__device__ __forceinline__ float gelu_exact(float x) {
    return 0.5f * x * (1.0f + erff(x * 0.70710678118654752440f));
}
__device__ __forceinline__ float ex2(float x) {
    float y; asm("ex2.approx.ftz.f32 %0, %1;" : "=f"(y) : "f"(x)); return y;
}
__device__ __forceinline__ uint32_t smem_u32(const void* p) {
    uint32_t a;
    asm("{ .reg .u64 t; cvta.to.shared.u64 t, %1; cvt.u32.u64 %0, t; }" : "=r"(a) : "l"(p));
    return a;
}

#define LDMX4(r0, r1, r2, r3, addr) \
    asm volatile("ldmatrix.sync.aligned.m8n8.x4.shared.b16 {%0,%1,%2,%3}, [%4];" \
        : "=r"(r0), "=r"(r1), "=r"(r2), "=r"(r3) : "r"(addr))
#define LDMX4T(r0, r1, r2, r3, addr) \
    asm volatile("ldmatrix.sync.aligned.m8n8.x4.trans.shared.b16 {%0,%1,%2,%3}, [%4];" \
        : "=r"(r0), "=r"(r1), "=r"(r2), "=r"(r3) : "r"(addr))
#define MMA16816(d, a, b0, b1) \
    asm volatile("mma.sync.aligned.m16n8k16.row.col.f32.bf16.bf16.f32 " \
        "{%0,%1,%2,%3}, {%4,%5,%6,%7}, {%8,%9}, {%0,%1,%2,%3};" \
        : "+f"((d)[0]), "+f"((d)[1]), "+f"((d)[2]), "+f"((d)[3]) \
        : "r"((a)[0]), "r"((a)[1]), "r"((a)[2]), "r"((a)[3]), "r"(b0), "r"(b1))

#define CP_ASYNC16(saddr, gptr) \
    asm volatile("cp.async.cg.shared.global [%0], [%1], 16;" :: "r"(saddr), "l"(gptr))
#define CP_COMMIT() asm volatile("cp.async.commit_group;" ::: "memory")
#define CP_WAIT1()  asm volatile("cp.async.wait_group 1;" ::: "memory")
#define CP_WAIT0()  asm volatile("cp.async.wait_group 0;" ::: "memory")

__device__ __forceinline__ void packpair(uint32_t& ph, uint32_t& pl, float x, float y) {
    bf16 hx = __float2bfloat16(x), hy = __float2bfloat16(y);
    __nv_bfloat162 t; t.x = hx; t.y = hy;
    ph = *reinterpret_cast<uint32_t*>(&t);
    __nv_bfloat162 u;
    u.x = __float2bfloat16(x - __bfloat162float(hx));
    u.y = __float2bfloat16(y - __bfloat162float(hy));
    pl = *reinterpret_cast<uint32_t*>(&u);
}

// ---------------------------------------------------------------------------
// activation split kernels
// ---------------------------------------------------------------------------
__global__ void split_k(const float* __restrict__ x, bf16* __restrict__ h,
                        bf16* __restrict__ l, int n4) {
    int i = blockIdx.x * 256 + threadIdx.x;
    if (i >= n4) return;
    float4 v = reinterpret_cast<const float4*>(x)[i];
    uint32_t h01, l01, h23, l23;
    packpair(h01, l01, v.x, v.y);
    packpair(h23, l23, v.z, v.w);
    reinterpret_cast<uint32_t*>(h)[i * 2]     = h01;
    reinterpret_cast<uint32_t*>(h)[i * 2 + 1] = h23;
    reinterpret_cast<uint32_t*>(l)[i * 2]     = l01;
    reinterpret_cast<uint32_t*>(l)[i * 2 + 1] = l23;
}

__global__ void splitcat_k(const float* __restrict__ kq, const float* __restrict__ v,
                           bf16* __restrict__ h, bf16* __restrict__ l) {
    int i = blockIdx.x * 256 + threadIdx.x;
    if (i >= R_TOTAL * 32) return;
    int e = i * 4;
    int r = e >> 7, d = e & 127;
    float4 val = (d < 64)
        ? *reinterpret_cast<const float4*>(&kq[(size_t)r * 64 + d])
        : *reinterpret_cast<const float4*>(&v[(size_t)r * 64 + (d - 64)]);
    uint32_t h01, l01, h23, l23;
    packpair(h01, l01, val.x, val.y);
    packpair(h23, l23, val.z, val.w);
    reinterpret_cast<uint32_t*>(h)[i * 2]     = h01;
    reinterpret_cast<uint32_t*>(h)[i * 2 + 1] = h23;
    reinterpret_cast<uint32_t*>(l)[i * 2]     = l01;
    reinterpret_cast<uint32_t*>(l)[i * 2 + 1] = l23;
}

// ---------------------------------------------------------------------------
// fused weight prep
// ---------------------------------------------------------------------------
__global__ void smallprep_k(const float* __restrict__ f2W, const float* __restrict__ outW,
                            const float* __restrict__ f2b, const float* __restrict__ out_b,
                            const float* __restrict__ A_bk, const float* __restrict__ A_bq,
                            const float* __restrict__ A_bv, const float* __restrict__ B_bk,
                            const float* __restrict__ B_bq,
                            float* __restrict__ Wc, float* __restrict__ bc,
                            float* __restrict__ qkvbA, float* __restrict__ kqb2)
{
    int gid = blockIdx.x * 256 + threadIdx.x;
    if (gid < 512 * 32) {
        int k = gid >> 5, n = gid & 31;
        float s = 0.f;
        for (int j = 0; j < 128; j++) s = fmaf(f2W[k * 128 + j], outW[j * 32 + n], s);
        Wc[gid] = s;
        return;
    }
    int r = gid - 512 * 32;
    if (r < 32) {
        float s = out_b[r];
        for (int j = 0; j < 128; j++) s = fmaf(f2b[j], outW[j * 32 + r], s);
        bc[r] = s;
        return;
    }
    r -= 32;
    if (r < 384) {
        float v = (r < 128) ? A_bk[r] : (r < 256) ? A_bq[r - 128] * LOG2E : A_bv[r - 256];
        qkvbA[r] = v;
        return;
    }
    r -= 384;
    if (r < 256) {
        kqb2[r] = (r < 128) ? B_bk[r] : B_bq[r - 128] * LOG2E;
    }
}

struct Prep10 { const float* s[10]; };
__device__ __constant__ const int  PS_START[10] = {0,16384,32768,49152,57344,65536,81920,147456,212992,278528};
#define PW_TOTAL 344064
__device__ __constant__ const int  PS_KD[10]    = {128,128,128, 64, 64,128,128,512,128,512};
__device__ __constant__ const int  PS_ND[10]    = {128,128,128,128,128,128,512,128,512, 32};
__device__ __constant__ const float PS_SC[10]   = {1.f,LOG2E,1.f,1.f,LOG2E,1.f,1.f,1.f,1.f,1.f};

__global__ void prepw_k(Prep10 srcs, bf16* __restrict__ th, bf16* __restrict__ tl) {
    int gid = blockIdx.x * 256 + threadIdx.x;
    if (gid >= PW_TOTAL) return;
    int s = 0;
#pragma unroll
    for (int i = 1; i < 10; i++) if (gid >= PS_START[i]) s = i;
    int idx = gid - PS_START[s];
    int Kd = PS_KD[s], Nd = PS_ND[s];
    int n = idx / Kd, k = idx - n * Kd;
    float w = (n < Nd) ? srcs.s[s][(size_t)k * Nd + n] * PS_SC[s] : 0.f;
    bf16 h = __float2bfloat16(w);
    th[gid] = h;
    tl[gid] = __float2bfloat16(w - __bfloat162float(h));
}

// ---------------------------------------------------------------------------
// mma_gemm: C = A[M,K] @ Wt[N,K]^T + bias, bf16x3 split, cp.async pipelined.
// 256 threads, CTA tile 128x128, warp tile 32x64. 80KB smem, FORCED 2 CTAs/SM.
// ---------------------------------------------------------------------------
#define GEMM_SMEM 81920
__global__ __launch_bounds__(256, 2) void mma_gemm(
    const bf16* __restrict__ Ah, const bf16* __restrict__ Al,
    const bf16* __restrict__ Bh, const bf16* __restrict__ Bl,
    const float* __restrict__ bias, int Nvalid,
    float* __restrict__ Cf, int f_lo, int fStride,
    bf16* __restrict__ Ch, bf16* __restrict__ Cl, int cStride,
    int K, int act)
{
    extern __shared__ __align__(16) char dsm[];
    bf16* smA_h = (bf16*)dsm;            // [2][5120]
    bf16* smA_l = smA_h + 10240;
    bf16* smB_h = smA_l + 10240;
    bf16* smB_l = smB_h + 10240;

    const int tid = threadIdx.x;
    const int l = tid & 31, w = tid >> 5;
    const int wm = w >> 1, wn = w & 1;
    const int bm = blockIdx.y * 128, bn = blockIdx.x * 128;

    float d[2][8][4];
#pragma unroll
    for (int mt = 0; mt < 2; mt++)
#pragma unroll
        for (int nt = 0; nt < 8; nt++)
#pragma unroll
            for (int q = 0; q < 4; q++) d[mt][nt][q] = 0.f;

    const uint32_t aAh = smem_u32(smA_h), aAl = smem_u32(smA_l);
    const uint32_t aBh = smem_u32(smB_h), aBl = smem_u32(smB_l);

    const int a_row = wm * 32 + (l & 7) + ((l >> 3) & 1) * 8;
    const int a_kof = (l >> 4) * 8;
    const int b_row = wn * 64 + (l >> 4) * 8 + (l & 7);
    const int b_kof = ((l >> 3) & 1) * 8;

    auto issue_chunk = [&](int kcElem, int buf) {
#pragma unroll
        for (int i = tid; i < 512; i += 256) {
            int row = i >> 2, ch = i & 3;
            size_t ga = (size_t)(bm + row) * K + kcElem + ch * 8;
            size_t gb = (size_t)(bn + row) * K + kcElem + ch * 8;
            int sa = buf * 5120 + row * 40 + ch * 8;
            CP_ASYNC16(smem_u32(smA_h + sa), Ah + ga);
            CP_ASYNC16(smem_u32(smA_l + sa), Al + ga);
            CP_ASYNC16(smem_u32(smB_h + sa), Bh + gb);
            CP_ASYNC16(smem_u32(smB_l + sa), Bl + gb);
        }
    };

    const int nch = K >> 5;
    issue_chunk(0, 0);
    CP_COMMIT();

    for (int kc = 0; kc < nch; kc++) {
        const int buf = kc & 1;
        if (kc + 1 < nch) { issue_chunk((kc + 1) << 5, buf ^ 1); CP_COMMIT(); CP_WAIT1(); }
        else              { CP_WAIT0(); }
        __syncthreads();

        const uint32_t bufB = (uint32_t)buf * 10240;
#pragma unroll
        for (int ks = 0; ks < 32; ks += 16) {
            uint32_t ah[2][4], al2[2][4];
#pragma unroll
            for (int mt = 0; mt < 2; mt++) {
                uint32_t off = bufB + (uint32_t)(((a_row + mt * 16) * 40 + a_kof + ks) * 2);
                LDMX4(ah[mt][0], ah[mt][1], ah[mt][2], ah[mt][3], aAh + off);
                LDMX4(al2[mt][0], al2[mt][1], al2[mt][2], al2[mt][3], aAl + off);
            }
#pragma unroll
            for (int j = 0; j < 4; j++) {
                uint32_t boff = bufB + (uint32_t)(((b_row + j * 16) * 40 + b_kof + ks) * 2);
                uint32_t bh[4], bl2[4];
                LDMX4(bh[0], bh[1], bh[2], bh[3], aBh + boff);
                LDMX4(bl2[0], bl2[1], bl2[2], bl2[3], aBl + boff);
#pragma unroll
                for (int mt = 0; mt < 2; mt++) {
                    MMA16816(d[mt][2 * j],     ah[mt],  bh[0],  bh[1]);
                    MMA16816(d[mt][2 * j],     al2[mt], bh[0],  bh[1]);
                    MMA16816(d[mt][2 * j],     ah[mt],  bl2[0], bl2[1]);
                    MMA16816(d[mt][2 * j + 1], ah[mt],  bh[2],  bh[3]);
                    MMA16816(d[mt][2 * j + 1], al2[mt], bh[2],  bh[3]);
                    MMA16816(d[mt][2 * j + 1], ah[mt],  bl2[2], bl2[3]);
                }
            }
        }
        __syncthreads();
    }

#pragma unroll
    for (int mt = 0; mt < 2; mt++) {
        int r0 = bm + wm * 32 + mt * 16 + (l >> 2);
#pragma unroll
        for (int nt = 0; nt < 8; nt++) {
            int c = bn + wn * 64 + nt * 8 + (l & 3) * 2;
            if (c >= Nvalid) continue;
            float b0 = bias[c], b1 = bias[c + 1];
            float2 v0, v1;
            v0.x = d[mt][nt][0] + b0; v0.y = d[mt][nt][1] + b1;
            v1.x = d[mt][nt][2] + b0; v1.y = d[mt][nt][3] + b1;
            if (act) {
                v0.x = gelu_exact(v0.x); v0.y = gelu_exact(v0.y);
                v1.x = gelu_exact(v1.x); v1.y = gelu_exact(v1.y);
            }
            if (Cf && c >= f_lo) {
                *reinterpret_cast<float2*>(&Cf[(size_t)r0 * fStride + (c - f_lo)]) = v0;
                *reinterpret_cast<float2*>(&Cf[(size_t)(r0 + 8) * fStride + (c - f_lo)]) = v1;
            }
            if (Ch) {
                uint32_t h0, l0p, h1v, l1p;
                packpair(h0, l0p, v0.x, v0.y);
                packpair(h1v, l1p, v1.x, v1.y);
                *reinterpret_cast<uint32_t*>(&Ch[(size_t)r0 * cStride + c]) = h0;
                *reinterpret_cast<uint32_t*>(&Cl[(size_t)r0 * cStride + c]) = l0p;
                *reinterpret_cast<uint32_t*>(&Ch[(size_t)(r0 + 8) * cStride + c]) = h1v;
                *reinterpret_cast<uint32_t*>(&Cl[(size_t)(r0 + 8) * cStride + c]) = l1p;
            }
        }
    }
}

// ---------------------------------------------------------------------------
// attn_tc: tensor-core flash attention, 64q x 64k tiles, dh=32,
// cp.async double-buffered K/V; Q staging ALIASED into KV buf1 (smem 40KB).
// 128 threads = 4 warps x 16 q rows. Q pre-scaled by log2(e).
// mode 0: j <= i.  mode 1: j < i OR (i==0 && j==0).
// smem element layout (bf16): buf b at b*10240: [Kh 2560][Kl 2560][Vh 2560][Vl 2560]
// Q staged at elements 10240 (Qh) / 12800 (Ql)  == buf1 region.
// ---------------------------------------------------------------------------
#define ATTN_SMEM 40960
__global__ __launch_bounds__(128) void attn_tc(
    const bf16* __restrict__ Qh, const bf16* __restrict__ Ql, int qStride,
    const bf16* __restrict__ Kh, const bf16* __restrict__ Kl, int kStride,
    const bf16* __restrict__ Vh, const bf16* __restrict__ Vl, int vStride,
    float* __restrict__ Of, bf16* __restrict__ Oh, bf16* __restrict__ Ol, int oStride,
    int mode)
{
    extern __shared__ __align__(16) char dsm[];
    bf16* dsmb = (bf16*)dsm;

    const int tid = threadIdx.x, l = tid & 31, w = tid >> 5;
    const int bh = blockIdx.y;
    const int hc = (bh & 3) * 32;
    const int bb = bh >> 2;
    const size_t baseQ = (size_t)bb * T_SEQ * qStride + hc;
    const size_t baseK = (size_t)bb * T_SEQ * kStride + hc;
    const size_t baseV = (size_t)bb * T_SEQ * vStride + hc;
    const size_t baseO = (size_t)bb * T_SEQ * oStride + hc;
    const int q0 = (gridDim.x - 1 - blockIdx.x) * 64;

    const uint32_t aKV = smem_u32(dsmb);

    auto issue_kv = [&](int j0, int buf) {
#pragma unroll
        for (int i = tid; i < 256; i += 128) {
            int row = i >> 2, ch = i & 3;
            size_t gk = baseK + (size_t)(j0 + row) * kStride + ch * 8;
            size_t gv = baseV + (size_t)(j0 + row) * vStride + ch * 8;
            uint32_t sa = aKV + (uint32_t)(buf * 10240 + row * 40 + ch * 8) * 2;
            CP_ASYNC16(sa,          Kh + gk);
            CP_ASYNC16(sa + 5120,   Kl + gk);
            CP_ASYNC16(sa + 10240,  Vh + gv);
            CP_ASYNC16(sa + 15360,  Vl + gv);
        }
    };

    issue_kv(0, 0);
    CP_COMMIT();

    // Q tile -> buf1 region (aliased; safe until first write to buf1 at jt=0)
    bf16* sQh = dsmb + 10240;
    bf16* sQl = dsmb + 12800;
    for (int i = tid; i < 256; i += 128) {
        int row = i >> 2, ch = i & 3;
        size_t g = baseQ + (size_t)(q0 + row) * qStride + ch * 8;
        *reinterpret_cast<uint4*>(&sQh[row * 40 + ch * 8]) = *reinterpret_cast<const uint4*>(&Qh[g]);
        *reinterpret_cast<uint4*>(&sQl[row * 40 + ch * 8]) = *reinterpret_cast<const uint4*>(&Ql[g]);
    }
    __syncthreads();

    uint32_t qh[2][4], ql[2][4];
    const int a_row = w * 16 + (l & 7) + ((l >> 3) & 1) * 8;
    const int a_col = (l >> 4) * 8;
    {
        const uint32_t aQh = smem_u32(sQh), aQl = smem_u32(sQl);
#pragma unroll
        for (int ks = 0; ks < 2; ks++) {
            uint32_t off = (uint32_t)((a_row * 40 + a_col + ks * 16) * 2);
            LDMX4(qh[ks][0], qh[ks][1], qh[ks][2], qh[ks][3], aQh + off);
            LDMX4(ql[ks][0], ql[ks][1], ql[ks][2], ql[ks][3], aQl + off);
        }
    }
    __syncthreads();   // all warps done reading Q before buf1 gets KV data

    const float NEG = -1e30f;
    const int r0 = q0 + w * 16 + (l >> 2);
    const int r1 = r0 + 8;
    float m0 = NEG, m1 = NEG, lac0 = 0.f, lac1 = 0.f;
    float o[4][4];
#pragma unroll
    for (int n = 0; n < 4; n++)
#pragma unroll
        for (int q = 0; q < 4; q++) o[n][q] = 0.f;

    const int b_row_base = (l >> 4) * 8 + (l & 7);
    const int b_kof = ((l >> 3) & 1) * 8;
    const int ntiles = (q0 >> 6) + 1;

    for (int jt = 0; jt < ntiles; jt++) {
        const int j0 = jt * 64;
        const int buf = jt & 1;
        if (jt + 1 < ntiles) { issue_kv(j0 + 64, buf ^ 1); CP_COMMIT(); CP_WAIT1(); }
        else                 { CP_WAIT0(); }
        __syncthreads();
        const uint32_t bufB = (uint32_t)buf * 20480;   // bytes

        // ---- S = Q K^T (bf16x3) ----
        float s[8][4];
#pragma unroll
        for (int nt = 0; nt < 8; nt++)
#pragma unroll
            for (int q = 0; q < 4; q++) s[nt][q] = 0.f;

#pragma unroll
        for (int ks = 0; ks < 2; ks++) {
#pragma unroll
            for (int jp = 0; jp < 4; jp++) {
                uint32_t off = aKV + bufB + (uint32_t)(((jp * 16 + b_row_base) * 40 + b_kof + ks * 16) * 2);
                uint32_t kb[4], kbl[4];
                LDMX4(kb[0], kb[1], kb[2], kb[3], off);
                LDMX4(kbl[0], kbl[1], kbl[2], kbl[3], off + 5120);
                MMA16816(s[2 * jp],     qh[ks], kb[0],  kb[1]);
                MMA16816(s[2 * jp],     ql[ks], kb[0],  kb[1]);
                MMA16816(s[2 * jp],     qh[ks], kbl[0], kbl[1]);
                MMA16816(s[2 * jp + 1], qh[ks], kb[2],  kb[3]);
                MMA16816(s[2 * jp + 1], ql[ks], kb[2],  kb[3]);
                MMA16816(s[2 * jp + 1], qh[ks], kbl[2], kbl[3]);
            }
        }

        // ---- mask (diagonal tile only) ----
        if (j0 >= q0) {
#pragma unroll
            for (int nt = 0; nt < 8; nt++) {
                int cb = j0 + nt * 8 + (l & 3) * 2;
                if (mode == 0) {
                    if (cb     > r0) s[nt][0] = NEG;
                    if (cb + 1 > r0) s[nt][1] = NEG;
                    if (cb     > r1) s[nt][2] = NEG;
                    if (cb + 1 > r1) s[nt][3] = NEG;
                } else {
                    if (!(cb     < r0 || (r0 == 0 && cb == 0))) s[nt][0] = NEG;
                    if (!(cb + 1 < r0))                          s[nt][1] = NEG;
                    if (!(cb     < r1)) s[nt][2] = NEG;
                    if (!(cb + 1 < r1)) s[nt][3] = NEG;
                }
            }
        }

        // ---- online softmax ----
        float ml0 = NEG, ml1 = NEG;
#pragma unroll
        for (int nt = 0; nt < 8; nt++) {
            ml0 = fmaxf(ml0, fmaxf(s[nt][0], s[nt][1]));
            ml1 = fmaxf(ml1, fmaxf(s[nt][2], s[nt][3]));
        }
        ml0 = fmaxf(ml0, __shfl_xor_sync(0xffffffffu, ml0, 1));
        ml0 = fmaxf(ml0, __shfl_xor_sync(0xffffffffu, ml0, 2));
        ml1 = fmaxf(ml1, __shfl_xor_sync(0xffffffffu, ml1, 1));
        ml1 = fmaxf(ml1, __shfl_xor_sync(0xffffffffu, ml1, 2));
        float mn0 = fmaxf(m0, ml0), mn1 = fmaxf(m1, ml1);
        float sc0 = ex2(m0 - mn0), sc1 = ex2(m1 - mn1);

        uint32_t pah[4][4], pal[4][4];
        float ps0 = 0.f, ps1 = 0.f;
#pragma unroll
        for (int pt = 0; pt < 4; pt++) {
#pragma unroll
            for (int half = 0; half < 2; half++) {
                int nt = 2 * pt + half;
                float p0 = ex2(s[nt][0] - mn0), p1 = ex2(s[nt][1] - mn0);
                float p2 = ex2(s[nt][2] - mn1), p3 = ex2(s[nt][3] - mn1);
                ps0 += p0 + p1; ps1 += p2 + p3;
                packpair(pah[pt][2 * half],     pal[pt][2 * half],     p0, p1);
                packpair(pah[pt][2 * half + 1], pal[pt][2 * half + 1], p2, p3);
            }
        }
        lac0 = lac0 * sc0 + ps0;
        lac1 = lac1 * sc1 + ps1;
#pragma unroll
        for (int n = 0; n < 4; n++) {
            o[n][0] *= sc0; o[n][1] *= sc0; o[n][2] *= sc1; o[n][3] *= sc1;
        }

        // ---- O += P V (bf16x3), V via trans ldmatrix ----
#pragma unroll
        for (int pt = 0; pt < 4; pt++) {
#pragma unroll
            for (int np = 0; np < 2; np++) {
                uint32_t off = aKV + bufB + 10240u
                             + (uint32_t)(((pt * 16 + (l & 15)) * 40 + np * 16 + (l >> 4) * 8) * 2);
                uint32_t vb[4], vbl[4];
                LDMX4T(vb[0], vb[1], vb[2], vb[3], off);
                LDMX4T(vbl[0], vbl[1], vbl[2], vbl[3], off + 5120);
                MMA16816(o[2 * np],     pah[pt], vb[0],  vb[1]);
                MMA16816(o[2 * np],     pal[pt], vb[0],  vb[1]);
                MMA16816(o[2 * np],     pah[pt], vbl[0], vbl[1]);
                MMA16816(o[2 * np + 1], pah[pt], vb[2],  vb[3]);
                MMA16816(o[2 * np + 1], pal[pt], vb[2],  vb[3]);
                MMA16816(o[2 * np + 1], pah[pt], vbl[2], vbl[3]);
            }
        }
        m0 = mn0; m1 = mn1;
        __syncthreads();
    }

    lac0 += __shfl_xor_sync(0xffffffffu, lac0, 1);
    lac0 += __shfl_xor_sync(0xffffffffu, lac0, 2);
    lac1 += __shfl_xor_sync(0xffffffffu, lac1, 1);
    lac1 += __shfl_xor_sync(0xffffffffu, lac1, 2);
    float inv0 = 1.f / lac0, inv1 = 1.f / lac1;

#pragma unroll
    for (int nt = 0; nt < 4; nt++) {
        int col = nt * 8 + (l & 3) * 2;
        float v00 = o[nt][0] * inv0, v01 = o[nt][1] * inv0;
        float v10 = o[nt][2] * inv1, v11 = o[nt][3] * inv1;
        if (Of) {
            float2 a; a.x = v00; a.y = v01;
            float2 b; b.x = v10; b.y = v11;
            *reinterpret_cast<float2*>(&Of[baseO + (size_t)r0 * oStride + col]) = a;
            *reinterpret_cast<float2*>(&Of[baseO + (size_t)r1 * oStride + col]) = b;
        }
        if (Oh) {
            uint32_t h0, l0p, h1v, l1p;
            packpair(h0, l0p, v00, v01);
            packpair(h1v, l1p, v10, v11);
            *reinterpret_cast<uint32_t*>(&Oh[baseO + (size_t)r0 * oStride + col]) = h0;
            *reinterpret_cast<uint32_t*>(&Ol[baseO + (size_t)r0 * oStride + col]) = l0p;
            *reinterpret_cast<uint32_t*>(&Oh[baseO + (size_t)r1 * oStride + col]) = h1v;
            *reinterpret_cast<uint32_t*>(&Ol[baseO + (size_t)r1 * oStride + col]) = l1p;
        }
    }
}

// ---------------------------------------------------------------------------
// out = LayerNorm(A + B) * gamma + beta; fp32 out optional, bf16 hi/lo optional
// ---------------------------------------------------------------------------
__global__ void add_ln_k(const float* __restrict__ A, const float* __restrict__ Bv,
                         const float* __restrict__ gam, const float* __restrict__ bet,
                         float* __restrict__ outf, bf16* __restrict__ outh,
                         bf16* __restrict__ outl)
{
    int row = blockIdx.x;
    int d = threadIdx.x;  // 128
    float x = A[(size_t)row * 128 + d] + Bv[(size_t)row * 128 + d];

    __shared__ float ws[4], ws2[4];
    float v = x;
#pragma unroll
    for (int off = 16; off; off >>= 1) v += __shfl_xor_sync(0xffffffffu, v, off);
    if ((d & 31) == 0) ws[d >> 5] = v;
    __syncthreads();
    float mean = (ws[0] + ws[1] + ws[2] + ws[3]) * (1.f / 128.f);
    float dif = x - mean;
    float v2 = dif * dif;
#pragma unroll
    for (int off = 16; off; off >>= 1) v2 += __shfl_xor_sync(0xffffffffu, v2, off);
    if ((d & 31) == 0) ws2[d >> 5] = v2;
    __syncthreads();
    float var = (ws2[0] + ws2[1] + ws2[2] + ws2[3]) * (1.f / 128.f);
    float y = dif * rsqrtf(var + 1e-5f) * gam[d] + bet[d];
    if (outf) outf[(size_t)row * 128 + d] = y;
    if (outh) {
        bf16 h = __float2bfloat16(y);
        outh[(size_t)row * 128 + d] = h;
        outl[(size_t)row * 128 + d] = __float2bfloat16(y - __bfloat162float(h));
    }
}

// ---------------------------------------------------------------------------
extern "C" void kernel_launch(void* const* d_in, const int* in_sizes, int n_in,
                              void* d_out, int out_size)
{
    const float* kq    = (const float*)d_in[0];
    const float* v_in  = (const float*)d_in[1];
    const float* A_Wk  = (const float*)d_in[2];
    const float* A_bk  = (const float*)d_in[3];
    const float* A_Wq  = (const float*)d_in[4];
    const float* A_bq  = (const float*)d_in[5];
    const float* A_Wv  = (const float*)d_in[6];
    const float* A_bv  = (const float*)d_in[7];
    const float* A_f1W = (const float*)d_in[8];
    const float* A_f1b = (const float*)d_in[9];
    const float* A_f2W = (const float*)d_in[10];
    const float* A_f2b = (const float*)d_in[11];
    const float* A_n1g = (const float*)d_in[12];
    const float* A_n1b = (const float*)d_in[13];
    const float* A_n2g = (const float*)d_in[14];
    const float* A_n2b = (const float*)d_in[15];
    const float* B_Wk  = (const float*)d_in[16];
    const float* B_bk  = (const float*)d_in[17];
    const float* B_Wq  = (const float*)d_in[18];
    const float* B_bq  = (const float*)d_in[19];
    const float* B_Wv  = (const float*)d_in[20];
    const float* B_bv  = (const float*)d_in[21];
    const float* B_f1W = (const float*)d_in[22];
    const float* B_f1b = (const float*)d_in[23];
    const float* B_f2W = (const float*)d_in[24];
    const float* B_f2b = (const float*)d_in[25];
    const float* out_W = (const float*)d_in[26];
    const float* out_b = (const float*)d_in[27];
    float* out = (float*)d_out;

    float* pool = nullptr;
    cudaGetSymbolAddress((void**)&pool, g_scratch);

    static bool attr_done = false;
    if (!attr_done) {
        cudaFuncSetAttribute(mma_gemm, cudaFuncAttributeMaxDynamicSharedMemorySize, GEMM_SMEM);
        cudaFuncSetAttribute(attn_tc, cudaFuncAttributeMaxDynamicSharedMemorySize, ATTN_SMEM);
        attr_done = true;
    }

    const size_t S = (size_t)R_TOTAL * 128;  // 2M floats per slot
    float* attnA = pool + 0 * S;
    float* h1    = pool + 1 * S;
    float* t1    = pool + 2 * S;
    float* Va    = pool + 3 * S;
    bf16* qkvA_h = (bf16*)(pool + 4 * S);    // R x 384 (slots 4-5)
    bf16* qkvA_l = (bf16*)(pool + 6 * S);    // slots 6-7
    bf16* sXh    = (bf16*)(pool + 8 * S);
    bf16* sXl    = (bf16*)(pool + 9 * S);
    bf16* ffh    = (bf16*)(pool + 10 * S);   // R x 512 (slots 10-11)
    bf16* ffl    = (bf16*)(pool + 12 * S);   // slots 12-13
    bf16* kqh    = (bf16*)(pool + 14 * S);
    bf16* kql    = (bf16*)(pool + 15 * S);
    bf16* kq2h   = (bf16*)(pool + 16 * S);   // R x 256
    bf16* kq2l   = (bf16*)(pool + 17 * S);
    bf16* v2h    = (bf16*)(pool + 18 * S);
    bf16* v2l    = (bf16*)(pool + 19 * S);
    bf16* at2h   = (bf16*)(pool + 20 * S);
    bf16* at2l   = (bf16*)(pool + 21 * S);
    bf16* vAh    = (bf16*)(pool + 22 * S);
    bf16* vAl    = (bf16*)(pool + 23 * S);
    float* Wc    = pool + 24 * S;            // 512x32 fp32
    float* bc    = Wc + 512 * 32;
    float* qkvbA = bc + 64;                  // 384
    float* kqb2  = qkvbA + 384;              // 256
    bf16* wArena = (bf16*)(pool + 25 * S);
    bf16* wH = wArena;
    bf16* wL = wArena + PW_TOTAL;
    bf16* qkvW_h = wH + 0;       bf16* qkvW_l = wL + 0;
    bf16* kqW_h  = wH + 49152;   bf16* kqW_l  = wL + 49152;
    bf16* bWv_h  = wH + 65536;   bf16* bWv_l  = wL + 65536;
    bf16* af1_h  = wH + 81920;   bf16* af1_l  = wL + 81920;
    bf16* af2_h  = wH + 147456;  bf16* af2_l  = wL + 147456;
    bf16* bf1_h  = wH + 212992;  bf16* bf1_l  = wL + 212992;
    bf16* wc_h   = wH + 278528;  bf16* wc_l   = wL + 278528;

    // ---- weight prep: 2 launches ----
    smallprep_k<<<(512*32 + 32 + 640 + 255) / 256, 256>>>(
        B_f2W, out_W, B_f2b, out_b, A_bk, A_bq, A_bv, B_bk, B_bq,
        Wc, bc, qkvbA, kqb2);
    Prep10 p10;
    p10.s[0] = A_Wk; p10.s[1] = A_Wq; p10.s[2] = A_Wv;
    p10.s[3] = B_Wk; p10.s[4] = B_Wq; p10.s[5] = B_Wv;
    p10.s[6] = A_f1W; p10.s[7] = A_f2W; p10.s[8] = B_f1W; p10.s[9] = Wc;
    prepw_k<<<(PW_TOTAL + 255) / 256, 256>>>(p10, wH, wL);

    dim3 blk256(256);
    dim3 attnGrid(T_SEQ / 64, 8 * NHEAD);  // (32, 32)

    // ---- Layer A ----
    splitcat_k<<<(R_TOTAL*32+255)/256, 256>>>(kq, v_in, sXh, sXl);
    mma_gemm<<<dim3(3, 128), blk256, GEMM_SMEM>>>(sXh, sXl, qkvW_h, qkvW_l, qkvbA, 384,
                                       Va, 256, 128, qkvA_h, qkvA_l, 384, 128, 0);
    attn_tc<<<attnGrid, 128, ATTN_SMEM>>>(qkvA_h + 128, qkvA_l + 128, 384,
                               qkvA_h, qkvA_l, 384,
                               qkvA_h + 256, qkvA_l + 256, 384,
                               attnA, nullptr, nullptr, 128, 0);
    add_ln_k<<<R_TOTAL, 128>>>(Va, attnA, A_n1g, A_n1b, h1, sXh, sXl);
    mma_gemm<<<dim3(4, 128), blk256, GEMM_SMEM>>>(sXh, sXl, af1_h, af1_l, A_f1b, 512,
                                       nullptr, 0, 0, ffh, ffl, 512, 128, 1);
    mma_gemm<<<dim3(1, 128), blk256, GEMM_SMEM>>>(ffh, ffl, af2_h, af2_l, A_f2b, 128,
                                       t1, 0, 128, nullptr, nullptr, 0, 512, 0);
    add_ln_k<<<R_TOTAL, 128>>>(h1, t1, A_n2g, A_n2b, nullptr, vAh, vAl);

    // ---- Layer B ----
    split_k<<<(R_TOTAL*16+255)/256, 256>>>(kq, kqh, kql, R_TOTAL*16);
    mma_gemm<<<dim3(2, 128), blk256, GEMM_SMEM>>>(kqh, kql, kqW_h, kqW_l, kqb2, 256,
                                       nullptr, 0, 0, kq2h, kq2l, 256, 64, 0);
    mma_gemm<<<dim3(1, 128), blk256, GEMM_SMEM>>>(vAh, vAl, bWv_h, bWv_l, B_bv, 128,
                                       nullptr, 0, 0, v2h, v2l, 128, 128, 0);
    attn_tc<<<attnGrid, 128, ATTN_SMEM>>>(kq2h + 128, kq2l + 128, 256,
                               kq2h, kq2l, 256,
                               v2h, v2l, 128,
                               nullptr, at2h, at2l, 128, 1);
    mma_gemm<<<dim3(4, 128), blk256, GEMM_SMEM>>>(at2h, at2l, bf1_h, bf1_l, B_f1b, 512,
                                       nullptr, 0, 0, ffh, ffl, 512, 128, 1);
    mma_gemm<<<dim3(1, 128), blk256, GEMM_SMEM>>>(ffh, ffl, wc_h, wc_l, bc, 32,
                                       out, 0, 32, nullptr, nullptr, 0, 512, 0);
}

// round 11
// speedup vs baseline: 1.1254x; 1.0070x over previous
#include <cuda_runtime.h>
#include <cuda_bf16.h>
#include <math.h>
#include <stdint.h>

// ---------------------------------------------------------------------------
// Model_19104014532987: 2-layer transformer
// B=8 T=2048 DKQ=64 DV=64 EKQ=EV=128 H=4 dh=32 FF=512 OUT=32, R=16384
// mma.sync bf16 (HMMA), bf16x3 split precision, cp.async pipelines.
// GEMM templated on M-tile (128 for big launches, 64 for sub-wave launches).
// ---------------------------------------------------------------------------

#define R_TOTAL 16384
#define T_SEQ   2048
#define EMB     128
#define NHEAD   4
#define LOG2E   1.4426950408889634f

typedef __nv_bfloat16 bf16;

// Scratch pool: 56M floats (224 MB), static device allocation (allowed).
static __device__ __align__(256) float g_scratch[56ull * 1024 * 1024];

__device__ __forceinline__ float gelu_exact(float x) {
    return 0.5f * x * (1.0f + erff(x * 0.70710678118654752440f));
}
__device__ __forceinline__ float ex2(float x) {
    float y; asm("ex2.approx.ftz.f32 %0, %1;" : "=f"(y) : "f"(x)); return y;
}
__device__ __forceinline__ uint32_t smem_u32(const void* p) {
    uint32_t a;
    asm("{ .reg .u64 t; cvta.to.shared.u64 t, %1; cvt.u32.u64 %0, t; }" : "=r"(a) : "l"(p));
    return a;
}

#define LDMX4(r0, r1, r2, r3, addr) \
    asm volatile("ldmatrix.sync.aligned.m8n8.x4.shared.b16 {%0,%1,%2,%3}, [%4];" \
        : "=r"(r0), "=r"(r1), "=r"(r2), "=r"(r3) : "r"(addr))
#define LDMX4T(r0, r1, r2, r3, addr) \
    asm volatile("ldmatrix.sync.aligned.m8n8.x4.trans.shared.b16 {%0,%1,%2,%3}, [%4];" \
        : "=r"(r0), "=r"(r1), "=r"(r2), "=r"(r3) : "r"(addr))
#define MMA16816(d, a, b0, b1) \
    asm volatile("mma.sync.aligned.m16n8k16.row.col.f32.bf16.bf16.f32 " \
        "{%0,%1,%2,%3}, {%4,%5,%6,%7}, {%8,%9}, {%0,%1,%2,%3};" \
        : "+f"((d)[0]), "+f"((d)[1]), "+f"((d)[2]), "+f"((d)[3]) \
        : "r"((a)[0]), "r"((a)[1]), "r"((a)[2]), "r"((a)[3]), "r"(b0), "r"(b1))

#define CP_ASYNC16(saddr, gptr) \
    asm volatile("cp.async.cg.shared.global [%0], [%1], 16;" :: "r"(saddr), "l"(gptr))
#define CP_COMMIT() asm volatile("cp.async.commit_group;" ::: "memory")
#define CP_WAIT1()  asm volatile("cp.async.wait_group 1;" ::: "memory")
#define CP_WAIT0()  asm volatile("cp.async.wait_group 0;" ::: "memory")

__device__ __forceinline__ void packpair(uint32_t& ph, uint32_t& pl, float x, float y) {
    bf16 hx = __float2bfloat16(x), hy = __float2bfloat16(y);
    __nv_bfloat162 t; t.x = hx; t.y = hy;
    ph = *reinterpret_cast<uint32_t*>(&t);
    __nv_bfloat162 u;
    u.x = __float2bfloat16(x - __bfloat162float(hx));
    u.y = __float2bfloat16(y - __bfloat162float(hy));
    pl = *reinterpret_cast<uint32_t*>(&u);
}

// ---------------------------------------------------------------------------
// activation split kernels
// ---------------------------------------------------------------------------
__global__ void split_k(const float* __restrict__ x, bf16* __restrict__ h,
                        bf16* __restrict__ l, int n4) {
    int i = blockIdx.x * 256 + threadIdx.x;
    if (i >= n4) return;
    float4 v = reinterpret_cast<const float4*>(x)[i];
    uint32_t h01, l01, h23, l23;
    packpair(h01, l01, v.x, v.y);
    packpair(h23, l23, v.z, v.w);
    reinterpret_cast<uint32_t*>(h)[i * 2]     = h01;
    reinterpret_cast<uint32_t*>(h)[i * 2 + 1] = h23;
    reinterpret_cast<uint32_t*>(l)[i * 2]     = l01;
    reinterpret_cast<uint32_t*>(l)[i * 2 + 1] = l23;
}

// splitcat: X = [kq | v] -> sX hi/lo; ALSO writes kq split (R x 64) for layer B.
__global__ void splitcat_k(const float* __restrict__ kq, const float* __restrict__ v,
                           bf16* __restrict__ h, bf16* __restrict__ l,
                           bf16* __restrict__ kqh, bf16* __restrict__ kql) {
    int i = blockIdx.x * 256 + threadIdx.x;
    if (i >= R_TOTAL * 32) return;
    int e = i * 4;
    int r = e >> 7, d = e & 127;
    float4 val = (d < 64)
        ? *reinterpret_cast<const float4*>(&kq[(size_t)r * 64 + d])
        : *reinterpret_cast<const float4*>(&v[(size_t)r * 64 + (d - 64)]);
    uint32_t h01, l01, h23, l23;
    packpair(h01, l01, val.x, val.y);
    packpair(h23, l23, val.z, val.w);
    reinterpret_cast<uint32_t*>(h)[i * 2]     = h01;
    reinterpret_cast<uint32_t*>(h)[i * 2 + 1] = h23;
    reinterpret_cast<uint32_t*>(l)[i * 2]     = l01;
    reinterpret_cast<uint32_t*>(l)[i * 2 + 1] = l23;
    if (d < 64) {
        size_t o = ((size_t)r * 64 + d) >> 1;   // uint32 index
        reinterpret_cast<uint32_t*>(kqh)[o]     = h01;
        reinterpret_cast<uint32_t*>(kqh)[o + 1] = h23;
        reinterpret_cast<uint32_t*>(kql)[o]     = l01;
        reinterpret_cast<uint32_t*>(kql)[o + 1] = l23;
    }
}

// ---------------------------------------------------------------------------
// fused weight prep
// ---------------------------------------------------------------------------
__global__ void smallprep_k(const float* __restrict__ f2W, const float* __restrict__ outW,
                            const float* __restrict__ f2b, const float* __restrict__ out_b,
                            const float* __restrict__ A_bk, const float* __restrict__ A_bq,
                            const float* __restrict__ A_bv, const float* __restrict__ B_bk,
                            const float* __restrict__ B_bq,
                            float* __restrict__ Wc, float* __restrict__ bc,
                            float* __restrict__ qkvbA, float* __restrict__ kqb2)
{
    int gid = blockIdx.x * 256 + threadIdx.x;
    if (gid < 512 * 32) {
        int k = gid >> 5, n = gid & 31;
        float s = 0.f;
        for (int j = 0; j < 128; j++) s = fmaf(f2W[k * 128 + j], outW[j * 32 + n], s);
        Wc[gid] = s;
        return;
    }
    int r = gid - 512 * 32;
    if (r < 32) {
        float s = out_b[r];
        for (int j = 0; j < 128; j++) s = fmaf(f2b[j], outW[j * 32 + r], s);
        bc[r] = s;
        return;
    }
    r -= 32;
    if (r < 384) {
        float v = (r < 128) ? A_bk[r] : (r < 256) ? A_bq[r - 128] * LOG2E : A_bv[r - 256];
        qkvbA[r] = v;
        return;
    }
    r -= 384;
    if (r < 256) {
        kqb2[r] = (r < 128) ? B_bk[r] : B_bq[r - 128] * LOG2E;
    }
}

struct Prep10 { const float* s[10]; };
__device__ __constant__ const int  PS_START[10] = {0,16384,32768,49152,57344,65536,81920,147456,212992,278528};
#define PW_TOTAL 344064
__device__ __constant__ const int  PS_KD[10]    = {128,128,128, 64, 64,128,128,512,128,512};
__device__ __constant__ const int  PS_ND[10]    = {128,128,128,128,128,128,512,128,512, 32};
__device__ __constant__ const float PS_SC[10]   = {1.f,LOG2E,1.f,1.f,LOG2E,1.f,1.f,1.f,1.f,1.f};

__global__ void prepw_k(Prep10 srcs, bf16* __restrict__ th, bf16* __restrict__ tl) {
    int gid = blockIdx.x * 256 + threadIdx.x;
    if (gid >= PW_TOTAL) return;
    int s = 0;
#pragma unroll
    for (int i = 1; i < 10; i++) if (gid >= PS_START[i]) s = i;
    int idx = gid - PS_START[s];
    int Kd = PS_KD[s], Nd = PS_ND[s];
    int n = idx / Kd, k = idx - n * Kd;
    float w = (n < Nd) ? srcs.s[s][(size_t)k * Nd + n] * PS_SC[s] : 0.f;
    bf16 h = __float2bfloat16(w);
    th[gid] = h;
    tl[gid] = __float2bfloat16(w - __bfloat162float(h));
}

// ---------------------------------------------------------------------------
// mma_gemm<BM>: C = A[M,K] @ Wt[N,K]^T + bias, bf16x3 split, cp.async pipelined.
// 256 threads; CTA tile BM x 128. BM=128: warp tile 32x64. BM=64: 32x32.
// ---------------------------------------------------------------------------
#define GEMM_SMEM128 81920
#define GEMM_SMEM64  61440
template<int BM>
__global__ __launch_bounds__(256, 2) void mma_gemm(
    const bf16* __restrict__ Ah, const bf16* __restrict__ Al,
    const bf16* __restrict__ Bh, const bf16* __restrict__ Bl,
    const float* __restrict__ bias, int Nvalid,
    float* __restrict__ Cf, int f_lo, int fStride,
    bf16* __restrict__ Ch, bf16* __restrict__ Cl, int cStride,
    int K, int act)
{
    constexpr int A_BUF  = BM * 40;              // elems per buffer
    constexpr int NWARPN = (BM == 128) ? 2 : 4;
    constexpr int WNT    = 128 / NWARPN;         // warp n-tile: 64 or 32
    constexpr int NJ     = WNT / 16;             // 4 or 2
    constexpr int NT     = 2 * NJ;               // 8 or 4

    extern __shared__ __align__(16) char dsm[];
    bf16* smA_h = (bf16*)dsm;                    // [2][A_BUF]
    bf16* smA_l = smA_h + 2 * A_BUF;
    bf16* smB_h = smA_l + 2 * A_BUF;             // [2][5120]
    bf16* smB_l = smB_h + 2 * 5120;

    const int tid = threadIdx.x;
    const int l = tid & 31, w = tid >> 5;
    const int wm = w / NWARPN, wn = w % NWARPN;
    const int bm = blockIdx.y * BM, bn = blockIdx.x * 128;

    float d[2][NT][4];
#pragma unroll
    for (int mt = 0; mt < 2; mt++)
#pragma unroll
        for (int nt = 0; nt < NT; nt++)
#pragma unroll
            for (int q = 0; q < 4; q++) d[mt][nt][q] = 0.f;

    const uint32_t aAh = smem_u32(smA_h), aAl = smem_u32(smA_l);
    const uint32_t aBh = smem_u32(smB_h), aBl = smem_u32(smB_l);

    const int a_row = wm * 32 + (l & 7) + ((l >> 3) & 1) * 8;
    const int a_kof = (l >> 4) * 8;
    const int b_row = wn * WNT + (l >> 4) * 8 + (l & 7);
    const int b_kof = ((l >> 3) & 1) * 8;

    auto issue_chunk = [&](int kcElem, int buf) {
#pragma unroll
        for (int i = tid; i < BM * 4; i += 256) {
            int row = i >> 2, ch = i & 3;
            size_t ga = (size_t)(bm + row) * K + kcElem + ch * 8;
            int sa = buf * A_BUF + row * 40 + ch * 8;
            CP_ASYNC16(smem_u32(smA_h + sa), Ah + ga);
            CP_ASYNC16(smem_u32(smA_l + sa), Al + ga);
        }
#pragma unroll
        for (int i = tid; i < 512; i += 256) {
            int row = i >> 2, ch = i & 3;
            size_t gb = (size_t)(bn + row) * K + kcElem + ch * 8;
            int sb = buf * 5120 + row * 40 + ch * 8;
            CP_ASYNC16(smem_u32(smB_h + sb), Bh + gb);
            CP_ASYNC16(smem_u32(smB_l + sb), Bl + gb);
        }
    };

    const int nch = K >> 5;
    issue_chunk(0, 0);
    CP_COMMIT();

    for (int kc = 0; kc < nch; kc++) {
        const int buf = kc & 1;
        if (kc + 1 < nch) { issue_chunk((kc + 1) << 5, buf ^ 1); CP_COMMIT(); CP_WAIT1(); }
        else              { CP_WAIT0(); }
        __syncthreads();

        const uint32_t bufA = (uint32_t)buf * A_BUF * 2;    // bytes
        const uint32_t bufB = (uint32_t)buf * 5120 * 2;
#pragma unroll
        for (int ks = 0; ks < 32; ks += 16) {
            uint32_t ah[2][4], al2[2][4];
#pragma unroll
            for (int mt = 0; mt < 2; mt++) {
                uint32_t off = bufA + (uint32_t)(((a_row + mt * 16) * 40 + a_kof + ks) * 2);
                LDMX4(ah[mt][0], ah[mt][1], ah[mt][2], ah[mt][3], aAh + off);
                LDMX4(al2[mt][0], al2[mt][1], al2[mt][2], al2[mt][3], aAl + off);
            }
#pragma unroll
            for (int j = 0; j < NJ; j++) {
                uint32_t boff = bufB + (uint32_t)(((b_row + j * 16) * 40 + b_kof + ks) * 2);
                uint32_t bh[4], bl2[4];
                LDMX4(bh[0], bh[1], bh[2], bh[3], aBh + boff);
                LDMX4(bl2[0], bl2[1], bl2[2], bl2[3], aBl + boff);
#pragma unroll
                for (int mt = 0; mt < 2; mt++) {
                    MMA16816(d[mt][2 * j],     ah[mt],  bh[0],  bh[1]);
                    MMA16816(d[mt][2 * j],     al2[mt], bh[0],  bh[1]);
                    MMA16816(d[mt][2 * j],     ah[mt],  bl2[0], bl2[1]);
                    MMA16816(d[mt][2 * j + 1], ah[mt],  bh[2],  bh[3]);
                    MMA16816(d[mt][2 * j + 1], al2[mt], bh[2],  bh[3]);
                    MMA16816(d[mt][2 * j + 1], ah[mt],  bl2[2], bl2[3]);
                }
            }
        }
        __syncthreads();
    }

#pragma unroll
    for (int mt = 0; mt < 2; mt++) {
        int r0 = bm + wm * 32 + mt * 16 + (l >> 2);
#pragma unroll
        for (int nt = 0; nt < NT; nt++) {
            int c = bn + wn * WNT + nt * 8 + (l & 3) * 2;
            if (c >= Nvalid) continue;
            float b0 = bias[c], b1 = bias[c + 1];
            float2 v0, v1;
            v0.x = d[mt][nt][0] + b0; v0.y = d[mt][nt][1] + b1;
            v1.x = d[mt][nt][2] + b0; v1.y = d[mt][nt][3] + b1;
            if (act) {
                v0.x = gelu_exact(v0.x); v0.y = gelu_exact(v0.y);
                v1.x = gelu_exact(v1.x); v1.y = gelu_exact(v1.y);
            }
            if (Cf && c >= f_lo) {
                *reinterpret_cast<float2*>(&Cf[(size_t)r0 * fStride + (c - f_lo)]) = v0;
                *reinterpret_cast<float2*>(&Cf[(size_t)(r0 + 8) * fStride + (c - f_lo)]) = v1;
            }
            if (Ch) {
                uint32_t h0, l0p, h1v, l1p;
                packpair(h0, l0p, v0.x, v0.y);
                packpair(h1v, l1p, v1.x, v1.y);
                *reinterpret_cast<uint32_t*>(&Ch[(size_t)r0 * cStride + c]) = h0;
                *reinterpret_cast<uint32_t*>(&Cl[(size_t)r0 * cStride + c]) = l0p;
                *reinterpret_cast<uint32_t*>(&Ch[(size_t)(r0 + 8) * cStride + c]) = h1v;
                *reinterpret_cast<uint32_t*>(&Cl[(size_t)(r0 + 8) * cStride + c]) = l1p;
            }
        }
    }
}

// ---------------------------------------------------------------------------
// attn_tc: tensor-core flash attention, 64q x 64k tiles, dh=32,
// cp.async double-buffered K/V; Q staging aliased into KV buf1 (smem 40KB).
// 128 threads = 4 warps x 16 q rows. Q pre-scaled by log2(e).
// mode 0: j <= i.  mode 1: j < i OR (i==0 && j==0).
// ---------------------------------------------------------------------------
#define ATTN_SMEM 40960
__global__ __launch_bounds__(128) void attn_tc(
    const bf16* __restrict__ Qh, const bf16* __restrict__ Ql, int qStride,
    const bf16* __restrict__ Kh, const bf16* __restrict__ Kl, int kStride,
    const bf16* __restrict__ Vh, const bf16* __restrict__ Vl, int vStride,
    float* __restrict__ Of, bf16* __restrict__ Oh, bf16* __restrict__ Ol, int oStride,
    int mode)
{
    extern __shared__ __align__(16) char dsm[];
    bf16* dsmb = (bf16*)dsm;

    const int tid = threadIdx.x, l = tid & 31, w = tid >> 5;
    const int bh = blockIdx.y;
    const int hc = (bh & 3) * 32;
    const int bb = bh >> 2;
    const size_t baseQ = (size_t)bb * T_SEQ * qStride + hc;
    const size_t baseK = (size_t)bb * T_SEQ * kStride + hc;
    const size_t baseV = (size_t)bb * T_SEQ * vStride + hc;
    const size_t baseO = (size_t)bb * T_SEQ * oStride + hc;
    const int q0 = (gridDim.x - 1 - blockIdx.x) * 64;

    const uint32_t aKV = smem_u32(dsmb);

    auto issue_kv = [&](int j0, int buf) {
#pragma unroll
        for (int i = tid; i < 256; i += 128) {
            int row = i >> 2, ch = i & 3;
            size_t gk = baseK + (size_t)(j0 + row) * kStride + ch * 8;
            size_t gv = baseV + (size_t)(j0 + row) * vStride + ch * 8;
            uint32_t sa = aKV + (uint32_t)(buf * 10240 + row * 40 + ch * 8) * 2;
            CP_ASYNC16(sa,          Kh + gk);
            CP_ASYNC16(sa + 5120,   Kl + gk);
            CP_ASYNC16(sa + 10240,  Vh + gv);
            CP_ASYNC16(sa + 15360,  Vl + gv);
        }
    };

    issue_kv(0, 0);
    CP_COMMIT();

    bf16* sQh = dsmb + 10240;
    bf16* sQl = dsmb + 12800;
    for (int i = tid; i < 256; i += 128) {
        int row = i >> 2, ch = i & 3;
        size_t g = baseQ + (size_t)(q0 + row) * qStride + ch * 8;
        *reinterpret_cast<uint4*>(&sQh[row * 40 + ch * 8]) = *reinterpret_cast<const uint4*>(&Qh[g]);
        *reinterpret_cast<uint4*>(&sQl[row * 40 + ch * 8]) = *reinterpret_cast<const uint4*>(&Ql[g]);
    }
    __syncthreads();

    uint32_t qh[2][4], ql[2][4];
    const int a_row = w * 16 + (l & 7) + ((l >> 3) & 1) * 8;
    const int a_col = (l >> 4) * 8;
    {
        const uint32_t aQh = smem_u32(sQh), aQl = smem_u32(sQl);
#pragma unroll
        for (int ks = 0; ks < 2; ks++) {
            uint32_t off = (uint32_t)((a_row * 40 + a_col + ks * 16) * 2);
            LDMX4(qh[ks][0], qh[ks][1], qh[ks][2], qh[ks][3], aQh + off);
            LDMX4(ql[ks][0], ql[ks][1], ql[ks][2], ql[ks][3], aQl + off);
        }
    }
    __syncthreads();

    const float NEG = -1e30f;
    const int r0 = q0 + w * 16 + (l >> 2);
    const int r1 = r0 + 8;
    float m0 = NEG, m1 = NEG, lac0 = 0.f, lac1 = 0.f;
    float o[4][4];
#pragma unroll
    for (int n = 0; n < 4; n++)
#pragma unroll
        for (int q = 0; q < 4; q++) o[n][q] = 0.f;

    const int b_row_base = (l >> 4) * 8 + (l & 7);
    const int b_kof = ((l >> 3) & 1) * 8;
    const int ntiles = (q0 >> 6) + 1;

    for (int jt = 0; jt < ntiles; jt++) {
        const int j0 = jt * 64;
        const int buf = jt & 1;
        if (jt + 1 < ntiles) { issue_kv(j0 + 64, buf ^ 1); CP_COMMIT(); CP_WAIT1(); }
        else                 { CP_WAIT0(); }
        __syncthreads();
        const uint32_t bufB = (uint32_t)buf * 20480;

        float s[8][4];
#pragma unroll
        for (int nt = 0; nt < 8; nt++)
#pragma unroll
            for (int q = 0; q < 4; q++) s[nt][q] = 0.f;

#pragma unroll
        for (int ks = 0; ks < 2; ks++) {
#pragma unroll
            for (int jp = 0; jp < 4; jp++) {
                uint32_t off = aKV + bufB + (uint32_t)(((jp * 16 + b_row_base) * 40 + b_kof + ks * 16) * 2);
                uint32_t kb[4], kbl[4];
                LDMX4(kb[0], kb[1], kb[2], kb[3], off);
                LDMX4(kbl[0], kbl[1], kbl[2], kbl[3], off + 5120);
                MMA16816(s[2 * jp],     qh[ks], kb[0],  kb[1]);
                MMA16816(s[2 * jp],     ql[ks], kb[0],  kb[1]);
                MMA16816(s[2 * jp],     qh[ks], kbl[0], kbl[1]);
                MMA16816(s[2 * jp + 1], qh[ks], kb[2],  kb[3]);
                MMA16816(s[2 * jp + 1], ql[ks], kb[2],  kb[3]);
                MMA16816(s[2 * jp + 1], qh[ks], kbl[2], kbl[3]);
            }
        }

        if (j0 >= q0) {
#pragma unroll
            for (int nt = 0; nt < 8; nt++) {
                int cb = j0 + nt * 8 + (l & 3) * 2;
                if (mode == 0) {
                    if (cb     > r0) s[nt][0] = NEG;
                    if (cb + 1 > r0) s[nt][1] = NEG;
                    if (cb     > r1) s[nt][2] = NEG;
                    if (cb + 1 > r1) s[nt][3] = NEG;
                } else {
                    if (!(cb     < r0 || (r0 == 0 && cb == 0))) s[nt][0] = NEG;
                    if (!(cb + 1 < r0))                          s[nt][1] = NEG;
                    if (!(cb     < r1)) s[nt][2] = NEG;
                    if (!(cb + 1 < r1)) s[nt][3] = NEG;
                }
            }
        }

        float ml0 = NEG, ml1 = NEG;
#pragma unroll
        for (int nt = 0; nt < 8; nt++) {
            ml0 = fmaxf(ml0, fmaxf(s[nt][0], s[nt][1]));
            ml1 = fmaxf(ml1, fmaxf(s[nt][2], s[nt][3]));
        }
        ml0 = fmaxf(ml0, __shfl_xor_sync(0xffffffffu, ml0, 1));
        ml0 = fmaxf(ml0, __shfl_xor_sync(0xffffffffu, ml0, 2));
        ml1 = fmaxf(ml1, __shfl_xor_sync(0xffffffffu, ml1, 1));
        ml1 = fmaxf(ml1, __shfl_xor_sync(0xffffffffu, ml1, 2));
        float mn0 = fmaxf(m0, ml0), mn1 = fmaxf(m1, ml1);
        float sc0 = ex2(m0 - mn0), sc1 = ex2(m1 - mn1);

        uint32_t pah[4][4], pal[4][4];
        float ps0 = 0.f, ps1 = 0.f;
#pragma unroll
        for (int pt = 0; pt < 4; pt++) {
#pragma unroll
            for (int half = 0; half < 2; half++) {
                int nt = 2 * pt + half;
                float p0 = ex2(s[nt][0] - mn0), p1 = ex2(s[nt][1] - mn0);
                float p2 = ex2(s[nt][2] - mn1), p3 = ex2(s[nt][3] - mn1);
                ps0 += p0 + p1; ps1 += p2 + p3;
                packpair(pah[pt][2 * half],     pal[pt][2 * half],     p0, p1);
                packpair(pah[pt][2 * half + 1], pal[pt][2 * half + 1], p2, p3);
            }
        }
        lac0 = lac0 * sc0 + ps0;
        lac1 = lac1 * sc1 + ps1;
#pragma unroll
        for (int n = 0; n < 4; n++) {
            o[n][0] *= sc0; o[n][1] *= sc0; o[n][2] *= sc1; o[n][3] *= sc1;
        }

#pragma unroll
        for (int pt = 0; pt < 4; pt++) {
#pragma unroll
            for (int np = 0; np < 2; np++) {
                uint32_t off = aKV + bufB + 10240u
                             + (uint32_t)(((pt * 16 + (l & 15)) * 40 + np * 16 + (l >> 4) * 8) * 2);
                uint32_t vb[4], vbl[4];
                LDMX4T(vb[0], vb[1], vb[2], vb[3], off);
                LDMX4T(vbl[0], vbl[1], vbl[2], vbl[3], off + 5120);
                MMA16816(o[2 * np],     pah[pt], vb[0],  vb[1]);
                MMA16816(o[2 * np],     pal[pt], vb[0],  vb[1]);
                MMA16816(o[2 * np],     pah[pt], vbl[0], vbl[1]);
                MMA16816(o[2 * np + 1], pah[pt], vb[2],  vb[3]);
                MMA16816(o[2 * np + 1], pal[pt], vb[2],  vb[3]);
                MMA16816(o[2 * np + 1], pah[pt], vbl[2], vbl[3]);
            }
        }
        m0 = mn0; m1 = mn1;
        __syncthreads();
    }

    lac0 += __shfl_xor_sync(0xffffffffu, lac0, 1);
    lac0 += __shfl_xor_sync(0xffffffffu, lac0, 2);
    lac1 += __shfl_xor_sync(0xffffffffu, lac1, 1);
    lac1 += __shfl_xor_sync(0xffffffffu, lac1, 2);
    float inv0 = 1.f / lac0, inv1 = 1.f / lac1;

#pragma unroll
    for (int nt = 0; nt < 4; nt++) {
        int col = nt * 8 + (l & 3) * 2;
        float v00 = o[nt][0] * inv0, v01 = o[nt][1] * inv0;
        float v10 = o[nt][2] * inv1, v11 = o[nt][3] * inv1;
        if (Of) {
            float2 a; a.x = v00; a.y = v01;
            float2 b; b.x = v10; b.y = v11;
            *reinterpret_cast<float2*>(&Of[baseO + (size_t)r0 * oStride + col]) = a;
            *reinterpret_cast<float2*>(&Of[baseO + (size_t)r1 * oStride + col]) = b;
        }
        if (Oh) {
            uint32_t h0, l0p, h1v, l1p;
            packpair(h0, l0p, v00, v01);
            packpair(h1v, l1p, v10, v11);
            *reinterpret_cast<uint32_t*>(&Oh[baseO + (size_t)r0 * oStride + col]) = h0;
            *reinterpret_cast<uint32_t*>(&Ol[baseO + (size_t)r0 * oStride + col]) = l0p;
            *reinterpret_cast<uint32_t*>(&Oh[baseO + (size_t)r1 * oStride + col]) = h1v;
            *reinterpret_cast<uint32_t*>(&Ol[baseO + (size_t)r1 * oStride + col]) = l1p;
        }
    }
}

// ---------------------------------------------------------------------------
// out = LayerNorm(A + B) * gamma + beta; fp32 out optional, bf16 hi/lo optional
// ---------------------------------------------------------------------------
__global__ void add_ln_k(const float* __restrict__ A, const float* __restrict__ Bv,
                         const float* __restrict__ gam, const float* __restrict__ bet,
                         float* __restrict__ outf, bf16* __restrict__ outh,
                         bf16* __restrict__ outl)
{
    int row = blockIdx.x;
    int d = threadIdx.x;  // 128
    float x = A[(size_t)row * 128 + d] + Bv[(size_t)row * 128 + d];

    __shared__ float ws[4], ws2[4];
    float v = x;
#pragma unroll
    for (int off = 16; off; off >>= 1) v += __shfl_xor_sync(0xffffffffu, v, off);
    if ((d & 31) == 0) ws[d >> 5] = v;
    __syncthreads();
    float mean = (ws[0] + ws[1] + ws[2] + ws[3]) * (1.f / 128.f);
    float dif = x - mean;
    float v2 = dif * dif;
#pragma unroll
    for (int off = 16; off; off >>= 1) v2 += __shfl_xor_sync(0xffffffffu, v2, off);
    if ((d & 31) == 0) ws2[d >> 5] = v2;
    __syncthreads();
    float var = (ws2[0] + ws2[1] + ws2[2] + ws2[3]) * (1.f / 128.f);
    float y = dif * rsqrtf(var + 1e-5f) * gam[d] + bet[d];
    if (outf) outf[(size_t)row * 128 + d] = y;
    if (outh) {
        bf16 h = __float2bfloat16(y);
        outh[(size_t)row * 128 + d] = h;
        outl[(size_t)row * 128 + d] = __float2bfloat16(y - __bfloat162float(h));
    }
}

// ---------------------------------------------------------------------------
extern "C" void kernel_launch(void* const* d_in, const int* in_sizes, int n_in,
                              void* d_out, int out_size)
{
    const float* kq    = (const float*)d_in[0];
    const float* v_in  = (const float*)d_in[1];
    const float* A_Wk  = (const float*)d_in[2];
    const float* A_bk  = (const float*)d_in[3];
    const float* A_Wq  = (const float*)d_in[4];
    const float* A_bq  = (const float*)d_in[5];
    const float* A_Wv  = (const float*)d_in[6];
    const float* A_bv  = (const float*)d_in[7];
    const float* A_f1W = (const float*)d_in[8];
    const float* A_f1b = (const float*)d_in[9];
    const float* A_f2W = (const float*)d_in[10];
    const float* A_f2b = (const float*)d_in[11];
    const float* A_n1g = (const float*)d_in[12];
    const float* A_n1b = (const float*)d_in[13];
    const float* A_n2g = (const float*)d_in[14];
    const float* A_n2b = (const float*)d_in[15];
    const float* B_Wk  = (const float*)d_in[16];
    const float* B_bk  = (const float*)d_in[17];
    const float* B_Wq  = (const float*)d_in[18];
    const float* B_bq  = (const float*)d_in[19];
    const float* B_Wv  = (const float*)d_in[20];
    const float* B_bv  = (const float*)d_in[21];
    const float* B_f1W = (const float*)d_in[22];
    const float* B_f1b = (const float*)d_in[23];
    const float* B_f2W = (const float*)d_in[24];
    const float* B_f2b = (const float*)d_in[25];
    const float* out_W = (const float*)d_in[26];
    const float* out_b = (const float*)d_in[27];
    float* out = (float*)d_out;

    float* pool = nullptr;
    cudaGetSymbolAddress((void**)&pool, g_scratch);

    static bool attr_done = false;
    if (!attr_done) {
        cudaFuncSetAttribute(mma_gemm<128>, cudaFuncAttributeMaxDynamicSharedMemorySize, GEMM_SMEM128);
        cudaFuncSetAttribute(mma_gemm<64>,  cudaFuncAttributeMaxDynamicSharedMemorySize, GEMM_SMEM64);
        cudaFuncSetAttribute(attn_tc, cudaFuncAttributeMaxDynamicSharedMemorySize, ATTN_SMEM);
        attr_done = true;
    }

    const size_t S = (size_t)R_TOTAL * 128;  // 2M floats per slot
    float* attnA = pool + 0 * S;
    float* h1    = pool + 1 * S;
    float* t1    = pool + 2 * S;
    float* Va    = pool + 3 * S;
    bf16* qkvA_h = (bf16*)(pool + 4 * S);    // R x 384 (slots 4-5)
    bf16* qkvA_l = (bf16*)(pool + 6 * S);    // slots 6-7
    bf16* sXh    = (bf16*)(pool + 8 * S);
    bf16* sXl    = (bf16*)(pool + 9 * S);
    bf16* ffh    = (bf16*)(pool + 10 * S);   // R x 512 (slots 10-11)
    bf16* ffl    = (bf16*)(pool + 12 * S);   // slots 12-13
    bf16* kqh    = (bf16*)(pool + 14 * S);
    bf16* kql    = (bf16*)(pool + 15 * S);
    bf16* kq2h   = (bf16*)(pool + 16 * S);   // R x 256
    bf16* kq2l   = (bf16*)(pool + 17 * S);
    bf16* v2h    = (bf16*)(pool + 18 * S);
    bf16* v2l    = (bf16*)(pool + 19 * S);
    bf16* at2h   = (bf16*)(pool + 20 * S);
    bf16* at2l   = (bf16*)(pool + 21 * S);
    bf16* vAh    = (bf16*)(pool + 22 * S);
    bf16* vAl    = (bf16*)(pool + 23 * S);
    float* Wc    = pool + 24 * S;            // 512x32 fp32
    float* bc    = Wc + 512 * 32;
    float* qkvbA = bc + 64;                  // 384
    float* kqb2  = qkvbA + 384;              // 256
    bf16* wArena = (bf16*)(pool + 25 * S);
    bf16* wH = wArena;
    bf16* wL = wArena + PW_TOTAL;
    bf16* qkvW_h = wH + 0;       bf16* qkvW_l = wL + 0;
    bf16* kqW_h  = wH + 49152;   bf16* kqW_l  = wL + 49152;
    bf16* bWv_h  = wH + 65536;   bf16* bWv_l  = wL + 65536;
    bf16* af1_h  = wH + 81920;   bf16* af1_l  = wL + 81920;
    bf16* af2_h  = wH + 147456;  bf16* af2_l  = wL + 147456;
    bf16* bf1_h  = wH + 212992;  bf16* bf1_l  = wL + 212992;
    bf16* wc_h   = wH + 278528;  bf16* wc_l   = wL + 278528;

    // ---- weight prep: 2 launches ----
    smallprep_k<<<(512*32 + 32 + 640 + 255) / 256, 256>>>(
        B_f2W, out_W, B_f2b, out_b, A_bk, A_bq, A_bv, B_bk, B_bq,
        Wc, bc, qkvbA, kqb2);
    Prep10 p10;
    p10.s[0] = A_Wk; p10.s[1] = A_Wq; p10.s[2] = A_Wv;
    p10.s[3] = B_Wk; p10.s[4] = B_Wq; p10.s[5] = B_Wv;
    p10.s[6] = A_f1W; p10.s[7] = A_f2W; p10.s[8] = B_f1W; p10.s[9] = Wc;
    prepw_k<<<(PW_TOTAL + 255) / 256, 256>>>(p10, wH, wL);

    dim3 blk256(256);
    dim3 attnGrid(T_SEQ / 64, 8 * NHEAD);  // (32, 32)

    // ---- Layer A ----
    splitcat_k<<<(R_TOTAL*32+255)/256, 256>>>(kq, v_in, sXh, sXl, kqh, kql);
    mma_gemm<128><<<dim3(3, 128), blk256, GEMM_SMEM128>>>(sXh, sXl, qkvW_h, qkvW_l, qkvbA, 384,
                                       Va, 256, 128, qkvA_h, qkvA_l, 384, 128, 0);
    attn_tc<<<attnGrid, 128, ATTN_SMEM>>>(qkvA_h + 128, qkvA_l + 128, 384,
                               qkvA_h, qkvA_l, 384,
                               qkvA_h + 256, qkvA_l + 256, 384,
                               attnA, nullptr, nullptr, 128, 0);
    add_ln_k<<<R_TOTAL, 128>>>(Va, attnA, A_n1g, A_n1b, h1, sXh, sXl);
    mma_gemm<128><<<dim3(4, 128), blk256, GEMM_SMEM128>>>(sXh, sXl, af1_h, af1_l, A_f1b, 512,
                                       nullptr, 0, 0, ffh, ffl, 512, 128, 1);
    mma_gemm<64><<<dim3(1, 256), blk256, GEMM_SMEM64>>>(ffh, ffl, af2_h, af2_l, A_f2b, 128,
                                       t1, 0, 128, nullptr, nullptr, 0, 512, 0);
    add_ln_k<<<R_TOTAL, 128>>>(h1, t1, A_n2g, A_n2b, nullptr, vAh, vAl);

    // ---- Layer B ----
    mma_gemm<64><<<dim3(2, 256), blk256, GEMM_SMEM64>>>(kqh, kql, kqW_h, kqW_l, kqb2, 256,
                                       nullptr, 0, 0, kq2h, kq2l, 256, 64, 0);
    mma_gemm<64><<<dim3(1, 256), blk256, GEMM_SMEM64>>>(vAh, vAl, bWv_h, bWv_l, B_bv, 128,
                                       nullptr, 0, 0, v2h, v2l, 128, 128, 0);
    attn_tc<<<attnGrid, 128, ATTN_SMEM>>>(kq2h + 128, kq2l + 128, 256,
                               kq2h, kq2l, 256,
                               v2h, v2l, 128,
                               nullptr, at2h, at2l, 128, 1);
    mma_gemm<128><<<dim3(4, 128), blk256, GEMM_SMEM128>>>(at2h, at2l, bf1_h, bf1_l, B_f1b, 512,
                                       nullptr, 0, 0, ffh, ffl, 512, 128, 1);
    mma_gemm<64><<<dim3(1, 256), blk256, GEMM_SMEM64>>>(ffh, ffl, wc_h, wc_l, bc, 32,
                                       out, 0, 32, nullptr, nullptr, 0, 512, 0);
}

// round 12
// speedup vs baseline: 1.1577x; 1.0287x over previous
#include <cuda_runtime.h>
#include <cuda_bf16.h>
#include <math.h>
#include <stdint.h>

// ---------------------------------------------------------------------------
// Model_19104014532987: 2-layer transformer
// B=8 T=2048 DKQ=64 DV=64 EKQ=EV=128 H=4 dh=32 FF=512 OUT=32, R=16384
// mma.sync bf16 (HMMA), bf16x3 split precision, cp.async pipelines.
// Multi-job GEMM launches, LN2 fused into FF2A epilogue, truncation splits.
// ---------------------------------------------------------------------------

#define R_TOTAL 16384
#define T_SEQ   2048
#define EMB     128
#define NHEAD   4
#define LOG2E   1.4426950408889634f

typedef __nv_bfloat16 bf16;

// Scratch pool: 56M floats (224 MB), static device allocation (allowed).
static __device__ __align__(256) float g_scratch[56ull * 1024 * 1024];

__device__ __forceinline__ float gelu_exact(float x) {
    return 0.5f * x * (1.0f + erff(x * 0.70710678118654752440f));
}
__device__ __forceinline__ float ex2(float x) {
    float y; asm("ex2.approx.ftz.f32 %0, %1;" : "=f"(y) : "f"(x)); return y;
}
__device__ __forceinline__ uint32_t smem_u32(const void* p) {
    uint32_t a;
    asm("{ .reg .u64 t; cvta.to.shared.u64 t, %1; cvt.u32.u64 %0, t; }" : "=r"(a) : "l"(p));
    return a;
}

#define LDMX4(r0, r1, r2, r3, addr) \
    asm volatile("ldmatrix.sync.aligned.m8n8.x4.shared.b16 {%0,%1,%2,%3}, [%4];" \
        : "=r"(r0), "=r"(r1), "=r"(r2), "=r"(r3) : "r"(addr))
#define LDMX4T(r0, r1, r2, r3, addr) \
    asm volatile("ldmatrix.sync.aligned.m8n8.x4.trans.shared.b16 {%0,%1,%2,%3}, [%4];" \
        : "=r"(r0), "=r"(r1), "=r"(r2), "=r"(r3) : "r"(addr))
#define MMA16816(d, a, b0, b1) \
    asm volatile("mma.sync.aligned.m16n8k16.row.col.f32.bf16.bf16.f32 " \
        "{%0,%1,%2,%3}, {%4,%5,%6,%7}, {%8,%9}, {%0,%1,%2,%3};" \
        : "+f"((d)[0]), "+f"((d)[1]), "+f"((d)[2]), "+f"((d)[3]) \
        : "r"((a)[0]), "r"((a)[1]), "r"((a)[2]), "r"((a)[3]), "r"(b0), "r"(b1))

#define CP_ASYNC16(saddr, gptr) \
    asm volatile("cp.async.cg.shared.global [%0], [%1], 16;" :: "r"(saddr), "l"(gptr))
#define CP_COMMIT() asm volatile("cp.async.commit_group;" ::: "memory")
#define CP_WAIT1()  asm volatile("cp.async.wait_group 1;" ::: "memory")
#define CP_WAIT0()  asm volatile("cp.async.wait_group 0;" ::: "memory")

// truncation-based bf16 hi/lo split of a float pair (lo absorbs the error)
__device__ __forceinline__ void packpair(uint32_t& ph, uint32_t& pl, float x, float y) {
    uint32_t xu = __float_as_uint(x), yu = __float_as_uint(y);
    ph = __byte_perm(xu, yu, 0x7632);
    float lx = x - __uint_as_float(xu & 0xFFFF0000u);
    float ly = y - __uint_as_float(yu & 0xFFFF0000u);
    pl = __byte_perm(__float_as_uint(lx), __float_as_uint(ly), 0x7632);
}

// ---------------------------------------------------------------------------
// activation split: X = [kq | v] -> sX hi/lo; ALSO writes kq split for layer B.
// ---------------------------------------------------------------------------
__global__ void splitcat_k(const float* __restrict__ kq, const float* __restrict__ v,
                           bf16* __restrict__ h, bf16* __restrict__ l,
                           bf16* __restrict__ kqh, bf16* __restrict__ kql) {
    int i = blockIdx.x * 256 + threadIdx.x;
    if (i >= R_TOTAL * 32) return;
    int e = i * 4;
    int r = e >> 7, d = e & 127;
    float4 val = (d < 64)
        ? *reinterpret_cast<const float4*>(&kq[(size_t)r * 64 + d])
        : *reinterpret_cast<const float4*>(&v[(size_t)r * 64 + (d - 64)]);
    uint32_t h01, l01, h23, l23;
    packpair(h01, l01, val.x, val.y);
    packpair(h23, l23, val.z, val.w);
    reinterpret_cast<uint32_t*>(h)[i * 2]     = h01;
    reinterpret_cast<uint32_t*>(h)[i * 2 + 1] = h23;
    reinterpret_cast<uint32_t*>(l)[i * 2]     = l01;
    reinterpret_cast<uint32_t*>(l)[i * 2 + 1] = l23;
    if (d < 64) {
        size_t o = ((size_t)r * 64 + d) >> 1;
        reinterpret_cast<uint32_t*>(kqh)[o]     = h01;
        reinterpret_cast<uint32_t*>(kqh)[o + 1] = h23;
        reinterpret_cast<uint32_t*>(kql)[o]     = l01;
        reinterpret_cast<uint32_t*>(kql)[o + 1] = l23;
    }
}

// ---------------------------------------------------------------------------
// fused weight prep
// ---------------------------------------------------------------------------
__global__ void smallprep_k(const float* __restrict__ f2W, const float* __restrict__ outW,
                            const float* __restrict__ f2b, const float* __restrict__ out_b,
                            const float* __restrict__ A_bk, const float* __restrict__ A_bq,
                            const float* __restrict__ A_bv, const float* __restrict__ B_bk,
                            const float* __restrict__ B_bq,
                            float* __restrict__ Wc, float* __restrict__ bc,
                            float* __restrict__ qkvbA, float* __restrict__ kqb2)
{
    int gid = blockIdx.x * 256 + threadIdx.x;
    if (gid < 512 * 32) {
        int k = gid >> 5, n = gid & 31;
        float s = 0.f;
        for (int j = 0; j < 128; j++) s = fmaf(f2W[k * 128 + j], outW[j * 32 + n], s);
        Wc[gid] = s;
        return;
    }
    int r = gid - 512 * 32;
    if (r < 32) {
        float s = out_b[r];
        for (int j = 0; j < 128; j++) s = fmaf(f2b[j], outW[j * 32 + r], s);
        bc[r] = s;
        return;
    }
    r -= 32;
    if (r < 384) {
        float v = (r < 128) ? A_bk[r] : (r < 256) ? A_bq[r - 128] * LOG2E : A_bv[r - 256];
        qkvbA[r] = v;
        return;
    }
    r -= 384;
    if (r < 256) {
        kqb2[r] = (r < 128) ? B_bk[r] : B_bq[r - 128] * LOG2E;
    }
}

struct Prep10 { const float* s[10]; };
__device__ __constant__ const int  PS_START[10] = {0,16384,32768,49152,57344,65536,81920,147456,212992,278528};
#define PW_TOTAL 344064
__device__ __constant__ const int  PS_KD[10]    = {128,128,128, 64, 64,128,128,512,128,512};
__device__ __constant__ const int  PS_ND[10]    = {128,128,128,128,128,128,512,128,512, 32};
__device__ __constant__ const float PS_SC[10]   = {1.f,LOG2E,1.f,1.f,LOG2E,1.f,1.f,1.f,1.f,1.f};

__global__ void prepw_k(Prep10 srcs, bf16* __restrict__ th, bf16* __restrict__ tl) {
    int gid = blockIdx.x * 256 + threadIdx.x;
    if (gid >= PW_TOTAL) return;
    int s = 0;
#pragma unroll
    for (int i = 1; i < 10; i++) if (gid >= PS_START[i]) s = i;
    int idx = gid - PS_START[s];
    int Kd = PS_KD[s], Nd = PS_ND[s];
    int n = idx / Kd, k = idx - n * Kd;
    float w = (n < Nd) ? srcs.s[s][(size_t)k * Nd + n] * PS_SC[s] : 0.f;
    bf16 h = __float2bfloat16(w);
    th[gid] = h;
    tl[gid] = __float2bfloat16(w - __bfloat162float(h));
}

// ---------------------------------------------------------------------------
// GEMM job descriptor + shared body
// ---------------------------------------------------------------------------
struct GemmJob {
    const bf16 *Ah, *Al, *Bh, *Bl;
    const float* bias;
    int Nvalid;
    float* Cf; int f_lo, fStride;
    bf16 *Ch, *Cl; int cStride;
    int K, act, gridX;
    const float* lnRes; const float* lnG; const float* lnB;  // LNF only
};

#define GEMM_SMEM128 81920
#define GEMM_SMEM64  61440

template<int BM, bool LNF>
__device__ __forceinline__ void gemm_body(const GemmJob& j, int bx, int by,
                                          char* dsm, int tid)
{
    constexpr int A_BUF  = BM * 40;
    constexpr int NWARPN = (BM == 128) ? 2 : 4;
    constexpr int WNT    = 128 / NWARPN;
    constexpr int NJ     = WNT / 16;
    constexpr int NT     = 2 * NJ;

    bf16* smA_h = (bf16*)dsm;
    bf16* smA_l = smA_h + 2 * A_BUF;
    bf16* smB_h = smA_l + 2 * A_BUF;
    bf16* smB_l = smB_h + 2 * 5120;

    const int l = tid & 31, w = tid >> 5;
    const int wm = w / NWARPN, wn = w % NWARPN;
    const int bm = by * BM, bn = bx * 128;
    const int K = j.K;

    float d[2][NT][4];
#pragma unroll
    for (int mt = 0; mt < 2; mt++)
#pragma unroll
        for (int nt = 0; nt < NT; nt++)
#pragma unroll
            for (int q = 0; q < 4; q++) d[mt][nt][q] = 0.f;

    const uint32_t aAh = smem_u32(smA_h), aAl = smem_u32(smA_l);
    const uint32_t aBh = smem_u32(smB_h), aBl = smem_u32(smB_l);

    const int a_row = wm * 32 + (l & 7) + ((l >> 3) & 1) * 8;
    const int a_kof = (l >> 4) * 8;
    const int b_row = wn * WNT + (l >> 4) * 8 + (l & 7);
    const int b_kof = ((l >> 3) & 1) * 8;

    auto issue_chunk = [&](int kcElem, int buf) {
#pragma unroll
        for (int i = tid; i < BM * 4; i += 256) {
            int row = i >> 2, ch = i & 3;
            size_t ga = (size_t)(bm + row) * K + kcElem + ch * 8;
            int sa = buf * A_BUF + row * 40 + ch * 8;
            CP_ASYNC16(smem_u32(smA_h + sa), j.Ah + ga);
            CP_ASYNC16(smem_u32(smA_l + sa), j.Al + ga);
        }
#pragma unroll
        for (int i = tid; i < 512; i += 256) {
            int row = i >> 2, ch = i & 3;
            size_t gb = (size_t)(bn + row) * K + kcElem + ch * 8;
            int sb = buf * 5120 + row * 40 + ch * 8;
            CP_ASYNC16(smem_u32(smB_h + sb), j.Bh + gb);
            CP_ASYNC16(smem_u32(smB_l + sb), j.Bl + gb);
        }
    };

    const int nch = K >> 5;
    issue_chunk(0, 0);
    CP_COMMIT();

    for (int kc = 0; kc < nch; kc++) {
        const int buf = kc & 1;
        if (kc + 1 < nch) { issue_chunk((kc + 1) << 5, buf ^ 1); CP_COMMIT(); CP_WAIT1(); }
        else              { CP_WAIT0(); }
        __syncthreads();

        const uint32_t bufA = (uint32_t)buf * A_BUF * 2;
        const uint32_t bufB = (uint32_t)buf * 5120 * 2;
#pragma unroll
        for (int ks = 0; ks < 32; ks += 16) {
            uint32_t ah[2][4], al2[2][4];
#pragma unroll
            for (int mt = 0; mt < 2; mt++) {
                uint32_t off = bufA + (uint32_t)(((a_row + mt * 16) * 40 + a_kof + ks) * 2);
                LDMX4(ah[mt][0], ah[mt][1], ah[mt][2], ah[mt][3], aAh + off);
                LDMX4(al2[mt][0], al2[mt][1], al2[mt][2], al2[mt][3], aAl + off);
            }
#pragma unroll
            for (int jj = 0; jj < NJ; jj++) {
                uint32_t boff = bufB + (uint32_t)(((b_row + jj * 16) * 40 + b_kof + ks) * 2);
                uint32_t bh[4], bl2[4];
                LDMX4(bh[0], bh[1], bh[2], bh[3], aBh + boff);
                LDMX4(bl2[0], bl2[1], bl2[2], bl2[3], aBl + boff);
#pragma unroll
                for (int mt = 0; mt < 2; mt++) {
                    MMA16816(d[mt][2 * jj],     ah[mt],  bh[0],  bh[1]);
                    MMA16816(d[mt][2 * jj],     al2[mt], bh[0],  bh[1]);
                    MMA16816(d[mt][2 * jj],     ah[mt],  bl2[0], bl2[1]);
                    MMA16816(d[mt][2 * jj + 1], ah[mt],  bh[2],  bh[3]);
                    MMA16816(d[mt][2 * jj + 1], al2[mt], bh[2],  bh[3]);
                    MMA16816(d[mt][2 * jj + 1], ah[mt],  bl2[2], bl2[3]);
                }
            }
        }
        __syncthreads();
    }

    if constexpr (LNF) {
        // fused residual + LayerNorm epilogue (BM=64, full 128-col rows per CTA)
        float* xs = (float*)dsm;   // [64][132] fp32 staging, stride 132
#pragma unroll
        for (int mt = 0; mt < 2; mt++) {
            int rl = wm * 32 + mt * 16 + (l >> 2);
#pragma unroll
            for (int nt = 0; nt < NT; nt++) {
                int c = wn * WNT + nt * 8 + (l & 3) * 2;
                float2 res0 = *reinterpret_cast<const float2*>(&j.lnRes[(size_t)(bm + rl) * 128 + c]);
                float2 res1 = *reinterpret_cast<const float2*>(&j.lnRes[(size_t)(bm + rl + 8) * 128 + c]);
                float b0 = j.bias[c], b1 = j.bias[c + 1];
                xs[rl * 132 + c]           = d[mt][nt][0] + b0 + res0.x;
                xs[rl * 132 + c + 1]       = d[mt][nt][1] + b1 + res0.y;
                xs[(rl + 8) * 132 + c]     = d[mt][nt][2] + b0 + res1.x;
                xs[(rl + 8) * 132 + c + 1] = d[mt][nt][3] + b1 + res1.y;
            }
        }
        __syncthreads();
        int row = tid >> 2, part = tid & 3;
        const float* xr = xs + row * 132 + part * 32;
        float sum = 0.f;
#pragma unroll
        for (int i = 0; i < 32; i++) sum += xr[i];
        sum += __shfl_xor_sync(0xffffffffu, sum, 1);
        sum += __shfl_xor_sync(0xffffffffu, sum, 2);
        float mean = sum * (1.f / 128.f);
        float s2 = 0.f;
#pragma unroll
        for (int i = 0; i < 32; i++) { float dl = xr[i] - mean; s2 += dl * dl; }
        s2 += __shfl_xor_sync(0xffffffffu, s2, 1);
        s2 += __shfl_xor_sync(0xffffffffu, s2, 2);
        float rstd = rsqrtf(s2 * (1.f / 128.f) + 1e-5f);
        size_t orow = (size_t)(bm + row) * 128 + part * 32;
#pragma unroll
        for (int i = 0; i < 32; i += 2) {
            int c = part * 32 + i;
            float y0 = (xr[i] - mean) * rstd * j.lnG[c] + j.lnB[c];
            float y1 = (xr[i + 1] - mean) * rstd * j.lnG[c + 1] + j.lnB[c + 1];
            uint32_t hh, ll;
            packpair(hh, ll, y0, y1);
            *reinterpret_cast<uint32_t*>(&j.Ch[orow + i]) = hh;
            *reinterpret_cast<uint32_t*>(&j.Cl[orow + i]) = ll;
        }
    } else {
#pragma unroll
        for (int mt = 0; mt < 2; mt++) {
            int r0 = bm + wm * 32 + mt * 16 + (l >> 2);
#pragma unroll
            for (int nt = 0; nt < NT; nt++) {
                int c = bn + wn * WNT + nt * 8 + (l & 3) * 2;
                if (c >= j.Nvalid) continue;
                float b0 = j.bias[c], b1 = j.bias[c + 1];
                float2 v0, v1;
                v0.x = d[mt][nt][0] + b0; v0.y = d[mt][nt][1] + b1;
                v1.x = d[mt][nt][2] + b0; v1.y = d[mt][nt][3] + b1;
                if (j.act) {
                    v0.x = gelu_exact(v0.x); v0.y = gelu_exact(v0.y);
                    v1.x = gelu_exact(v1.x); v1.y = gelu_exact(v1.y);
                }
                if (j.Cf && c >= j.f_lo) {
                    *reinterpret_cast<float2*>(&j.Cf[(size_t)r0 * j.fStride + (c - j.f_lo)]) = v0;
                    *reinterpret_cast<float2*>(&j.Cf[(size_t)(r0 + 8) * j.fStride + (c - j.f_lo)]) = v1;
                }
                if (j.Ch) {
                    uint32_t h0, l0p, h1v, l1p;
                    packpair(h0, l0p, v0.x, v0.y);
                    packpair(h1v, l1p, v1.x, v1.y);
                    *reinterpret_cast<uint32_t*>(&j.Ch[(size_t)r0 * j.cStride + c]) = h0;
                    *reinterpret_cast<uint32_t*>(&j.Cl[(size_t)r0 * j.cStride + c]) = l0p;
                    *reinterpret_cast<uint32_t*>(&j.Ch[(size_t)(r0 + 8) * j.cStride + c]) = h1v;
                    *reinterpret_cast<uint32_t*>(&j.Cl[(size_t)(r0 + 8) * j.cStride + c]) = l1p;
                }
            }
        }
    }
}

template<int BM, bool LNF>
__global__ __launch_bounds__(256, 2) void mma_gemm1(GemmJob j) {
    extern __shared__ __align__(16) char dsm[];
    gemm_body<BM, LNF>(j, blockIdx.x, blockIdx.y, dsm, threadIdx.x);
}

// two independent jobs in one launch (both BM=128); blockIdx.y < splitY -> j0
__global__ __launch_bounds__(256, 2) void mma_gemm2(GemmJob j0, GemmJob j1, int splitY) {
    extern __shared__ __align__(16) char dsm[];
    int by = blockIdx.y;
    const GemmJob& j = (by < splitY) ? j0 : j1;
    if (by >= splitY) by -= splitY;
    if ((int)blockIdx.x >= j.gridX) return;
    gemm_body<128, false>(j, blockIdx.x, by, dsm, threadIdx.x);
}

// ---------------------------------------------------------------------------
// attn_tc: tensor-core flash attention, 64q x 64k tiles, dh=32,
// cp.async double-buffered K/V; Q staging aliased into KV buf1 (smem 40KB).
// 128 threads = 4 warps x 16 q rows. Q pre-scaled by log2(e).
// mode 0: j <= i.  mode 1: j < i OR (i==0 && j==0).
// ---------------------------------------------------------------------------
#define ATTN_SMEM 40960
__global__ __launch_bounds__(128) void attn_tc(
    const bf16* __restrict__ Qh, const bf16* __restrict__ Ql, int qStride,
    const bf16* __restrict__ Kh, const bf16* __restrict__ Kl, int kStride,
    const bf16* __restrict__ Vh, const bf16* __restrict__ Vl, int vStride,
    float* __restrict__ Of, bf16* __restrict__ Oh, bf16* __restrict__ Ol, int oStride,
    int mode)
{
    extern __shared__ __align__(16) char dsm[];
    bf16* dsmb = (bf16*)dsm;

    const int tid = threadIdx.x, l = tid & 31, w = tid >> 5;
    const int bh = blockIdx.y;
    const int hc = (bh & 3) * 32;
    const int bb = bh >> 2;
    const size_t baseQ = (size_t)bb * T_SEQ * qStride + hc;
    const size_t baseK = (size_t)bb * T_SEQ * kStride + hc;
    const size_t baseV = (size_t)bb * T_SEQ * vStride + hc;
    const size_t baseO = (size_t)bb * T_SEQ * oStride + hc;
    const int q0 = (gridDim.x - 1 - blockIdx.x) * 64;

    const uint32_t aKV = smem_u32(dsmb);

    auto issue_kv = [&](int j0, int buf) {
#pragma unroll
        for (int i = tid; i < 256; i += 128) {
            int row = i >> 2, ch = i & 3;
            size_t gk = baseK + (size_t)(j0 + row) * kStride + ch * 8;
            size_t gv = baseV + (size_t)(j0 + row) * vStride + ch * 8;
            uint32_t sa = aKV + (uint32_t)(buf * 10240 + row * 40 + ch * 8) * 2;
            CP_ASYNC16(sa,          Kh + gk);
            CP_ASYNC16(sa + 5120,   Kl + gk);
            CP_ASYNC16(sa + 10240,  Vh + gv);
            CP_ASYNC16(sa + 15360,  Vl + gv);
        }
    };

    issue_kv(0, 0);
    CP_COMMIT();

    bf16* sQh = dsmb + 10240;
    bf16* sQl = dsmb + 12800;
    for (int i = tid; i < 256; i += 128) {
        int row = i >> 2, ch = i & 3;
        size_t g = baseQ + (size_t)(q0 + row) * qStride + ch * 8;
        *reinterpret_cast<uint4*>(&sQh[row * 40 + ch * 8]) = *reinterpret_cast<const uint4*>(&Qh[g]);
        *reinterpret_cast<uint4*>(&sQl[row * 40 + ch * 8]) = *reinterpret_cast<const uint4*>(&Ql[g]);
    }
    __syncthreads();

    uint32_t qh[2][4], ql[2][4];
    const int a_row = w * 16 + (l & 7) + ((l >> 3) & 1) * 8;
    const int a_col = (l >> 4) * 8;
    {
        const uint32_t aQh = smem_u32(sQh), aQl = smem_u32(sQl);
#pragma unroll
        for (int ks = 0; ks < 2; ks++) {
            uint32_t off = (uint32_t)((a_row * 40 + a_col + ks * 16) * 2);
            LDMX4(qh[ks][0], qh[ks][1], qh[ks][2], qh[ks][3], aQh + off);
            LDMX4(ql[ks][0], ql[ks][1], ql[ks][2], ql[ks][3], aQl + off);
        }
    }
    __syncthreads();

    const float NEG = -1e30f;
    const int r0 = q0 + w * 16 + (l >> 2);
    const int r1 = r0 + 8;
    float m0 = NEG, m1 = NEG, lac0 = 0.f, lac1 = 0.f;
    float o[4][4];
#pragma unroll
    for (int n = 0; n < 4; n++)
#pragma unroll
        for (int q = 0; q < 4; q++) o[n][q] = 0.f;

    const int b_row_base = (l >> 4) * 8 + (l & 7);
    const int b_kof = ((l >> 3) & 1) * 8;
    const int ntiles = (q0 >> 6) + 1;

    for (int jt = 0; jt < ntiles; jt++) {
        const int j0 = jt * 64;
        const int buf = jt & 1;
        if (jt + 1 < ntiles) { issue_kv(j0 + 64, buf ^ 1); CP_COMMIT(); CP_WAIT1(); }
        else                 { CP_WAIT0(); }
        __syncthreads();
        const uint32_t bufB = (uint32_t)buf * 20480;

        float s[8][4];
#pragma unroll
        for (int nt = 0; nt < 8; nt++)
#pragma unroll
            for (int q = 0; q < 4; q++) s[nt][q] = 0.f;

#pragma unroll
        for (int ks = 0; ks < 2; ks++) {
#pragma unroll
            for (int jp = 0; jp < 4; jp++) {
                uint32_t off = aKV + bufB + (uint32_t)(((jp * 16 + b_row_base) * 40 + b_kof + ks * 16) * 2);
                uint32_t kb[4], kbl[4];
                LDMX4(kb[0], kb[1], kb[2], kb[3], off);
                LDMX4(kbl[0], kbl[1], kbl[2], kbl[3], off + 5120);
                MMA16816(s[2 * jp],     qh[ks], kb[0],  kb[1]);
                MMA16816(s[2 * jp],     ql[ks], kb[0],  kb[1]);
                MMA16816(s[2 * jp],     qh[ks], kbl[0], kbl[1]);
                MMA16816(s[2 * jp + 1], qh[ks], kb[2],  kb[3]);
                MMA16816(s[2 * jp + 1], ql[ks], kb[2],  kb[3]);
                MMA16816(s[2 * jp + 1], qh[ks], kbl[2], kbl[3]);
            }
        }

        if (j0 >= q0) {
#pragma unroll
            for (int nt = 0; nt < 8; nt++) {
                int cb = j0 + nt * 8 + (l & 3) * 2;
                if (mode == 0) {
                    if (cb     > r0) s[nt][0] = NEG;
                    if (cb + 1 > r0) s[nt][1] = NEG;
                    if (cb     > r1) s[nt][2] = NEG;
                    if (cb + 1 > r1) s[nt][3] = NEG;
                } else {
                    if (!(cb     < r0 || (r0 == 0 && cb == 0))) s[nt][0] = NEG;
                    if (!(cb + 1 < r0))                          s[nt][1] = NEG;
                    if (!(cb     < r1)) s[nt][2] = NEG;
                    if (!(cb + 1 < r1)) s[nt][3] = NEG;
                }
            }
        }

        float ml0 = NEG, ml1 = NEG;
#pragma unroll
        for (int nt = 0; nt < 8; nt++) {
            ml0 = fmaxf(ml0, fmaxf(s[nt][0], s[nt][1]));
            ml1 = fmaxf(ml1, fmaxf(s[nt][2], s[nt][3]));
        }
        ml0 = fmaxf(ml0, __shfl_xor_sync(0xffffffffu, ml0, 1));
        ml0 = fmaxf(ml0, __shfl_xor_sync(0xffffffffu, ml0, 2));
        ml1 = fmaxf(ml1, __shfl_xor_sync(0xffffffffu, ml1, 1));
        ml1 = fmaxf(ml1, __shfl_xor_sync(0xffffffffu, ml1, 2));
        float mn0 = fmaxf(m0, ml0), mn1 = fmaxf(m1, ml1);
        float sc0 = ex2(m0 - mn0), sc1 = ex2(m1 - mn1);

        uint32_t pah[4][4], pal[4][4];
        float ps0 = 0.f, ps1 = 0.f;
#pragma unroll
        for (int pt = 0; pt < 4; pt++) {
#pragma unroll
            for (int half = 0; half < 2; half++) {
                int nt = 2 * pt + half;
                float p0 = ex2(s[nt][0] - mn0), p1 = ex2(s[nt][1] - mn0);
                float p2 = ex2(s[nt][2] - mn1), p3 = ex2(s[nt][3] - mn1);
                ps0 += p0 + p1; ps1 += p2 + p3;
                packpair(pah[pt][2 * half],     pal[pt][2 * half],     p0, p1);
                packpair(pah[pt][2 * half + 1], pal[pt][2 * half + 1], p2, p3);
            }
        }
        lac0 = lac0 * sc0 + ps0;
        lac1 = lac1 * sc1 + ps1;
#pragma unroll
        for (int n = 0; n < 4; n++) {
            o[n][0] *= sc0; o[n][1] *= sc0; o[n][2] *= sc1; o[n][3] *= sc1;
        }

#pragma unroll
        for (int pt = 0; pt < 4; pt++) {
#pragma unroll
            for (int np = 0; np < 2; np++) {
                uint32_t off = aKV + bufB + 10240u
                             + (uint32_t)(((pt * 16 + (l & 15)) * 40 + np * 16 + (l >> 4) * 8) * 2);
                uint32_t vb[4], vbl[4];
                LDMX4T(vb[0], vb[1], vb[2], vb[3], off);
                LDMX4T(vbl[0], vbl[1], vbl[2], vbl[3], off + 5120);
                MMA16816(o[2 * np],     pah[pt], vb[0],  vb[1]);
                MMA16816(o[2 * np],     pal[pt], vb[0],  vb[1]);
                MMA16816(o[2 * np],     pah[pt], vbl[0], vbl[1]);
                MMA16816(o[2 * np + 1], pah[pt], vb[2],  vb[3]);
                MMA16816(o[2 * np + 1], pal[pt], vb[2],  vb[3]);
                MMA16816(o[2 * np + 1], pah[pt], vbl[2], vbl[3]);
            }
        }
        m0 = mn0; m1 = mn1;
        __syncthreads();
    }

    lac0 += __shfl_xor_sync(0xffffffffu, lac0, 1);
    lac0 += __shfl_xor_sync(0xffffffffu, lac0, 2);
    lac1 += __shfl_xor_sync(0xffffffffu, lac1, 1);
    lac1 += __shfl_xor_sync(0xffffffffu, lac1, 2);
    float inv0 = 1.f / lac0, inv1 = 1.f / lac1;

#pragma unroll
    for (int nt = 0; nt < 4; nt++) {
        int col = nt * 8 + (l & 3) * 2;
        float v00 = o[nt][0] * inv0, v01 = o[nt][1] * inv0;
        float v10 = o[nt][2] * inv1, v11 = o[nt][3] * inv1;
        if (Of) {
            float2 a; a.x = v00; a.y = v01;
            float2 b; b.x = v10; b.y = v11;
            *reinterpret_cast<float2*>(&Of[baseO + (size_t)r0 * oStride + col]) = a;
            *reinterpret_cast<float2*>(&Of[baseO + (size_t)r1 * oStride + col]) = b;
        }
        if (Oh) {
            uint32_t h0, l0p, h1v, l1p;
            packpair(h0, l0p, v00, v01);
            packpair(h1v, l1p, v10, v11);
            *reinterpret_cast<uint32_t*>(&Oh[baseO + (size_t)r0 * oStride + col]) = h0;
            *reinterpret_cast<uint32_t*>(&Ol[baseO + (size_t)r0 * oStride + col]) = l0p;
            *reinterpret_cast<uint32_t*>(&Oh[baseO + (size_t)r1 * oStride + col]) = h1v;
            *reinterpret_cast<uint32_t*>(&Ol[baseO + (size_t)r1 * oStride + col]) = l1p;
        }
    }
}

// ---------------------------------------------------------------------------
// out = LayerNorm(A + B) * gamma + beta; fp32 out + bf16 hi/lo out
// ---------------------------------------------------------------------------
__global__ void add_ln_k(const float* __restrict__ A, const float* __restrict__ Bv,
                         const float* __restrict__ gam, const float* __restrict__ bet,
                         float* __restrict__ outf, bf16* __restrict__ outh,
                         bf16* __restrict__ outl)
{
    int row = blockIdx.x;
    int d = threadIdx.x;  // 128
    float x = A[(size_t)row * 128 + d] + Bv[(size_t)row * 128 + d];

    __shared__ float ws[4], ws2[4];
    float v = x;
#pragma unroll
    for (int off = 16; off; off >>= 1) v += __shfl_xor_sync(0xffffffffu, v, off);
    if ((d & 31) == 0) ws[d >> 5] = v;
    __syncthreads();
    float mean = (ws[0] + ws[1] + ws[2] + ws[3]) * (1.f / 128.f);
    float dif = x - mean;
    float v2 = dif * dif;
#pragma unroll
    for (int off = 16; off; off >>= 1) v2 += __shfl_xor_sync(0xffffffffu, v2, off);
    if ((d & 31) == 0) ws2[d >> 5] = v2;
    __syncthreads();
    float var = (ws2[0] + ws2[1] + ws2[2] + ws2[3]) * (1.f / 128.f);
    float y = dif * rsqrtf(var + 1e-5f) * gam[d] + bet[d];
    if (outf) outf[(size_t)row * 128 + d] = y;
    if (outh) {
        bf16 h = __float2bfloat16(y);
        outh[(size_t)row * 128 + d] = h;
        outl[(size_t)row * 128 + d] = __float2bfloat16(y - __bfloat162float(h));
    }
}

// ---------------------------------------------------------------------------
extern "C" void kernel_launch(void* const* d_in, const int* in_sizes, int n_in,
                              void* d_out, int out_size)
{
    const float* kq    = (const float*)d_in[0];
    const float* v_in  = (const float*)d_in[1];
    const float* A_Wk  = (const float*)d_in[2];
    const float* A_bk  = (const float*)d_in[3];
    const float* A_Wq  = (const float*)d_in[4];
    const float* A_bq  = (const float*)d_in[5];
    const float* A_Wv  = (const float*)d_in[6];
    const float* A_bv  = (const float*)d_in[7];
    const float* A_f1W = (const float*)d_in[8];
    const float* A_f1b = (const float*)d_in[9];
    const float* A_f2W = (const float*)d_in[10];
    const float* A_f2b = (const float*)d_in[11];
    const float* A_n1g = (const float*)d_in[12];
    const float* A_n1b = (const float*)d_in[13];
    const float* A_n2g = (const float*)d_in[14];
    const float* A_n2b = (const float*)d_in[15];
    const float* B_Wk  = (const float*)d_in[16];
    const float* B_bk  = (const float*)d_in[17];
    const float* B_Wq  = (const float*)d_in[18];
    const float* B_bq  = (const float*)d_in[19];
    const float* B_Wv  = (const float*)d_in[20];
    const float* B_bv  = (const float*)d_in[21];
    const float* B_f1W = (const float*)d_in[22];
    const float* B_f1b = (const float*)d_in[23];
    const float* B_f2W = (const float*)d_in[24];
    const float* B_f2b = (const float*)d_in[25];
    const float* out_W = (const float*)d_in[26];
    const float* out_b = (const float*)d_in[27];
    float* out = (float*)d_out;

    float* pool = nullptr;
    cudaGetSymbolAddress((void**)&pool, g_scratch);

    static bool attr_done = false;
    if (!attr_done) {
        cudaFuncSetAttribute(mma_gemm1<128,false>, cudaFuncAttributeMaxDynamicSharedMemorySize, GEMM_SMEM128);
        cudaFuncSetAttribute(mma_gemm1<64,false>,  cudaFuncAttributeMaxDynamicSharedMemorySize, GEMM_SMEM64);
        cudaFuncSetAttribute(mma_gemm1<64,true>,   cudaFuncAttributeMaxDynamicSharedMemorySize, GEMM_SMEM64);
        cudaFuncSetAttribute(mma_gemm2, cudaFuncAttributeMaxDynamicSharedMemorySize, GEMM_SMEM128);
        cudaFuncSetAttribute(attn_tc, cudaFuncAttributeMaxDynamicSharedMemorySize, ATTN_SMEM);
        attr_done = true;
    }

    const size_t S = (size_t)R_TOTAL * 128;  // 2M floats per slot
    float* attnA = pool + 0 * S;
    float* h1    = pool + 1 * S;
    float* Va    = pool + 3 * S;
    bf16* qkvA_h = (bf16*)(pool + 4 * S);    // R x 384 (slots 4-5)
    bf16* qkvA_l = (bf16*)(pool + 6 * S);    // slots 6-7
    bf16* sXh    = (bf16*)(pool + 8 * S);
    bf16* sXl    = (bf16*)(pool + 9 * S);
    bf16* ffh    = (bf16*)(pool + 10 * S);   // R x 512 (slots 10-11)
    bf16* ffl    = (bf16*)(pool + 12 * S);   // slots 12-13
    bf16* kqh    = (bf16*)(pool + 14 * S);
    bf16* kql    = (bf16*)(pool + 15 * S);
    bf16* kq2h   = (bf16*)(pool + 16 * S);   // R x 256
    bf16* kq2l   = (bf16*)(pool + 17 * S);
    bf16* v2h    = (bf16*)(pool + 18 * S);
    bf16* v2l    = (bf16*)(pool + 19 * S);
    bf16* at2h   = (bf16*)(pool + 20 * S);
    bf16* at2l   = (bf16*)(pool + 21 * S);
    bf16* vAh    = (bf16*)(pool + 22 * S);
    bf16* vAl    = (bf16*)(pool + 23 * S);
    float* Wc    = pool + 24 * S;            // 512x32 fp32
    float* bc    = Wc + 512 * 32;
    float* qkvbA = bc + 64;                  // 384
    float* kqb2  = qkvbA + 384;              // 256
    bf16* wArena = (bf16*)(pool + 25 * S);
    bf16* wH = wArena;
    bf16* wL = wArena + PW_TOTAL;
    bf16* qkvW_h = wH + 0;       bf16* qkvW_l = wL + 0;
    bf16* kqW_h  = wH + 49152;   bf16* kqW_l  = wL + 49152;
    bf16* bWv_h  = wH + 65536;   bf16* bWv_l  = wL + 65536;
    bf16* af1_h  = wH + 81920;   bf16* af1_l  = wL + 81920;
    bf16* af2_h  = wH + 147456;  bf16* af2_l  = wL + 147456;
    bf16* bf1_h  = wH + 212992;  bf16* bf1_l  = wL + 212992;
    bf16* wc_h   = wH + 278528;  bf16* wc_l   = wL + 278528;

    // ---- weight prep: 2 launches ----
    smallprep_k<<<(512*32 + 32 + 640 + 255) / 256, 256>>>(
        B_f2W, out_W, B_f2b, out_b, A_bk, A_bq, A_bv, B_bk, B_bq,
        Wc, bc, qkvbA, kqb2);
    Prep10 p10;
    p10.s[0] = A_Wk; p10.s[1] = A_Wq; p10.s[2] = A_Wv;
    p10.s[3] = B_Wk; p10.s[4] = B_Wq; p10.s[5] = B_Wv;
    p10.s[6] = A_f1W; p10.s[7] = A_f2W; p10.s[8] = B_f1W; p10.s[9] = Wc;
    prepw_k<<<(PW_TOTAL + 255) / 256, 256>>>(p10, wH, wL);

    dim3 attnGrid(T_SEQ / 64, 8 * NHEAD);  // (32, 32)

    auto J = [](const bf16* Ah, const bf16* Al, const bf16* Bh, const bf16* Bl,
                const float* bias, int Nvalid, float* Cf, int f_lo, int fStride,
                bf16* Ch, bf16* Cl, int cStride, int K, int act, int gridX,
                const float* lnRes = nullptr, const float* lnG = nullptr,
                const float* lnB = nullptr) {
        GemmJob j;
        j.Ah = Ah; j.Al = Al; j.Bh = Bh; j.Bl = Bl; j.bias = bias; j.Nvalid = Nvalid;
        j.Cf = Cf; j.f_lo = f_lo; j.fStride = fStride;
        j.Ch = Ch; j.Cl = Cl; j.cStride = cStride; j.K = K; j.act = act; j.gridX = gridX;
        j.lnRes = lnRes; j.lnG = lnG; j.lnB = lnB;
        return j;
    };

    // ---- Layer A (+ layer-B K/Q merged into the QKV launch) ----
    splitcat_k<<<(R_TOTAL*32+255)/256, 256>>>(kq, v_in, sXh, sXl, kqh, kql);
    {
        GemmJob j0 = J(sXh, sXl, qkvW_h, qkvW_l, qkvbA, 384, Va, 256, 128,
                       qkvA_h, qkvA_l, 384, 128, 0, 3);
        GemmJob j1 = J(kqh, kql, kqW_h, kqW_l, kqb2, 256, nullptr, 0, 0,
                       kq2h, kq2l, 256, 64, 0, 2);
        mma_gemm2<<<dim3(3, 256), 256, GEMM_SMEM128>>>(j0, j1, 128);
    }
    attn_tc<<<attnGrid, 128, ATTN_SMEM>>>(qkvA_h + 128, qkvA_l + 128, 384,
                               qkvA_h, qkvA_l, 384,
                               qkvA_h + 256, qkvA_l + 256, 384,
                               attnA, nullptr, nullptr, 128, 0);
    add_ln_k<<<R_TOTAL, 128>>>(Va, attnA, A_n1g, A_n1b, h1, sXh, sXl);
    mma_gemm1<128,false><<<dim3(4, 128), 256, GEMM_SMEM128>>>(
        J(sXh, sXl, af1_h, af1_l, A_f1b, 512, nullptr, 0, 0, ffh, ffl, 512, 128, 1, 4));
    // FF2A with fused residual+LN2 -> vAh/vAl
    mma_gemm1<64,true><<<dim3(1, 256), 256, GEMM_SMEM64>>>(
        J(ffh, ffl, af2_h, af2_l, A_f2b, 128, nullptr, 0, 0, vAh, vAl, 128, 512, 0, 1,
          h1, A_n2g, A_n2b));

    // ---- Layer B ----
    mma_gemm1<64,false><<<dim3(1, 256), 256, GEMM_SMEM64>>>(
        J(vAh, vAl, bWv_h, bWv_l, B_bv, 128, nullptr, 0, 0, v2h, v2l, 128, 128, 0, 1));
    attn_tc<<<attnGrid, 128, ATTN_SMEM>>>(kq2h + 128, kq2l + 128, 256,
                               kq2h, kq2l, 256,
                               v2h, v2l, 128,
                               nullptr, at2h, at2l, 128, 1);
    mma_gemm1<128,false><<<dim3(4, 128), 256, GEMM_SMEM128>>>(
        J(at2h, at2l, bf1_h, bf1_l, B_f1b, 512, nullptr, 0, 0, ffh, ffl, 512, 128, 1, 4));
    mma_gemm1<64,false><<<dim3(1, 256), 256, GEMM_SMEM64>>>(
        J(ffh, ffl, wc_h, wc_l, bc, 32, out, 0, 32, nullptr, nullptr, 0, 512, 0, 1));
}

// round 13
// speedup vs baseline: 1.2119x; 1.0468x over previous
#include <cuda_runtime.h>
#include <cuda_bf16.h>
#include <math.h>
#include <stdint.h>

// ---------------------------------------------------------------------------
// Model_19104014532987: 2-layer transformer
// B=8 T=2048 DKQ=64 DV=64 EKQ=EV=128 H=4 dh=32 FF=512 OUT=32, R=16384
// mma.sync bf16 (HMMA), bf16x3 split precision, cp.async pipelines.
// Multi-job flat-grid GEMM launches, LN2 fused into FF2A, stream-overlapped prep.
// ---------------------------------------------------------------------------

#define R_TOTAL 16384
#define T_SEQ   2048
#define EMB     128
#define NHEAD   4
#define LOG2E   1.4426950408889634f

typedef __nv_bfloat16 bf16;

// Scratch pool: 56M floats (224 MB), static device allocation (allowed).
static __device__ __align__(256) float g_scratch[56ull * 1024 * 1024];

__device__ __forceinline__ float gelu_exact(float x) {
    return 0.5f * x * (1.0f + erff(x * 0.70710678118654752440f));
}
__device__ __forceinline__ float ex2(float x) {
    float y; asm("ex2.approx.ftz.f32 %0, %1;" : "=f"(y) : "f"(x)); return y;
}
__device__ __forceinline__ uint32_t smem_u32(const void* p) {
    uint32_t a;
    asm("{ .reg .u64 t; cvta.to.shared.u64 t, %1; cvt.u32.u64 %0, t; }" : "=r"(a) : "l"(p));
    return a;
}

#define LDMX4(r0, r1, r2, r3, addr) \
    asm volatile("ldmatrix.sync.aligned.m8n8.x4.shared.b16 {%0,%1,%2,%3}, [%4];" \
        : "=r"(r0), "=r"(r1), "=r"(r2), "=r"(r3) : "r"(addr))
#define LDMX4T(r0, r1, r2, r3, addr) \
    asm volatile("ldmatrix.sync.aligned.m8n8.x4.trans.shared.b16 {%0,%1,%2,%3}, [%4];" \
        : "=r"(r0), "=r"(r1), "=r"(r2), "=r"(r3) : "r"(addr))
#define MMA16816(d, a, b0, b1) \
    asm volatile("mma.sync.aligned.m16n8k16.row.col.f32.bf16.bf16.f32 " \
        "{%0,%1,%2,%3}, {%4,%5,%6,%7}, {%8,%9}, {%0,%1,%2,%3};" \
        : "+f"((d)[0]), "+f"((d)[1]), "+f"((d)[2]), "+f"((d)[3]) \
        : "r"((a)[0]), "r"((a)[1]), "r"((a)[2]), "r"((a)[3]), "r"(b0), "r"(b1))

#define CP_ASYNC16(saddr, gptr) \
    asm volatile("cp.async.cg.shared.global [%0], [%1], 16;" :: "r"(saddr), "l"(gptr))
#define CP_COMMIT() asm volatile("cp.async.commit_group;" ::: "memory")
#define CP_WAIT1()  asm volatile("cp.async.wait_group 1;" ::: "memory")
#define CP_WAIT0()  asm volatile("cp.async.wait_group 0;" ::: "memory")

// truncation-based bf16 hi/lo split of a float pair (lo absorbs the error)
__device__ __forceinline__ void packpair(uint32_t& ph, uint32_t& pl, float x, float y) {
    uint32_t xu = __float_as_uint(x), yu = __float_as_uint(y);
    ph = __byte_perm(xu, yu, 0x7632);
    float lx = x - __uint_as_float(xu & 0xFFFF0000u);
    float ly = y - __uint_as_float(yu & 0xFFFF0000u);
    pl = __byte_perm(__float_as_uint(lx), __float_as_uint(ly), 0x7632);
}

// ---------------------------------------------------------------------------
// activation split: X = [kq | v] -> sX hi/lo; ALSO writes kq split for layer B.
// ---------------------------------------------------------------------------
__global__ void splitcat_k(const float* __restrict__ kq, const float* __restrict__ v,
                           bf16* __restrict__ h, bf16* __restrict__ l,
                           bf16* __restrict__ kqh, bf16* __restrict__ kql) {
    int i = blockIdx.x * 256 + threadIdx.x;
    if (i >= R_TOTAL * 32) return;
    int e = i * 4;
    int r = e >> 7, d = e & 127;
    float4 val = (d < 64)
        ? *reinterpret_cast<const float4*>(&kq[(size_t)r * 64 + d])
        : *reinterpret_cast<const float4*>(&v[(size_t)r * 64 + (d - 64)]);
    uint32_t h01, l01, h23, l23;
    packpair(h01, l01, val.x, val.y);
    packpair(h23, l23, val.z, val.w);
    reinterpret_cast<uint32_t*>(h)[i * 2]     = h01;
    reinterpret_cast<uint32_t*>(h)[i * 2 + 1] = h23;
    reinterpret_cast<uint32_t*>(l)[i * 2]     = l01;
    reinterpret_cast<uint32_t*>(l)[i * 2 + 1] = l23;
    if (d < 64) {
        size_t o = ((size_t)r * 64 + d) >> 1;
        reinterpret_cast<uint32_t*>(kqh)[o]     = h01;
        reinterpret_cast<uint32_t*>(kqh)[o + 1] = h23;
        reinterpret_cast<uint32_t*>(kql)[o]     = l01;
        reinterpret_cast<uint32_t*>(kql)[o + 1] = l23;
    }
}

// ---------------------------------------------------------------------------
// fused weight prep
// ---------------------------------------------------------------------------
__global__ void smallprep_k(const float* __restrict__ f2W, const float* __restrict__ outW,
                            const float* __restrict__ f2b, const float* __restrict__ out_b,
                            const float* __restrict__ A_bk, const float* __restrict__ A_bq,
                            const float* __restrict__ A_bv, const float* __restrict__ B_bk,
                            const float* __restrict__ B_bq,
                            float* __restrict__ Wc, float* __restrict__ bc,
                            float* __restrict__ qkvbA, float* __restrict__ kqb2)
{
    int gid = blockIdx.x * 256 + threadIdx.x;
    if (gid < 512 * 32) {
        int k = gid >> 5, n = gid & 31;
        float s = 0.f;
        for (int j = 0; j < 128; j++) s = fmaf(f2W[k * 128 + j], outW[j * 32 + n], s);
        Wc[gid] = s;
        return;
    }
    int r = gid - 512 * 32;
    if (r < 32) {
        float s = out_b[r];
        for (int j = 0; j < 128; j++) s = fmaf(f2b[j], outW[j * 32 + r], s);
        bc[r] = s;
        return;
    }
    r -= 32;
    if (r < 384) {
        float v = (r < 128) ? A_bk[r] : (r < 256) ? A_bq[r - 128] * LOG2E : A_bv[r - 256];
        qkvbA[r] = v;
        return;
    }
    r -= 384;
    if (r < 256) {
        kqb2[r] = (r < 128) ? B_bk[r] : B_bq[r - 128] * LOG2E;
    }
}

struct Prep10 { const float* s[10]; };
__device__ __constant__ const int  PS_START[10] = {0,16384,32768,49152,57344,65536,81920,147456,212992,278528};
#define PW_TOTAL 344064
__device__ __constant__ const int  PS_KD[10]    = {128,128,128, 64, 64,128,128,512,128,512};
__device__ __constant__ const int  PS_ND[10]    = {128,128,128,128,128,128,512,128,512, 32};
__device__ __constant__ const float PS_SC[10]   = {1.f,LOG2E,1.f,1.f,LOG2E,1.f,1.f,1.f,1.f,1.f};

__global__ void prepw_k(Prep10 srcs, bf16* __restrict__ th, bf16* __restrict__ tl) {
    int gid = blockIdx.x * 256 + threadIdx.x;
    if (gid >= PW_TOTAL) return;
    int s = 0;
#pragma unroll
    for (int i = 1; i < 10; i++) if (gid >= PS_START[i]) s = i;
    int idx = gid - PS_START[s];
    int Kd = PS_KD[s], Nd = PS_ND[s];
    int n = idx / Kd, k = idx - n * Kd;
    float w = (n < Nd) ? srcs.s[s][(size_t)k * Nd + n] * PS_SC[s] : 0.f;
    bf16 h = __float2bfloat16(w);
    th[gid] = h;
    tl[gid] = __float2bfloat16(w - __bfloat162float(h));
}

// ---------------------------------------------------------------------------
// GEMM job descriptor + shared body
// ---------------------------------------------------------------------------
struct GemmJob {
    const bf16 *Ah, *Al, *Bh, *Bl;
    const float* bias;
    int Nvalid;
    float* Cf; int f_lo, fStride;
    bf16 *Ch, *Cl; int cStride;
    int K, act, gridX;
    const float* lnRes; const float* lnG; const float* lnB;  // LNF only
};

#define GEMM_SMEM128 81920
#define GEMM_SMEM64  61440

template<int BM, bool LNF>
__device__ __forceinline__ void gemm_body(const GemmJob& j, int bx, int by,
                                          char* dsm, int tid)
{
    constexpr int A_BUF  = BM * 40;
    constexpr int NWARPN = (BM == 128) ? 2 : 4;
    constexpr int WNT    = 128 / NWARPN;
    constexpr int NJ     = WNT / 16;
    constexpr int NT     = 2 * NJ;

    bf16* smA_h = (bf16*)dsm;
    bf16* smA_l = smA_h + 2 * A_BUF;
    bf16* smB_h = smA_l + 2 * A_BUF;
    bf16* smB_l = smB_h + 2 * 5120;

    const int l = tid & 31, w = tid >> 5;
    const int wm = w / NWARPN, wn = w % NWARPN;
    const int bm = by * BM, bn = bx * 128;
    const int K = j.K;

    float d[2][NT][4];
#pragma unroll
    for (int mt = 0; mt < 2; mt++)
#pragma unroll
        for (int nt = 0; nt < NT; nt++)
#pragma unroll
            for (int q = 0; q < 4; q++) d[mt][nt][q] = 0.f;

    const uint32_t aAh = smem_u32(smA_h), aAl = smem_u32(smA_l);
    const uint32_t aBh = smem_u32(smB_h), aBl = smem_u32(smB_l);

    const int a_row = wm * 32 + (l & 7) + ((l >> 3) & 1) * 8;
    const int a_kof = (l >> 4) * 8;
    const int b_row = wn * WNT + (l >> 4) * 8 + (l & 7);
    const int b_kof = ((l >> 3) & 1) * 8;

    auto issue_chunk = [&](int kcElem, int buf) {
#pragma unroll
        for (int i = tid; i < BM * 4; i += 256) {
            int row = i >> 2, ch = i & 3;
            size_t ga = (size_t)(bm + row) * K + kcElem + ch * 8;
            int sa = buf * A_BUF + row * 40 + ch * 8;
            CP_ASYNC16(smem_u32(smA_h + sa), j.Ah + ga);
            CP_ASYNC16(smem_u32(smA_l + sa), j.Al + ga);
        }
#pragma unroll
        for (int i = tid; i < 512; i += 256) {
            int row = i >> 2, ch = i & 3;
            size_t gb = (size_t)(bn + row) * K + kcElem + ch * 8;
            int sb = buf * 5120 + row * 40 + ch * 8;
            CP_ASYNC16(smem_u32(smB_h + sb), j.Bh + gb);
            CP_ASYNC16(smem_u32(smB_l + sb), j.Bl + gb);
        }
    };

    const int nch = K >> 5;
    issue_chunk(0, 0);
    CP_COMMIT();

    for (int kc = 0; kc < nch; kc++) {
        const int buf = kc & 1;
        if (kc + 1 < nch) { issue_chunk((kc + 1) << 5, buf ^ 1); CP_COMMIT(); CP_WAIT1(); }
        else              { CP_WAIT0(); }
        __syncthreads();

        const uint32_t bufA = (uint32_t)buf * A_BUF * 2;
        const uint32_t bufB = (uint32_t)buf * 5120 * 2;
#pragma unroll
        for (int ks = 0; ks < 32; ks += 16) {
            uint32_t ah[2][4], al2[2][4];
#pragma unroll
            for (int mt = 0; mt < 2; mt++) {
                uint32_t off = bufA + (uint32_t)(((a_row + mt * 16) * 40 + a_kof + ks) * 2);
                LDMX4(ah[mt][0], ah[mt][1], ah[mt][2], ah[mt][3], aAh + off);
                LDMX4(al2[mt][0], al2[mt][1], al2[mt][2], al2[mt][3], aAl + off);
            }
#pragma unroll
            for (int jj = 0; jj < NJ; jj++) {
                uint32_t boff = bufB + (uint32_t)(((b_row + jj * 16) * 40 + b_kof + ks) * 2);
                uint32_t bh[4], bl2[4];
                LDMX4(bh[0], bh[1], bh[2], bh[3], aBh + boff);
                LDMX4(bl2[0], bl2[1], bl2[2], bl2[3], aBl + boff);
#pragma unroll
                for (int mt = 0; mt < 2; mt++) {
                    MMA16816(d[mt][2 * jj],     ah[mt],  bh[0],  bh[1]);
                    MMA16816(d[mt][2 * jj],     al2[mt], bh[0],  bh[1]);
                    MMA16816(d[mt][2 * jj],     ah[mt],  bl2[0], bl2[1]);
                    MMA16816(d[mt][2 * jj + 1], ah[mt],  bh[2],  bh[3]);
                    MMA16816(d[mt][2 * jj + 1], al2[mt], bh[2],  bh[3]);
                    MMA16816(d[mt][2 * jj + 1], ah[mt],  bl2[2], bl2[3]);
                }
            }
        }
        __syncthreads();
    }

    if constexpr (LNF) {
        // fused residual + LayerNorm epilogue (BM=64, full 128-col rows per CTA)
        float* xs = (float*)dsm;   // [64][132] fp32 staging
#pragma unroll
        for (int mt = 0; mt < 2; mt++) {
            int rl = wm * 32 + mt * 16 + (l >> 2);
#pragma unroll
            for (int nt = 0; nt < NT; nt++) {
                int c = wn * WNT + nt * 8 + (l & 3) * 2;
                float2 res0 = *reinterpret_cast<const float2*>(&j.lnRes[(size_t)(bm + rl) * 128 + c]);
                float2 res1 = *reinterpret_cast<const float2*>(&j.lnRes[(size_t)(bm + rl + 8) * 128 + c]);
                float b0 = j.bias[c], b1 = j.bias[c + 1];
                xs[rl * 132 + c]           = d[mt][nt][0] + b0 + res0.x;
                xs[rl * 132 + c + 1]       = d[mt][nt][1] + b1 + res0.y;
                xs[(rl + 8) * 132 + c]     = d[mt][nt][2] + b0 + res1.x;
                xs[(rl + 8) * 132 + c + 1] = d[mt][nt][3] + b1 + res1.y;
            }
        }
        __syncthreads();
        int row = tid >> 2, part = tid & 3;
        const float* xr = xs + row * 132 + part * 32;
        float sum = 0.f;
#pragma unroll
        for (int i = 0; i < 32; i++) sum += xr[i];
        sum += __shfl_xor_sync(0xffffffffu, sum, 1);
        sum += __shfl_xor_sync(0xffffffffu, sum, 2);
        float mean = sum * (1.f / 128.f);
        float s2 = 0.f;
#pragma unroll
        for (int i = 0; i < 32; i++) { float dl = xr[i] - mean; s2 += dl * dl; }
        s2 += __shfl_xor_sync(0xffffffffu, s2, 1);
        s2 += __shfl_xor_sync(0xffffffffu, s2, 2);
        float rstd = rsqrtf(s2 * (1.f / 128.f) + 1e-5f);
        size_t orow = (size_t)(bm + row) * 128 + part * 32;
#pragma unroll
        for (int i = 0; i < 32; i += 2) {
            int c = part * 32 + i;
            float y0 = (xr[i] - mean) * rstd * j.lnG[c] + j.lnB[c];
            float y1 = (xr[i + 1] - mean) * rstd * j.lnG[c + 1] + j.lnB[c + 1];
            uint32_t hh, ll;
            packpair(hh, ll, y0, y1);
            *reinterpret_cast<uint32_t*>(&j.Ch[orow + i]) = hh;
            *reinterpret_cast<uint32_t*>(&j.Cl[orow + i]) = ll;
        }
    } else {
#pragma unroll
        for (int mt = 0; mt < 2; mt++) {
            int r0 = bm + wm * 32 + mt * 16 + (l >> 2);
#pragma unroll
            for (int nt = 0; nt < NT; nt++) {
                int c = bn + wn * WNT + nt * 8 + (l & 3) * 2;
                if (c >= j.Nvalid) continue;
                float b0 = j.bias[c], b1 = j.bias[c + 1];
                float2 v0, v1;
                v0.x = d[mt][nt][0] + b0; v0.y = d[mt][nt][1] + b1;
                v1.x = d[mt][nt][2] + b0; v1.y = d[mt][nt][3] + b1;
                if (j.act) {
                    v0.x = gelu_exact(v0.x); v0.y = gelu_exact(v0.y);
                    v1.x = gelu_exact(v1.x); v1.y = gelu_exact(v1.y);
                }
                if (j.Cf && c >= j.f_lo) {
                    *reinterpret_cast<float2*>(&j.Cf[(size_t)r0 * j.fStride + (c - j.f_lo)]) = v0;
                    *reinterpret_cast<float2*>(&j.Cf[(size_t)(r0 + 8) * j.fStride + (c - j.f_lo)]) = v1;
                }
                if (j.Ch) {
                    uint32_t h0, l0p, h1v, l1p;
                    packpair(h0, l0p, v0.x, v0.y);
                    packpair(h1v, l1p, v1.x, v1.y);
                    *reinterpret_cast<uint32_t*>(&j.Ch[(size_t)r0 * j.cStride + c]) = h0;
                    *reinterpret_cast<uint32_t*>(&j.Cl[(size_t)r0 * j.cStride + c]) = l0p;
                    *reinterpret_cast<uint32_t*>(&j.Ch[(size_t)(r0 + 8) * j.cStride + c]) = h1v;
                    *reinterpret_cast<uint32_t*>(&j.Cl[(size_t)(r0 + 8) * j.cStride + c]) = l1p;
                }
            }
        }
    }
}

template<int BM, bool LNF>
__global__ __launch_bounds__(256, 2) void mma_gemm1(GemmJob j) {
    extern __shared__ __align__(16) char dsm[];
    gemm_body<BM, LNF>(j, blockIdx.x, blockIdx.y, dsm, threadIdx.x);
}

// two independent jobs in one FLAT launch (both BM=128); linear CTA id.
__global__ __launch_bounds__(256, 2) void mma_gemm2(GemmJob j0, GemmJob j1, int n0) {
    extern __shared__ __align__(16) char dsm[];
    int id = blockIdx.x;
    const GemmJob& j = (id < n0) ? j0 : j1;
    if (id >= n0) id -= n0;
    int bx = id % j.gridX;
    int by = id / j.gridX;
    gemm_body<128, false>(j, bx, by, dsm, threadIdx.x);
}

// ---------------------------------------------------------------------------
// attn_tc: tensor-core flash attention, 64q x 64k tiles, dh=32,
// cp.async double-buffered K/V; Q staging aliased into KV buf1 (smem 40KB).
// 128 threads = 4 warps x 16 q rows; forced 5 CTAs/SM.
// mode 0: j <= i.  mode 1: j < i OR (i==0 && j==0).
// ---------------------------------------------------------------------------
#define ATTN_SMEM 40960
__global__ __launch_bounds__(128, 5) void attn_tc(
    const bf16* __restrict__ Qh, const bf16* __restrict__ Ql, int qStride,
    const bf16* __restrict__ Kh, const bf16* __restrict__ Kl, int kStride,
    const bf16* __restrict__ Vh, const bf16* __restrict__ Vl, int vStride,
    float* __restrict__ Of, bf16* __restrict__ Oh, bf16* __restrict__ Ol, int oStride,
    int mode)
{
    extern __shared__ __align__(16) char dsm[];
    bf16* dsmb = (bf16*)dsm;

    const int tid = threadIdx.x, l = tid & 31, w = tid >> 5;
    const int bh = blockIdx.y;
    const int hc = (bh & 3) * 32;
    const int bb = bh >> 2;
    const size_t baseQ = (size_t)bb * T_SEQ * qStride + hc;
    const size_t baseK = (size_t)bb * T_SEQ * kStride + hc;
    const size_t baseV = (size_t)bb * T_SEQ * vStride + hc;
    const size_t baseO = (size_t)bb * T_SEQ * oStride + hc;
    const int q0 = (gridDim.x - 1 - blockIdx.x) * 64;

    const uint32_t aKV = smem_u32(dsmb);

    auto issue_kv = [&](int j0, int buf) {
#pragma unroll
        for (int i = tid; i < 256; i += 128) {
            int row = i >> 2, ch = i & 3;
            size_t gk = baseK + (size_t)(j0 + row) * kStride + ch * 8;
            size_t gv = baseV + (size_t)(j0 + row) * vStride + ch * 8;
            uint32_t sa = aKV + (uint32_t)(buf * 10240 + row * 40 + ch * 8) * 2;
            CP_ASYNC16(sa,          Kh + gk);
            CP_ASYNC16(sa + 5120,   Kl + gk);
            CP_ASYNC16(sa + 10240,  Vh + gv);
            CP_ASYNC16(sa + 15360,  Vl + gv);
        }
    };

    issue_kv(0, 0);
    CP_COMMIT();

    bf16* sQh = dsmb + 10240;
    bf16* sQl = dsmb + 12800;
    for (int i = tid; i < 256; i += 128) {
        int row = i >> 2, ch = i & 3;
        size_t g = baseQ + (size_t)(q0 + row) * qStride + ch * 8;
        *reinterpret_cast<uint4*>(&sQh[row * 40 + ch * 8]) = *reinterpret_cast<const uint4*>(&Qh[g]);
        *reinterpret_cast<uint4*>(&sQl[row * 40 + ch * 8]) = *reinterpret_cast<const uint4*>(&Ql[g]);
    }
    __syncthreads();

    uint32_t qh[2][4], ql[2][4];
    const int a_row = w * 16 + (l & 7) + ((l >> 3) & 1) * 8;
    const int a_col = (l >> 4) * 8;
    {
        const uint32_t aQh = smem_u32(sQh), aQl = smem_u32(sQl);
#pragma unroll
        for (int ks = 0; ks < 2; ks++) {
            uint32_t off = (uint32_t)((a_row * 40 + a_col + ks * 16) * 2);
            LDMX4(qh[ks][0], qh[ks][1], qh[ks][2], qh[ks][3], aQh + off);
            LDMX4(ql[ks][0], ql[ks][1], ql[ks][2], ql[ks][3], aQl + off);
        }
    }
    __syncthreads();

    const float NEG = -1e30f;
    const int r0 = q0 + w * 16 + (l >> 2);
    const int r1 = r0 + 8;
    float m0 = NEG, m1 = NEG, lac0 = 0.f, lac1 = 0.f;
    float o[4][4];
#pragma unroll
    for (int n = 0; n < 4; n++)
#pragma unroll
        for (int q = 0; q < 4; q++) o[n][q] = 0.f;

    const int b_row_base = (l >> 4) * 8 + (l & 7);
    const int b_kof = ((l >> 3) & 1) * 8;
    const int ntiles = (q0 >> 6) + 1;

    for (int jt = 0; jt < ntiles; jt++) {
        const int j0 = jt * 64;
        const int buf = jt & 1;
        if (jt + 1 < ntiles) { issue_kv(j0 + 64, buf ^ 1); CP_COMMIT(); CP_WAIT1(); }
        else                 { CP_WAIT0(); }
        __syncthreads();
        const uint32_t bufB = (uint32_t)buf * 20480;

        float s[8][4];
#pragma unroll
        for (int nt = 0; nt < 8; nt++)
#pragma unroll
            for (int q = 0; q < 4; q++) s[nt][q] = 0.f;

#pragma unroll
        for (int ks = 0; ks < 2; ks++) {
#pragma unroll
            for (int jp = 0; jp < 4; jp++) {
                uint32_t off = aKV + bufB + (uint32_t)(((jp * 16 + b_row_base) * 40 + b_kof + ks * 16) * 2);
                uint32_t kb[4], kbl[4];
                LDMX4(kb[0], kb[1], kb[2], kb[3], off);
                LDMX4(kbl[0], kbl[1], kbl[2], kbl[3], off + 5120);
                MMA16816(s[2 * jp],     qh[ks], kb[0],  kb[1]);
                MMA16816(s[2 * jp],     ql[ks], kb[0],  kb[1]);
                MMA16816(s[2 * jp],     qh[ks], kbl[0], kbl[1]);
                MMA16816(s[2 * jp + 1], qh[ks], kb[2],  kb[3]);
                MMA16816(s[2 * jp + 1], ql[ks], kb[2],  kb[3]);
                MMA16816(s[2 * jp + 1], qh[ks], kbl[2], kbl[3]);
            }
        }

        if (j0 >= q0) {
#pragma unroll
            for (int nt = 0; nt < 8; nt++) {
                int cb = j0 + nt * 8 + (l & 3) * 2;
                if (mode == 0) {
                    if (cb     > r0) s[nt][0] = NEG;
                    if (cb + 1 > r0) s[nt][1] = NEG;
                    if (cb     > r1) s[nt][2] = NEG;
                    if (cb + 1 > r1) s[nt][3] = NEG;
                } else {
                    if (!(cb     < r0 || (r0 == 0 && cb == 0))) s[nt][0] = NEG;
                    if (!(cb + 1 < r0))                          s[nt][1] = NEG;
                    if (!(cb     < r1)) s[nt][2] = NEG;
                    if (!(cb + 1 < r1)) s[nt][3] = NEG;
                }
            }
        }

        float ml0 = NEG, ml1 = NEG;
#pragma unroll
        for (int nt = 0; nt < 8; nt++) {
            ml0 = fmaxf(ml0, fmaxf(s[nt][0], s[nt][1]));
            ml1 = fmaxf(ml1, fmaxf(s[nt][2], s[nt][3]));
        }
        ml0 = fmaxf(ml0, __shfl_xor_sync(0xffffffffu, ml0, 1));
        ml0 = fmaxf(ml0, __shfl_xor_sync(0xffffffffu, ml0, 2));
        ml1 = fmaxf(ml1, __shfl_xor_sync(0xffffffffu, ml1, 1));
        ml1 = fmaxf(ml1, __shfl_xor_sync(0xffffffffu, ml1, 2));
        float mn0 = fmaxf(m0, ml0), mn1 = fmaxf(m1, ml1);
        float sc0 = ex2(m0 - mn0), sc1 = ex2(m1 - mn1);

        uint32_t pah[4][4], pal[4][4];
        float ps0 = 0.f, ps1 = 0.f;
#pragma unroll
        for (int pt = 0; pt < 4; pt++) {
#pragma unroll
            for (int half = 0; half < 2; half++) {
                int nt = 2 * pt + half;
                float p0 = ex2(s[nt][0] - mn0), p1 = ex2(s[nt][1] - mn0);
                float p2 = ex2(s[nt][2] - mn1), p3 = ex2(s[nt][3] - mn1);
                ps0 += p0 + p1; ps1 += p2 + p3;
                packpair(pah[pt][2 * half],     pal[pt][2 * half],     p0, p1);
                packpair(pah[pt][2 * half + 1], pal[pt][2 * half + 1], p2, p3);
            }
        }
        lac0 = lac0 * sc0 + ps0;
        lac1 = lac1 * sc1 + ps1;
#pragma unroll
        for (int n = 0; n < 4; n++) {
            o[n][0] *= sc0; o[n][1] *= sc0; o[n][2] *= sc1; o[n][3] *= sc1;
        }

#pragma unroll
        for (int pt = 0; pt < 4; pt++) {
#pragma unroll
            for (int np = 0; np < 2; np++) {
                uint32_t off = aKV + bufB + 10240u
                             + (uint32_t)(((pt * 16 + (l & 15)) * 40 + np * 16 + (l >> 4) * 8) * 2);
                uint32_t vb[4], vbl[4];
                LDMX4T(vb[0], vb[1], vb[2], vb[3], off);
                LDMX4T(vbl[0], vbl[1], vbl[2], vbl[3], off + 5120);
                MMA16816(o[2 * np],     pah[pt], vb[0],  vb[1]);
                MMA16816(o[2 * np],     pal[pt], vb[0],  vb[1]);
                MMA16816(o[2 * np],     pah[pt], vbl[0], vbl[1]);
                MMA16816(o[2 * np + 1], pah[pt], vb[2],  vb[3]);
                MMA16816(o[2 * np + 1], pal[pt], vb[2],  vb[3]);
                MMA16816(o[2 * np + 1], pah[pt], vbl[2], vbl[3]);
            }
        }
        m0 = mn0; m1 = mn1;
        __syncthreads();
    }

    lac0 += __shfl_xor_sync(0xffffffffu, lac0, 1);
    lac0 += __shfl_xor_sync(0xffffffffu, lac0, 2);
    lac1 += __shfl_xor_sync(0xffffffffu, lac1, 1);
    lac1 += __shfl_xor_sync(0xffffffffu, lac1, 2);
    float inv0 = 1.f / lac0, inv1 = 1.f / lac1;

#pragma unroll
    for (int nt = 0; nt < 4; nt++) {
        int col = nt * 8 + (l & 3) * 2;
        float v00 = o[nt][0] * inv0, v01 = o[nt][1] * inv0;
        float v10 = o[nt][2] * inv1, v11 = o[nt][3] * inv1;
        if (Of) {
            float2 a; a.x = v00; a.y = v01;
            float2 b; b.x = v10; b.y = v11;
            *reinterpret_cast<float2*>(&Of[baseO + (size_t)r0 * oStride + col]) = a;
            *reinterpret_cast<float2*>(&Of[baseO + (size_t)r1 * oStride + col]) = b;
        }
        if (Oh) {
            uint32_t h0, l0p, h1v, l1p;
            packpair(h0, l0p, v00, v01);
            packpair(h1v, l1p, v10, v11);
            *reinterpret_cast<uint32_t*>(&Oh[baseO + (size_t)r0 * oStride + col]) = h0;
            *reinterpret_cast<uint32_t*>(&Ol[baseO + (size_t)r0 * oStride + col]) = l0p;
            *reinterpret_cast<uint32_t*>(&Oh[baseO + (size_t)r1 * oStride + col]) = h1v;
            *reinterpret_cast<uint32_t*>(&Ol[baseO + (size_t)r1 * oStride + col]) = l1p;
        }
    }
}

// ---------------------------------------------------------------------------
// out = LayerNorm(A + B) * gamma + beta; fp32 out + bf16 hi/lo out
// ---------------------------------------------------------------------------
__global__ void add_ln_k(const float* __restrict__ A, const float* __restrict__ Bv,
                         const float* __restrict__ gam, const float* __restrict__ bet,
                         float* __restrict__ outf, bf16* __restrict__ outh,
                         bf16* __restrict__ outl)
{
    int row = blockIdx.x;
    int d = threadIdx.x;  // 128
    float x = A[(size_t)row * 128 + d] + Bv[(size_t)row * 128 + d];

    __shared__ float ws[4], ws2[4];
    float v = x;
#pragma unroll
    for (int off = 16; off; off >>= 1) v += __shfl_xor_sync(0xffffffffu, v, off);
    if ((d & 31) == 0) ws[d >> 5] = v;
    __syncthreads();
    float mean = (ws[0] + ws[1] + ws[2] + ws[3]) * (1.f / 128.f);
    float dif = x - mean;
    float v2 = dif * dif;
#pragma unroll
    for (int off = 16; off; off >>= 1) v2 += __shfl_xor_sync(0xffffffffu, v2, off);
    if ((d & 31) == 0) ws2[d >> 5] = v2;
    __syncthreads();
    float var = (ws2[0] + ws2[1] + ws2[2] + ws2[3]) * (1.f / 128.f);
    float y = dif * rsqrtf(var + 1e-5f) * gam[d] + bet[d];
    if (outf) outf[(size_t)row * 128 + d] = y;
    if (outh) {
        bf16 h = __float2bfloat16(y);
        outh[(size_t)row * 128 + d] = h;
        outl[(size_t)row * 128 + d] = __float2bfloat16(y - __bfloat162float(h));
    }
}

// ---------------------------------------------------------------------------
extern "C" void kernel_launch(void* const* d_in, const int* in_sizes, int n_in,
                              void* d_out, int out_size)
{
    const float* kq    = (const float*)d_in[0];
    const float* v_in  = (const float*)d_in[1];
    const float* A_Wk  = (const float*)d_in[2];
    const float* A_bk  = (const float*)d_in[3];
    const float* A_Wq  = (const float*)d_in[4];
    const float* A_bq  = (const float*)d_in[5];
    const float* A_Wv  = (const float*)d_in[6];
    const float* A_bv  = (const float*)d_in[7];
    const float* A_f1W = (const float*)d_in[8];
    const float* A_f1b = (const float*)d_in[9];
    const float* A_f2W = (const float*)d_in[10];
    const float* A_f2b = (const float*)d_in[11];
    const float* A_n1g = (const float*)d_in[12];
    const float* A_n1b = (const float*)d_in[13];
    const float* A_n2g = (const float*)d_in[14];
    const float* A_n2b = (const float*)d_in[15];
    const float* B_Wk  = (const float*)d_in[16];
    const float* B_bk  = (const float*)d_in[17];
    const float* B_Wq  = (const float*)d_in[18];
    const float* B_bq  = (const float*)d_in[19];
    const float* B_Wv  = (const float*)d_in[20];
    const float* B_bv  = (const float*)d_in[21];
    const float* B_f1W = (const float*)d_in[22];
    const float* B_f1b = (const float*)d_in[23];
    const float* B_f2W = (const float*)d_in[24];
    const float* B_f2b = (const float*)d_in[25];
    const float* out_W = (const float*)d_in[26];
    const float* out_b = (const float*)d_in[27];
    float* out = (float*)d_out;

    float* pool = nullptr;
    cudaGetSymbolAddress((void**)&pool, g_scratch);

    static cudaStream_t s2 = nullptr;
    static cudaEvent_t e1 = nullptr, e2 = nullptr;
    static bool attr_done = false;
    if (!attr_done) {
        cudaFuncSetAttribute(mma_gemm1<128,false>, cudaFuncAttributeMaxDynamicSharedMemorySize, GEMM_SMEM128);
        cudaFuncSetAttribute(mma_gemm1<64,false>,  cudaFuncAttributeMaxDynamicSharedMemorySize, GEMM_SMEM64);
        cudaFuncSetAttribute(mma_gemm1<64,true>,   cudaFuncAttributeMaxDynamicSharedMemorySize, GEMM_SMEM64);
        cudaFuncSetAttribute(mma_gemm2, cudaFuncAttributeMaxDynamicSharedMemorySize, GEMM_SMEM128);
        cudaFuncSetAttribute(attn_tc, cudaFuncAttributeMaxDynamicSharedMemorySize, ATTN_SMEM);
        cudaStreamCreateWithFlags(&s2, cudaStreamNonBlocking);
        cudaEventCreateWithFlags(&e1, cudaEventDisableTiming);
        cudaEventCreateWithFlags(&e2, cudaEventDisableTiming);
        attr_done = true;
    }

    const size_t S = (size_t)R_TOTAL * 128;  // 2M floats per slot
    float* attnA = pool + 0 * S;
    float* h1    = pool + 1 * S;
    float* Va    = pool + 3 * S;
    bf16* qkvA_h = (bf16*)(pool + 4 * S);    // R x 384 (slots 4-5)
    bf16* qkvA_l = (bf16*)(pool + 6 * S);    // slots 6-7
    bf16* sXh    = (bf16*)(pool + 8 * S);
    bf16* sXl    = (bf16*)(pool + 9 * S);
    bf16* ffh    = (bf16*)(pool + 10 * S);   // R x 512 (slots 10-11)
    bf16* ffl    = (bf16*)(pool + 12 * S);   // slots 12-13
    bf16* kqh    = (bf16*)(pool + 14 * S);
    bf16* kql    = (bf16*)(pool + 15 * S);
    bf16* kq2h   = (bf16*)(pool + 16 * S);   // R x 256
    bf16* kq2l   = (bf16*)(pool + 17 * S);
    bf16* v2h    = (bf16*)(pool + 18 * S);
    bf16* v2l    = (bf16*)(pool + 19 * S);
    bf16* at2h   = (bf16*)(pool + 20 * S);
    bf16* at2l   = (bf16*)(pool + 21 * S);
    bf16* vAh    = (bf16*)(pool + 22 * S);
    bf16* vAl    = (bf16*)(pool + 23 * S);
    float* Wc    = pool + 24 * S;            // 512x32 fp32
    float* bc    = Wc + 512 * 32;
    float* qkvbA = bc + 64;                  // 384
    float* kqb2  = qkvbA + 384;              // 256
    bf16* wArena = (bf16*)(pool + 25 * S);
    bf16* wH = wArena;
    bf16* wL = wArena + PW_TOTAL;
    bf16* qkvW_h = wH + 0;       bf16* qkvW_l = wL + 0;
    bf16* kqW_h  = wH + 49152;   bf16* kqW_l  = wL + 49152;
    bf16* bWv_h  = wH + 65536;   bf16* bWv_l  = wL + 65536;
    bf16* af1_h  = wH + 81920;   bf16* af1_l  = wL + 81920;
    bf16* af2_h  = wH + 147456;  bf16* af2_l  = wL + 147456;
    bf16* bf1_h  = wH + 212992;  bf16* bf1_l  = wL + 212992;
    bf16* wc_h   = wH + 278528;  bf16* wc_l   = wL + 278528;

    // ---- prep on side stream (fork) overlapping splitcat (main) ----
    cudaEventRecord(e1, 0);
    cudaStreamWaitEvent(s2, e1, 0);
    smallprep_k<<<(512*32 + 32 + 640 + 255) / 256, 256, 0, s2>>>(
        B_f2W, out_W, B_f2b, out_b, A_bk, A_bq, A_bv, B_bk, B_bq,
        Wc, bc, qkvbA, kqb2);
    Prep10 p10;
    p10.s[0] = A_Wk; p10.s[1] = A_Wq; p10.s[2] = A_Wv;
    p10.s[3] = B_Wk; p10.s[4] = B_Wq; p10.s[5] = B_Wv;
    p10.s[6] = A_f1W; p10.s[7] = A_f2W; p10.s[8] = B_f1W; p10.s[9] = Wc;
    prepw_k<<<(PW_TOTAL + 255) / 256, 256, 0, s2>>>(p10, wH, wL);
    cudaEventRecord(e2, s2);

    splitcat_k<<<(R_TOTAL*32+255)/256, 256>>>(kq, v_in, sXh, sXl, kqh, kql);
    cudaStreamWaitEvent(0, e2, 0);   // join before first GEMM

    dim3 attnGrid(T_SEQ / 64, 8 * NHEAD);  // (32, 32)

    auto J = [](const bf16* Ah, const bf16* Al, const bf16* Bh, const bf16* Bl,
                const float* bias, int Nvalid, float* Cf, int f_lo, int fStride,
                bf16* Ch, bf16* Cl, int cStride, int K, int act, int gridX,
                const float* lnRes = nullptr, const float* lnG = nullptr,
                const float* lnB = nullptr) {
        GemmJob j;
        j.Ah = Ah; j.Al = Al; j.Bh = Bh; j.Bl = Bl; j.bias = bias; j.Nvalid = Nvalid;
        j.Cf = Cf; j.f_lo = f_lo; j.fStride = fStride;
        j.Ch = Ch; j.Cl = Cl; j.cStride = cStride; j.K = K; j.act = act; j.gridX = gridX;
        j.lnRes = lnRes; j.lnG = lnG; j.lnB = lnB;
        return j;
    };

    // ---- Layer A (+ layer-B K/Q merged, flat grid: 384 + 256 = 640 CTAs) ----
    {
        GemmJob j0 = J(sXh, sXl, qkvW_h, qkvW_l, qkvbA, 384, Va, 256, 128,
                       qkvA_h, qkvA_l, 384, 128, 0, 3);
        GemmJob j1 = J(kqh, kql, kqW_h, kqW_l, kqb2, 256, nullptr, 0, 0,
                       kq2h, kq2l, 256, 64, 0, 2);
        mma_gemm2<<<640, 256, GEMM_SMEM128>>>(j0, j1, 384);
    }
    attn_tc<<<attnGrid, 128, ATTN_SMEM>>>(qkvA_h + 128, qkvA_l + 128, 384,
                               qkvA_h, qkvA_l, 384,
                               qkvA_h + 256, qkvA_l + 256, 384,
                               attnA, nullptr, nullptr, 128, 0);
    add_ln_k<<<R_TOTAL, 128>>>(Va, attnA, A_n1g, A_n1b, h1, sXh, sXl);
    mma_gemm1<128,false><<<dim3(4, 128), 256, GEMM_SMEM128>>>(
        J(sXh, sXl, af1_h, af1_l, A_f1b, 512, nullptr, 0, 0, ffh, ffl, 512, 128, 1, 4));
    // FF2A with fused residual+LN2 -> vAh/vAl
    mma_gemm1<64,true><<<dim3(1, 256), 256, GEMM_SMEM64>>>(
        J(ffh, ffl, af2_h, af2_l, A_f2b, 128, nullptr, 0, 0, vAh, vAl, 128, 512, 0, 1,
          h1, A_n2g, A_n2b));

    // ---- Layer B ----
    mma_gemm1<64,false><<<dim3(1, 256), 256, GEMM_SMEM64>>>(
        J(vAh, vAl, bWv_h, bWv_l, B_bv, 128, nullptr, 0, 0, v2h, v2l, 128, 128, 0, 1));
    attn_tc<<<attnGrid, 128, ATTN_SMEM>>>(kq2h + 128, kq2l + 128, 256,
                               kq2h, kq2l, 256,
                               v2h, v2l, 128,
                               nullptr, at2h, at2l, 128, 1);
    mma_gemm1<128,false><<<dim3(4, 128), 256, GEMM_SMEM128>>>(
        J(at2h, at2l, bf1_h, bf1_l, B_f1b, 512, nullptr, 0, 0, ffh, ffl, 512, 128, 1, 4));
    mma_gemm1<64,false><<<dim3(1, 256), 256, GEMM_SMEM64>>>(
        J(ffh, ffl, wc_h, wc_l, bc, 32, out, 0, 32, nullptr, nullptr, 0, 512, 0, 1));
}

// round 14
// speedup vs baseline: 1.2126x; 1.0006x over previous
#include <cuda_runtime.h>
#include <cuda_bf16.h>
#include <math.h>
#include <stdint.h>

// ---------------------------------------------------------------------------
// Model_19104014532987: 2-layer transformer
// B=8 T=2048 DKQ=64 DV=64 EKQ=EV=128 H=4 dh=32 FF=512 OUT=32, R=16384
// mma.sync bf16 (HMMA), bf16x3 split precision, cp.async pipelines
// (2-deep BM=128, 3-deep BM=64). Multi-job flat GEMM launches, fused LN2,
// stream-overlapped prep, batched LN.
// ---------------------------------------------------------------------------

#define R_TOTAL 16384
#define T_SEQ   2048
#define EMB     128
#define NHEAD   4
#define LOG2E   1.4426950408889634f

typedef __nv_bfloat16 bf16;

// Scratch pool: 56M floats (224 MB), static device allocation (allowed).
static __device__ __align__(256) float g_scratch[56ull * 1024 * 1024];

__device__ __forceinline__ float gelu_exact(float x) {
    return 0.5f * x * (1.0f + erff(x * 0.70710678118654752440f));
}
__device__ __forceinline__ float ex2(float x) {
    float y; asm("ex2.approx.ftz.f32 %0, %1;" : "=f"(y) : "f"(x)); return y;
}
__device__ __forceinline__ uint32_t smem_u32(const void* p) {
    uint32_t a;
    asm("{ .reg .u64 t; cvta.to.shared.u64 t, %1; cvt.u32.u64 %0, t; }" : "=r"(a) : "l"(p));
    return a;
}

#define LDMX4(r0, r1, r2, r3, addr) \
    asm volatile("ldmatrix.sync.aligned.m8n8.x4.shared.b16 {%0,%1,%2,%3}, [%4];" \
        : "=r"(r0), "=r"(r1), "=r"(r2), "=r"(r3) : "r"(addr))
#define LDMX4T(r0, r1, r2, r3, addr) \
    asm volatile("ldmatrix.sync.aligned.m8n8.x4.trans.shared.b16 {%0,%1,%2,%3}, [%4];" \
        : "=r"(r0), "=r"(r1), "=r"(r2), "=r"(r3) : "r"(addr))
#define MMA16816(d, a, b0, b1) \
    asm volatile("mma.sync.aligned.m16n8k16.row.col.f32.bf16.bf16.f32 " \
        "{%0,%1,%2,%3}, {%4,%5,%6,%7}, {%8,%9}, {%0,%1,%2,%3};" \
        : "+f"((d)[0]), "+f"((d)[1]), "+f"((d)[2]), "+f"((d)[3]) \
        : "r"((a)[0]), "r"((a)[1]), "r"((a)[2]), "r"((a)[3]), "r"(b0), "r"(b1))

#define CP_ASYNC16(saddr, gptr) \
    asm volatile("cp.async.cg.shared.global [%0], [%1], 16;" :: "r"(saddr), "l"(gptr))
#define CP_COMMIT() asm volatile("cp.async.commit_group;" ::: "memory")
#define CP_WAIT2()  asm volatile("cp.async.wait_group 2;" ::: "memory")
#define CP_WAIT1()  asm volatile("cp.async.wait_group 1;" ::: "memory")
#define CP_WAIT0()  asm volatile("cp.async.wait_group 0;" ::: "memory")

// truncation-based bf16 hi/lo split of a float pair (lo absorbs the error)
__device__ __forceinline__ void packpair(uint32_t& ph, uint32_t& pl, float x, float y) {
    uint32_t xu = __float_as_uint(x), yu = __float_as_uint(y);
    ph = __byte_perm(xu, yu, 0x7632);
    float lx = x - __uint_as_float(xu & 0xFFFF0000u);
    float ly = y - __uint_as_float(yu & 0xFFFF0000u);
    pl = __byte_perm(__float_as_uint(lx), __float_as_uint(ly), 0x7632);
}

// ---------------------------------------------------------------------------
// activation split: X = [kq | v] -> sX hi/lo; ALSO writes kq split for layer B.
// ---------------------------------------------------------------------------
__global__ void splitcat_k(const float* __restrict__ kq, const float* __restrict__ v,
                           bf16* __restrict__ h, bf16* __restrict__ l,
                           bf16* __restrict__ kqh, bf16* __restrict__ kql) {
    int i = blockIdx.x * 256 + threadIdx.x;
    if (i >= R_TOTAL * 32) return;
    int e = i * 4;
    int r = e >> 7, d = e & 127;
    float4 val = (d < 64)
        ? *reinterpret_cast<const float4*>(&kq[(size_t)r * 64 + d])
        : *reinterpret_cast<const float4*>(&v[(size_t)r * 64 + (d - 64)]);
    uint32_t h01, l01, h23, l23;
    packpair(h01, l01, val.x, val.y);
    packpair(h23, l23, val.z, val.w);
    reinterpret_cast<uint32_t*>(h)[i * 2]     = h01;
    reinterpret_cast<uint32_t*>(h)[i * 2 + 1] = h23;
    reinterpret_cast<uint32_t*>(l)[i * 2]     = l01;
    reinterpret_cast<uint32_t*>(l)[i * 2 + 1] = l23;
    if (d < 64) {
        size_t o = ((size_t)r * 64 + d) >> 1;
        reinterpret_cast<uint32_t*>(kqh)[o]     = h01;
        reinterpret_cast<uint32_t*>(kqh)[o + 1] = h23;
        reinterpret_cast<uint32_t*>(kql)[o]     = l01;
        reinterpret_cast<uint32_t*>(kql)[o + 1] = l23;
    }
}

// ---------------------------------------------------------------------------
// fused weight prep
// ---------------------------------------------------------------------------
__global__ void smallprep_k(const float* __restrict__ f2W, const float* __restrict__ outW,
                            const float* __restrict__ f2b, const float* __restrict__ out_b,
                            const float* __restrict__ A_bk, const float* __restrict__ A_bq,
                            const float* __restrict__ A_bv, const float* __restrict__ B_bk,
                            const float* __restrict__ B_bq,
                            float* __restrict__ Wc, float* __restrict__ bc,
                            float* __restrict__ qkvbA, float* __restrict__ kqb2)
{
    int gid = blockIdx.x * 256 + threadIdx.x;
    if (gid < 512 * 32) {
        int k = gid >> 5, n = gid & 31;
        float s = 0.f;
        for (int j = 0; j < 128; j++) s = fmaf(f2W[k * 128 + j], outW[j * 32 + n], s);
        Wc[gid] = s;
        return;
    }
    int r = gid - 512 * 32;
    if (r < 32) {
        float s = out_b[r];
        for (int j = 0; j < 128; j++) s = fmaf(f2b[j], outW[j * 32 + r], s);
        bc[r] = s;
        return;
    }
    r -= 32;
    if (r < 384) {
        float v = (r < 128) ? A_bk[r] : (r < 256) ? A_bq[r - 128] * LOG2E : A_bv[r - 256];
        qkvbA[r] = v;
        return;
    }
    r -= 384;
    if (r < 256) {
        kqb2[r] = (r < 128) ? B_bk[r] : B_bq[r - 128] * LOG2E;
    }
}

struct Prep10 { const float* s[10]; };
__device__ __constant__ const int  PS_START[10] = {0,16384,32768,49152,57344,65536,81920,147456,212992,278528};
#define PW_TOTAL 344064
__device__ __constant__ const int  PS_KD[10]    = {128,128,128, 64, 64,128,128,512,128,512};
__device__ __constant__ const int  PS_ND[10]    = {128,128,128,128,128,128,512,128,512, 32};
__device__ __constant__ const float PS_SC[10]   = {1.f,LOG2E,1.f,1.f,LOG2E,1.f,1.f,1.f,1.f,1.f};

__global__ void prepw_k(Prep10 srcs, bf16* __restrict__ th, bf16* __restrict__ tl) {
    int gid = blockIdx.x * 256 + threadIdx.x;
    if (gid >= PW_TOTAL) return;
    int s = 0;
#pragma unroll
    for (int i = 1; i < 10; i++) if (gid >= PS_START[i]) s = i;
    int idx = gid - PS_START[s];
    int Kd = PS_KD[s], Nd = PS_ND[s];
    int n = idx / Kd, k = idx - n * Kd;
    float w = (n < Nd) ? srcs.s[s][(size_t)k * Nd + n] * PS_SC[s] : 0.f;
    bf16 h = __float2bfloat16(w);
    th[gid] = h;
    tl[gid] = __float2bfloat16(w - __bfloat162float(h));
}

// ---------------------------------------------------------------------------
// GEMM job descriptor + shared body
// ---------------------------------------------------------------------------
struct GemmJob {
    const bf16 *Ah, *Al, *Bh, *Bl;
    const float* bias;
    int Nvalid;
    float* Cf; int f_lo, fStride;
    bf16 *Ch, *Cl; int cStride;
    int K, act, gridX;
    const float* lnRes; const float* lnG; const float* lnB;  // LNF only
};

#define GEMM_SMEM128 81920
#define GEMM_SMEM64  92160   // 3 buffers x 30720B

template<int BM, bool LNF>
__device__ __forceinline__ void gemm_body(const GemmJob& j, int bx, int by,
                                          char* dsm, int tid)
{
    constexpr int A_BUF  = BM * 40;
    constexpr int NBUF   = (BM == 128) ? 2 : 3;
    constexpr int NWARPN = (BM == 128) ? 2 : 4;
    constexpr int WNT    = 128 / NWARPN;
    constexpr int NJ     = WNT / 16;
    constexpr int NT     = 2 * NJ;

    bf16* smA_h = (bf16*)dsm;
    bf16* smA_l = smA_h + NBUF * A_BUF;
    bf16* smB_h = smA_l + NBUF * A_BUF;
    bf16* smB_l = smB_h + NBUF * 5120;

    const int l = tid & 31, w = tid >> 5;
    const int wm = w / NWARPN, wn = w % NWARPN;
    const int bm = by * BM, bn = bx * 128;
    const int K = j.K;

    float d[2][NT][4];
#pragma unroll
    for (int mt = 0; mt < 2; mt++)
#pragma unroll
        for (int nt = 0; nt < NT; nt++)
#pragma unroll
            for (int q = 0; q < 4; q++) d[mt][nt][q] = 0.f;

    const uint32_t aAh = smem_u32(smA_h), aAl = smem_u32(smA_l);
    const uint32_t aBh = smem_u32(smB_h), aBl = smem_u32(smB_l);

    const int a_row = wm * 32 + (l & 7) + ((l >> 3) & 1) * 8;
    const int a_kof = (l >> 4) * 8;
    const int b_row = wn * WNT + (l >> 4) * 8 + (l & 7);
    const int b_kof = ((l >> 3) & 1) * 8;

    auto issue_chunk = [&](int kcElem, int buf) {
#pragma unroll
        for (int i = tid; i < BM * 4; i += 256) {
            int row = i >> 2, ch = i & 3;
            size_t ga = (size_t)(bm + row) * K + kcElem + ch * 8;
            int sa = buf * A_BUF + row * 40 + ch * 8;
            CP_ASYNC16(smem_u32(smA_h + sa), j.Ah + ga);
            CP_ASYNC16(smem_u32(smA_l + sa), j.Al + ga);
        }
#pragma unroll
        for (int i = tid; i < 512; i += 256) {
            int row = i >> 2, ch = i & 3;
            size_t gb = (size_t)(bn + row) * K + kcElem + ch * 8;
            int sb = buf * 5120 + row * 40 + ch * 8;
            CP_ASYNC16(smem_u32(smB_h + sb), j.Bh + gb);
            CP_ASYNC16(smem_u32(smB_l + sb), j.Bl + gb);
        }
    };

    const int nch = K >> 5;
    issue_chunk(0, 0);
    CP_COMMIT();
    if (NBUF == 3 && nch > 1) { issue_chunk(32, 1); CP_COMMIT(); }

    for (int kc = 0; kc < nch; kc++) {
        const int nxt = kc + NBUF - 1;
        if (nxt < nch) { issue_chunk(nxt << 5, nxt % NBUF); CP_COMMIT(); }
        const int rem = nch - 1 - kc;  // groups newer than chunk kc
        if (NBUF == 3) {
            if (rem >= 2) CP_WAIT2(); else if (rem == 1) CP_WAIT1(); else CP_WAIT0();
        } else {
            if (rem >= 1) CP_WAIT1(); else CP_WAIT0();
        }
        __syncthreads();

        const int buf = kc % NBUF;
        const uint32_t bufA = (uint32_t)buf * A_BUF * 2;
        const uint32_t bufB = (uint32_t)buf * 5120 * 2;
#pragma unroll
        for (int ks = 0; ks < 32; ks += 16) {
            uint32_t ah[2][4], al2[2][4];
#pragma unroll
            for (int mt = 0; mt < 2; mt++) {
                uint32_t off = bufA + (uint32_t)(((a_row + mt * 16) * 40 + a_kof + ks) * 2);
                LDMX4(ah[mt][0], ah[mt][1], ah[mt][2], ah[mt][3], aAh + off);
                LDMX4(al2[mt][0], al2[mt][1], al2[mt][2], al2[mt][3], aAl + off);
            }
#pragma unroll
            for (int jj = 0; jj < NJ; jj++) {
                uint32_t boff = bufB + (uint32_t)(((b_row + jj * 16) * 40 + b_kof + ks) * 2);
                uint32_t bh[4], bl2[4];
                LDMX4(bh[0], bh[1], bh[2], bh[3], aBh + boff);
                LDMX4(bl2[0], bl2[1], bl2[2], bl2[3], aBl + boff);
#pragma unroll
                for (int mt = 0; mt < 2; mt++) {
                    MMA16816(d[mt][2 * jj],     ah[mt],  bh[0],  bh[1]);
                    MMA16816(d[mt][2 * jj],     al2[mt], bh[0],  bh[1]);
                    MMA16816(d[mt][2 * jj],     ah[mt],  bl2[0], bl2[1]);
                    MMA16816(d[mt][2 * jj + 1], ah[mt],  bh[2],  bh[3]);
                    MMA16816(d[mt][2 * jj + 1], al2[mt], bh[2],  bh[3]);
                    MMA16816(d[mt][2 * jj + 1], ah[mt],  bl2[2], bl2[3]);
                }
            }
        }
        __syncthreads();
    }

    if constexpr (LNF) {
        // fused residual + LayerNorm epilogue (BM=64, full 128-col rows per CTA)
        float* xs = (float*)dsm;   // [64][132] fp32 staging
#pragma unroll
        for (int mt = 0; mt < 2; mt++) {
            int rl = wm * 32 + mt * 16 + (l >> 2);
#pragma unroll
            for (int nt = 0; nt < NT; nt++) {
                int c = wn * WNT + nt * 8 + (l & 3) * 2;
                float2 res0 = *reinterpret_cast<const float2*>(&j.lnRes[(size_t)(bm + rl) * 128 + c]);
                float2 res1 = *reinterpret_cast<const float2*>(&j.lnRes[(size_t)(bm + rl + 8) * 128 + c]);
                float b0 = j.bias[c], b1 = j.bias[c + 1];
                xs[rl * 132 + c]           = d[mt][nt][0] + b0 + res0.x;
                xs[rl * 132 + c + 1]       = d[mt][nt][1] + b1 + res0.y;
                xs[(rl + 8) * 132 + c]     = d[mt][nt][2] + b0 + res1.x;
                xs[(rl + 8) * 132 + c + 1] = d[mt][nt][3] + b1 + res1.y;
            }
        }
        __syncthreads();
        int row = tid >> 2, part = tid & 3;
        const float* xr = xs + row * 132 + part * 32;
        float sum = 0.f;
#pragma unroll
        for (int i = 0; i < 32; i++) sum += xr[i];
        sum += __shfl_xor_sync(0xffffffffu, sum, 1);
        sum += __shfl_xor_sync(0xffffffffu, sum, 2);
        float mean = sum * (1.f / 128.f);
        float s2 = 0.f;
#pragma unroll
        for (int i = 0; i < 32; i++) { float dl = xr[i] - mean; s2 += dl * dl; }
        s2 += __shfl_xor_sync(0xffffffffu, s2, 1);
        s2 += __shfl_xor_sync(0xffffffffu, s2, 2);
        float rstd = rsqrtf(s2 * (1.f / 128.f) + 1e-5f);
        size_t orow = (size_t)(bm + row) * 128 + part * 32;
#pragma unroll
        for (int i = 0; i < 32; i += 2) {
            int c = part * 32 + i;
            float y0 = (xr[i] - mean) * rstd * j.lnG[c] + j.lnB[c];
            float y1 = (xr[i + 1] - mean) * rstd * j.lnG[c + 1] + j.lnB[c + 1];
            uint32_t hh, ll;
            packpair(hh, ll, y0, y1);
            *reinterpret_cast<uint32_t*>(&j.Ch[orow + i]) = hh;
            *reinterpret_cast<uint32_t*>(&j.Cl[orow + i]) = ll;
        }
    } else {
#pragma unroll
        for (int mt = 0; mt < 2; mt++) {
            int r0 = bm + wm * 32 + mt * 16 + (l >> 2);
#pragma unroll
            for (int nt = 0; nt < NT; nt++) {
                int c = bn + wn * WNT + nt * 8 + (l & 3) * 2;
                if (c >= j.Nvalid) continue;
                float b0 = j.bias[c], b1 = j.bias[c + 1];
                float2 v0, v1;
                v0.x = d[mt][nt][0] + b0; v0.y = d[mt][nt][1] + b1;
                v1.x = d[mt][nt][2] + b0; v1.y = d[mt][nt][3] + b1;
                if (j.act) {
                    v0.x = gelu_exact(v0.x); v0.y = gelu_exact(v0.y);
                    v1.x = gelu_exact(v1.x); v1.y = gelu_exact(v1.y);
                }
                if (j.Cf && c >= j.f_lo) {
                    *reinterpret_cast<float2*>(&j.Cf[(size_t)r0 * j.fStride + (c - j.f_lo)]) = v0;
                    *reinterpret_cast<float2*>(&j.Cf[(size_t)(r0 + 8) * j.fStride + (c - j.f_lo)]) = v1;
                }
                if (j.Ch) {
                    uint32_t h0, l0p, h1v, l1p;
                    packpair(h0, l0p, v0.x, v0.y);
                    packpair(h1v, l1p, v1.x, v1.y);
                    *reinterpret_cast<uint32_t*>(&j.Ch[(size_t)r0 * j.cStride + c]) = h0;
                    *reinterpret_cast<uint32_t*>(&j.Cl[(size_t)r0 * j.cStride + c]) = l0p;
                    *reinterpret_cast<uint32_t*>(&j.Ch[(size_t)(r0 + 8) * j.cStride + c]) = h1v;
                    *reinterpret_cast<uint32_t*>(&j.Cl[(size_t)(r0 + 8) * j.cStride + c]) = l1p;
                }
            }
        }
    }
}

template<int BM, bool LNF>
__global__ __launch_bounds__(256, 2) void mma_gemm1(GemmJob j) {
    extern __shared__ __align__(16) char dsm[];
    gemm_body<BM, LNF>(j, blockIdx.x, blockIdx.y, dsm, threadIdx.x);
}

// two independent jobs in one FLAT launch (both BM=128); linear CTA id.
__global__ __launch_bounds__(256, 2) void mma_gemm2(GemmJob j0, GemmJob j1, int n0) {
    extern __shared__ __align__(16) char dsm[];
    int id = blockIdx.x;
    const GemmJob& j = (id < n0) ? j0 : j1;
    if (id >= n0) id -= n0;
    int bx = id % j.gridX;
    int by = id / j.gridX;
    gemm_body<128, false>(j, bx, by, dsm, threadIdx.x);
}

// ---------------------------------------------------------------------------
// attn_tc: tensor-core flash attention, 64q x 64k tiles, dh=32,
// cp.async double-buffered K/V; Q staging aliased into KV buf1 (smem 40KB).
// 128 threads = 4 warps x 16 q rows; forced 5 CTAs/SM.
// mode 0: j <= i.  mode 1: j < i OR (i==0 && j==0).
// ---------------------------------------------------------------------------
#define ATTN_SMEM 40960
__global__ __launch_bounds__(128, 5) void attn_tc(
    const bf16* __restrict__ Qh, const bf16* __restrict__ Ql, int qStride,
    const bf16* __restrict__ Kh, const bf16* __restrict__ Kl, int kStride,
    const bf16* __restrict__ Vh, const bf16* __restrict__ Vl, int vStride,
    float* __restrict__ Of, bf16* __restrict__ Oh, bf16* __restrict__ Ol, int oStride,
    int mode)
{
    extern __shared__ __align__(16) char dsm[];
    bf16* dsmb = (bf16*)dsm;

    const int tid = threadIdx.x, l = tid & 31, w = tid >> 5;
    const int bh = blockIdx.y;
    const int hc = (bh & 3) * 32;
    const int bb = bh >> 2;
    const size_t baseQ = (size_t)bb * T_SEQ * qStride + hc;
    const size_t baseK = (size_t)bb * T_SEQ * kStride + hc;
    const size_t baseV = (size_t)bb * T_SEQ * vStride + hc;
    const size_t baseO = (size_t)bb * T_SEQ * oStride + hc;
    const int q0 = (gridDim.x - 1 - blockIdx.x) * 64;

    const uint32_t aKV = smem_u32(dsmb);

    auto issue_kv = [&](int j0, int buf) {
#pragma unroll
        for (int i = tid; i < 256; i += 128) {
            int row = i >> 2, ch = i & 3;
            size_t gk = baseK + (size_t)(j0 + row) * kStride + ch * 8;
            size_t gv = baseV + (size_t)(j0 + row) * vStride + ch * 8;
            uint32_t sa = aKV + (uint32_t)(buf * 10240 + row * 40 + ch * 8) * 2;
            CP_ASYNC16(sa,          Kh + gk);
            CP_ASYNC16(sa + 5120,   Kl + gk);
            CP_ASYNC16(sa + 10240,  Vh + gv);
            CP_ASYNC16(sa + 15360,  Vl + gv);
        }
    };

    issue_kv(0, 0);
    CP_COMMIT();

    bf16* sQh = dsmb + 10240;
    bf16* sQl = dsmb + 12800;
    for (int i = tid; i < 256; i += 128) {
        int row = i >> 2, ch = i & 3;
        size_t g = baseQ + (size_t)(q0 + row) * qStride + ch * 8;
        *reinterpret_cast<uint4*>(&sQh[row * 40 + ch * 8]) = *reinterpret_cast<const uint4*>(&Qh[g]);
        *reinterpret_cast<uint4*>(&sQl[row * 40 + ch * 8]) = *reinterpret_cast<const uint4*>(&Ql[g]);
    }
    __syncthreads();

    uint32_t qh[2][4], ql[2][4];
    const int a_row = w * 16 + (l & 7) + ((l >> 3) & 1) * 8;
    const int a_col = (l >> 4) * 8;
    {
        const uint32_t aQh = smem_u32(sQh), aQl = smem_u32(sQl);
#pragma unroll
        for (int ks = 0; ks < 2; ks++) {
            uint32_t off = (uint32_t)((a_row * 40 + a_col + ks * 16) * 2);
            LDMX4(qh[ks][0], qh[ks][1], qh[ks][2], qh[ks][3], aQh + off);
            LDMX4(ql[ks][0], ql[ks][1], ql[ks][2], ql[ks][3], aQl + off);
        }
    }
    __syncthreads();

    const float NEG = -1e30f;
    const int r0 = q0 + w * 16 + (l >> 2);
    const int r1 = r0 + 8;
    float m0 = NEG, m1 = NEG, lac0 = 0.f, lac1 = 0.f;
    float o[4][4];
#pragma unroll
    for (int n = 0; n < 4; n++)
#pragma unroll
        for (int q = 0; q < 4; q++) o[n][q] = 0.f;

    const int b_row_base = (l >> 4) * 8 + (l & 7);
    const int b_kof = ((l >> 3) & 1) * 8;
    const int ntiles = (q0 >> 6) + 1;

    for (int jt = 0; jt < ntiles; jt++) {
        const int j0 = jt * 64;
        const int buf = jt & 1;
        if (jt + 1 < ntiles) { issue_kv(j0 + 64, buf ^ 1); CP_COMMIT(); CP_WAIT1(); }
        else                 { CP_WAIT0(); }
        __syncthreads();
        const uint32_t bufB = (uint32_t)buf * 20480;

        float s[8][4];
#pragma unroll
        for (int nt = 0; nt < 8; nt++)
#pragma unroll
            for (int q = 0; q < 4; q++) s[nt][q] = 0.f;

#pragma unroll
        for (int ks = 0; ks < 2; ks++) {
#pragma unroll
            for (int jp = 0; jp < 4; jp++) {
                uint32_t off = aKV + bufB + (uint32_t)(((jp * 16 + b_row_base) * 40 + b_kof + ks * 16) * 2);
                uint32_t kb[4], kbl[4];
                LDMX4(kb[0], kb[1], kb[2], kb[3], off);
                LDMX4(kbl[0], kbl[1], kbl[2], kbl[3], off + 5120);
                MMA16816(s[2 * jp],     qh[ks], kb[0],  kb[1]);
                MMA16816(s[2 * jp],     ql[ks], kb[0],  kb[1]);
                MMA16816(s[2 * jp],     qh[ks], kbl[0], kbl[1]);
                MMA16816(s[2 * jp + 1], qh[ks], kb[2],  kb[3]);
                MMA16816(s[2 * jp + 1], ql[ks], kb[2],  kb[3]);
                MMA16816(s[2 * jp + 1], qh[ks], kbl[2], kbl[3]);
            }
        }

        if (j0 >= q0) {
#pragma unroll
            for (int nt = 0; nt < 8; nt++) {
                int cb = j0 + nt * 8 + (l & 3) * 2;
                if (mode == 0) {
                    if (cb     > r0) s[nt][0] = NEG;
                    if (cb + 1 > r0) s[nt][1] = NEG;
                    if (cb     > r1) s[nt][2] = NEG;
                    if (cb + 1 > r1) s[nt][3] = NEG;
                } else {
                    if (!(cb     < r0 || (r0 == 0 && cb == 0))) s[nt][0] = NEG;
                    if (!(cb + 1 < r0))                          s[nt][1] = NEG;
                    if (!(cb     < r1)) s[nt][2] = NEG;
                    if (!(cb + 1 < r1)) s[nt][3] = NEG;
                }
            }
        }

        float ml0 = NEG, ml1 = NEG;
#pragma unroll
        for (int nt = 0; nt < 8; nt++) {
            ml0 = fmaxf(ml0, fmaxf(s[nt][0], s[nt][1]));
            ml1 = fmaxf(ml1, fmaxf(s[nt][2], s[nt][3]));
        }
        ml0 = fmaxf(ml0, __shfl_xor_sync(0xffffffffu, ml0, 1));
        ml0 = fmaxf(ml0, __shfl_xor_sync(0xffffffffu, ml0, 2));
        ml1 = fmaxf(ml1, __shfl_xor_sync(0xffffffffu, ml1, 1));
        ml1 = fmaxf(ml1, __shfl_xor_sync(0xffffffffu, ml1, 2));
        float mn0 = fmaxf(m0, ml0), mn1 = fmaxf(m1, ml1);
        float sc0 = ex2(m0 - mn0), sc1 = ex2(m1 - mn1);

        uint32_t pah[4][4], pal[4][4];
        float ps0 = 0.f, ps1 = 0.f;
#pragma unroll
        for (int pt = 0; pt < 4; pt++) {
#pragma unroll
            for (int half = 0; half < 2; half++) {
                int nt = 2 * pt + half;
                float p0 = ex2(s[nt][0] - mn0), p1 = ex2(s[nt][1] - mn0);
                float p2 = ex2(s[nt][2] - mn1), p3 = ex2(s[nt][3] - mn1);
                ps0 += p0 + p1; ps1 += p2 + p3;
                packpair(pah[pt][2 * half],     pal[pt][2 * half],     p0, p1);
                packpair(pah[pt][2 * half + 1], pal[pt][2 * half + 1], p2, p3);
            }
        }
        lac0 = lac0 * sc0 + ps0;
        lac1 = lac1 * sc1 + ps1;
#pragma unroll
        for (int n = 0; n < 4; n++) {
            o[n][0] *= sc0; o[n][1] *= sc0; o[n][2] *= sc1; o[n][3] *= sc1;
        }

#pragma unroll
        for (int pt = 0; pt < 4; pt++) {
#pragma unroll
            for (int np = 0; np < 2; np++) {
                uint32_t off = aKV + bufB + 10240u
                             + (uint32_t)(((pt * 16 + (l & 15)) * 40 + np * 16 + (l >> 4) * 8) * 2);
                uint32_t vb[4], vbl[4];
                LDMX4T(vb[0], vb[1], vb[2], vb[3], off);
                LDMX4T(vbl[0], vbl[1], vbl[2], vbl[3], off + 5120);
                MMA16816(o[2 * np],     pah[pt], vb[0],  vb[1]);
                MMA16816(o[2 * np],     pal[pt], vb[0],  vb[1]);
                MMA16816(o[2 * np],     pah[pt], vbl[0], vbl[1]);
                MMA16816(o[2 * np + 1], pah[pt], vb[2],  vb[3]);
                MMA16816(o[2 * np + 1], pal[pt], vb[2],  vb[3]);
                MMA16816(o[2 * np + 1], pah[pt], vbl[2], vbl[3]);
            }
        }
        m0 = mn0; m1 = mn1;
        __syncthreads();
    }

    lac0 += __shfl_xor_sync(0xffffffffu, lac0, 1);
    lac0 += __shfl_xor_sync(0xffffffffu, lac0, 2);
    lac1 += __shfl_xor_sync(0xffffffffu, lac1, 1);
    lac1 += __shfl_xor_sync(0xffffffffu, lac1, 2);
    float inv0 = 1.f / lac0, inv1 = 1.f / lac1;

#pragma unroll
    for (int nt = 0; nt < 4; nt++) {
        int col = nt * 8 + (l & 3) * 2;
        float v00 = o[nt][0] * inv0, v01 = o[nt][1] * inv0;
        float v10 = o[nt][2] * inv1, v11 = o[nt][3] * inv1;
        if (Of) {
            float2 a; a.x = v00; a.y = v01;
            float2 b; b.x = v10; b.y = v11;
            *reinterpret_cast<float2*>(&Of[baseO + (size_t)r0 * oStride + col]) = a;
            *reinterpret_cast<float2*>(&Of[baseO + (size_t)r1 * oStride + col]) = b;
        }
        if (Oh) {
            uint32_t h0, l0p, h1v, l1p;
            packpair(h0, l0p, v00, v01);
            packpair(h1v, l1p, v10, v11);
            *reinterpret_cast<uint32_t*>(&Oh[baseO + (size_t)r0 * oStride + col]) = h0;
            *reinterpret_cast<uint32_t*>(&Ol[baseO + (size_t)r0 * oStride + col]) = l0p;
            *reinterpret_cast<uint32_t*>(&Oh[baseO + (size_t)r1 * oStride + col]) = h1v;
            *reinterpret_cast<uint32_t*>(&Ol[baseO + (size_t)r1 * oStride + col]) = l1p;
        }
    }
}

// ---------------------------------------------------------------------------
// LayerNorm(A + B): 4 rows per 512-thread CTA; fp32 out + bf16 hi/lo out
// ---------------------------------------------------------------------------
__global__ __launch_bounds__(512) void add_ln_k(
    const float* __restrict__ A, const float* __restrict__ Bv,
    const float* __restrict__ gam, const float* __restrict__ bet,
    float* __restrict__ outf, bf16* __restrict__ outh, bf16* __restrict__ outl)
{
    int rloc = threadIdx.x >> 7;               // 0..3 row within block
    int row  = blockIdx.x * 4 + rloc;
    int d    = threadIdx.x & 127;
    float x = A[(size_t)row * 128 + d] + Bv[(size_t)row * 128 + d];

    __shared__ float ws[16], ws2[16];
    int warp = (d >> 5);                       // warp-in-row 0..3
    float v = x;
#pragma unroll
    for (int off = 16; off; off >>= 1) v += __shfl_xor_sync(0xffffffffu, v, off);
    if ((d & 31) == 0) ws[rloc * 4 + warp] = v;
    __syncthreads();
    float mean = (ws[rloc*4] + ws[rloc*4+1] + ws[rloc*4+2] + ws[rloc*4+3]) * (1.f / 128.f);
    float dif = x - mean;
    float v2 = dif * dif;
#pragma unroll
    for (int off = 16; off; off >>= 1) v2 += __shfl_xor_sync(0xffffffffu, v2, off);
    if ((d & 31) == 0) ws2[rloc * 4 + warp] = v2;
    __syncthreads();
    float var = (ws2[rloc*4] + ws2[rloc*4+1] + ws2[rloc*4+2] + ws2[rloc*4+3]) * (1.f / 128.f);
    float y = dif * rsqrtf(var + 1e-5f) * gam[d] + bet[d];
    if (outf) outf[(size_t)row * 128 + d] = y;
    if (outh) {
        bf16 h = __float2bfloat16(y);
        outh[(size_t)row * 128 + d] = h;
        outl[(size_t)row * 128 + d] = __float2bfloat16(y - __bfloat162float(h));
    }
}

// ---------------------------------------------------------------------------
extern "C" void kernel_launch(void* const* d_in, const int* in_sizes, int n_in,
                              void* d_out, int out_size)
{
    const float* kq    = (const float*)d_in[0];
    const float* v_in  = (const float*)d_in[1];
    const float* A_Wk  = (const float*)d_in[2];
    const float* A_bk  = (const float*)d_in[3];
    const float* A_Wq  = (const float*)d_in[4];
    const float* A_bq  = (const float*)d_in[5];
    const float* A_Wv  = (const float*)d_in[6];
    const float* A_bv  = (const float*)d_in[7];
    const float* A_f1W = (const float*)d_in[8];
    const float* A_f1b = (const float*)d_in[9];
    const float* A_f2W = (const float*)d_in[10];
    const float* A_f2b = (const float*)d_in[11];
    const float* A_n1g = (const float*)d_in[12];
    const float* A_n1b = (const float*)d_in[13];
    const float* A_n2g = (const float*)d_in[14];
    const float* A_n2b = (const float*)d_in[15];
    const float* B_Wk  = (const float*)d_in[16];
    const float* B_bk  = (const float*)d_in[17];
    const float* B_Wq  = (const float*)d_in[18];
    const float* B_bq  = (const float*)d_in[19];
    const float* B_Wv  = (const float*)d_in[20];
    const float* B_bv  = (const float*)d_in[21];
    const float* B_f1W = (const float*)d_in[22];
    const float* B_f1b = (const float*)d_in[23];
    const float* B_f2W = (const float*)d_in[24];
    const float* B_f2b = (const float*)d_in[25];
    const float* out_W = (const float*)d_in[26];
    const float* out_b = (const float*)d_in[27];
    float* out = (float*)d_out;

    float* pool = nullptr;
    cudaGetSymbolAddress((void**)&pool, g_scratch);

    static cudaStream_t s2 = nullptr;
    static cudaEvent_t e1 = nullptr, e2 = nullptr;
    static bool attr_done = false;
    if (!attr_done) {
        cudaFuncSetAttribute(mma_gemm1<128,false>, cudaFuncAttributeMaxDynamicSharedMemorySize, GEMM_SMEM128);
        cudaFuncSetAttribute(mma_gemm1<64,false>,  cudaFuncAttributeMaxDynamicSharedMemorySize, GEMM_SMEM64);
        cudaFuncSetAttribute(mma_gemm1<64,true>,   cudaFuncAttributeMaxDynamicSharedMemorySize, GEMM_SMEM64);
        cudaFuncSetAttribute(mma_gemm2, cudaFuncAttributeMaxDynamicSharedMemorySize, GEMM_SMEM128);
        cudaFuncSetAttribute(attn_tc, cudaFuncAttributeMaxDynamicSharedMemorySize, ATTN_SMEM);
        cudaStreamCreateWithFlags(&s2, cudaStreamNonBlocking);
        cudaEventCreateWithFlags(&e1, cudaEventDisableTiming);
        cudaEventCreateWithFlags(&e2, cudaEventDisableTiming);
        attr_done = true;
    }

    const size_t S = (size_t)R_TOTAL * 128;  // 2M floats per slot
    float* attnA = pool + 0 * S;
    float* h1    = pool + 1 * S;
    float* Va    = pool + 3 * S;
    bf16* qkvA_h = (bf16*)(pool + 4 * S);    // R x 384 (slots 4-5)
    bf16* qkvA_l = (bf16*)(pool + 6 * S);    // slots 6-7
    bf16* sXh    = (bf16*)(pool + 8 * S);
    bf16* sXl    = (bf16*)(pool + 9 * S);
    bf16* ffh    = (bf16*)(pool + 10 * S);   // R x 512 (slots 10-11)
    bf16* ffl    = (bf16*)(pool + 12 * S);   // slots 12-13
    bf16* kqh    = (bf16*)(pool + 14 * S);
    bf16* kql    = (bf16*)(pool + 15 * S);
    bf16* kq2h   = (bf16*)(pool + 16 * S);   // R x 256
    bf16* kq2l   = (bf16*)(pool + 17 * S);
    bf16* v2h    = (bf16*)(pool + 18 * S);
    bf16* v2l    = (bf16*)(pool + 19 * S);
    bf16* at2h   = (bf16*)(pool + 20 * S);
    bf16* at2l   = (bf16*)(pool + 21 * S);
    bf16* vAh    = (bf16*)(pool + 22 * S);
    bf16* vAl    = (bf16*)(pool + 23 * S);
    float* Wc    = pool + 24 * S;            // 512x32 fp32
    float* bc    = Wc + 512 * 32;
    float* qkvbA = bc + 64;                  // 384
    float* kqb2  = qkvbA + 384;              // 256
    bf16* wArena = (bf16*)(pool + 25 * S);
    bf16* wH = wArena;
    bf16* wL = wArena + PW_TOTAL;
    bf16* qkvW_h = wH + 0;       bf16* qkvW_l = wL + 0;
    bf16* kqW_h  = wH + 49152;   bf16* kqW_l  = wL + 49152;
    bf16* bWv_h  = wH + 65536;   bf16* bWv_l  = wL + 65536;
    bf16* af1_h  = wH + 81920;   bf16* af1_l  = wL + 81920;
    bf16* af2_h  = wH + 147456;  bf16* af2_l  = wL + 147456;
    bf16* bf1_h  = wH + 212992;  bf16* bf1_l  = wL + 212992;
    bf16* wc_h   = wH + 278528;  bf16* wc_l   = wL + 278528;

    // ---- prep on side stream (fork) overlapping splitcat (main) ----
    cudaEventRecord(e1, 0);
    cudaStreamWaitEvent(s2, e1, 0);
    smallprep_k<<<(512*32 + 32 + 640 + 255) / 256, 256, 0, s2>>>(
        B_f2W, out_W, B_f2b, out_b, A_bk, A_bq, A_bv, B_bk, B_bq,
        Wc, bc, qkvbA, kqb2);
    Prep10 p10;
    p10.s[0] = A_Wk; p10.s[1] = A_Wq; p10.s[2] = A_Wv;
    p10.s[3] = B_Wk; p10.s[4] = B_Wq; p10.s[5] = B_Wv;
    p10.s[6] = A_f1W; p10.s[7] = A_f2W; p10.s[8] = B_f1W; p10.s[9] = Wc;
    prepw_k<<<(PW_TOTAL + 255) / 256, 256, 0, s2>>>(p10, wH, wL);
    cudaEventRecord(e2, s2);

    splitcat_k<<<(R_TOTAL*32+255)/256, 256>>>(kq, v_in, sXh, sXl, kqh, kql);
    cudaStreamWaitEvent(0, e2, 0);   // join before first GEMM

    dim3 attnGrid(T_SEQ / 64, 8 * NHEAD);  // (32, 32)

    auto J = [](const bf16* Ah, const bf16* Al, const bf16* Bh, const bf16* Bl,
                const float* bias, int Nvalid, float* Cf, int f_lo, int fStride,
                bf16* Ch, bf16* Cl, int cStride, int K, int act, int gridX,
                const float* lnRes = nullptr, const float* lnG = nullptr,
                const float* lnB = nullptr) {
        GemmJob j;
        j.Ah = Ah; j.Al = Al; j.Bh = Bh; j.Bl = Bl; j.bias = bias; j.Nvalid = Nvalid;
        j.Cf = Cf; j.f_lo = f_lo; j.fStride = fStride;
        j.Ch = Ch; j.Cl = Cl; j.cStride = cStride; j.K = K; j.act = act; j.gridX = gridX;
        j.lnRes = lnRes; j.lnG = lnG; j.lnB = lnB;
        return j;
    };

    // ---- Layer A (+ layer-B K/Q merged, flat grid: 384 + 256 = 640 CTAs) ----
    {
        GemmJob j0 = J(sXh, sXl, qkvW_h, qkvW_l, qkvbA, 384, Va, 256, 128,
                       qkvA_h, qkvA_l, 384, 128, 0, 3);
        GemmJob j1 = J(kqh, kql, kqW_h, kqW_l, kqb2, 256, nullptr, 0, 0,
                       kq2h, kq2l, 256, 64, 0, 2);
        mma_gemm2<<<640, 256, GEMM_SMEM128>>>(j0, j1, 384);
    }
    attn_tc<<<attnGrid, 128, ATTN_SMEM>>>(qkvA_h + 128, qkvA_l + 128, 384,
                               qkvA_h, qkvA_l, 384,
                               qkvA_h + 256, qkvA_l + 256, 384,
                               attnA, nullptr, nullptr, 128, 0);
    add_ln_k<<<R_TOTAL / 4, 512>>>(Va, attnA, A_n1g, A_n1b, h1, sXh, sXl);
    mma_gemm1<128,false><<<dim3(4, 128), 256, GEMM_SMEM128>>>(
        J(sXh, sXl, af1_h, af1_l, A_f1b, 512, nullptr, 0, 0, ffh, ffl, 512, 128, 1, 4));
    // FF2A with fused residual+LN2 -> vAh/vAl
    mma_gemm1<64,true><<<dim3(1, 256), 256, GEMM_SMEM64>>>(
        J(ffh, ffl, af2_h, af2_l, A_f2b, 128, nullptr, 0, 0, vAh, vAl, 128, 512, 0, 1,
          h1, A_n2g, A_n2b));

    // ---- Layer B ----
    mma_gemm1<64,false><<<dim3(1, 256), 256, GEMM_SMEM64>>>(
        J(vAh, vAl, bWv_h, bWv_l, B_bv, 128, nullptr, 0, 0, v2h, v2l, 128, 128, 0, 1));
    attn_tc<<<attnGrid, 128, ATTN_SMEM>>>(kq2h + 128, kq2l + 128, 256,
                               kq2h, kq2l, 256,
                               v2h, v2l, 128,
                               nullptr, at2h, at2l, 128, 1);
    mma_gemm1<128,false><<<dim3(4, 128), 256, GEMM_SMEM128>>>(
        J(at2h, at2l, bf1_h, bf1_l, B_f1b, 512, nullptr, 0, 0, ffh, ffl, 512, 128, 1, 4));
    mma_gemm1<64,false><<<dim3(1, 256), 256, GEMM_SMEM64>>>(
        J(ffh, ffl, wc_h, wc_l, bc, 32, out, 0, 32, nullptr, nullptr, 0, 512, 0, 1));
}